// round 8
// baseline (speedup 1.0000x reference)
#include <cuda_runtime.h>
#include <cuda_fp16.h>
#include <cstdint>
#include <cstddef>

// ---------------------------------------------------------------------------
// Problem constants: B=8, N=M=128, H=512, D=2H=1024
// ---------------------------------------------------------------------------
#define BB   8
#define NN   128
#define HH   512
#define DD   1024

// Scratch layout (floats)
#define SZ_PROJ (BB*NN*HH)
#define SZ_XB   (BB*NN*DD)
#define SZ_S    (BB*NN*NN)
#define SZ_SD   (BB*NN*4*NN)
#define SZ_AGG  (BB*NN*2*DD)

#define OFF_XC  0
#define OFF_YC  (OFF_XC + SZ_PROJ)
#define OFF_XM  (OFF_YC + SZ_PROJ)
#define OFF_YM  (OFF_XM + SZ_PROJ)
#define OFF_XB  (OFF_YM + SZ_PROJ)
#define OFF_SC  (OFF_XB + SZ_XB)
#define OFF_SB  (OFF_SC + SZ_S)
#define OFF_SMN (OFF_SB + SZ_S)
#define OFF_SD1 (OFF_SMN + SZ_S)
#define OFF_SD2 (OFF_SD1 + SZ_SD)
#define OFF_AGG (OFF_SD2 + SZ_SD)
#define OFF_W1V (OFF_AGG + SZ_AGG)
#define SCRATCH_TOTAL (OFF_W1V + 2*DD)

__device__ float g_scratch[SCRATCH_TOTAL];

// fp16 pool: dot W^T x2, x0/x1, proj W^T x4
#define HW1 0
#define HW2 (HW1 + HH*DD)
#define HX0 (HW2 + HH*DD)
#define HX1 (HX0 + NN*BB*DD)
#define HC1 (HX1 + NN*BB*DD)
#define HC2 (HC1 + HH*DD)
#define HM  (HC2 + HH*DD)
#define HB  (HM  + HH*DD)
#define HALF_TOTAL (HB + DD*DD)
__device__ __align__(16) __half g_half[HALF_TOTAL];

// tanh via MUFU.TANH
__device__ __forceinline__ float ftanh(float x) {
    float y;
    asm("tanh.approx.f32 %0, %1;" : "=f"(y) : "f"(x));
    return y;
}

__device__ __forceinline__ uint32_t smem_u32(const void* p) {
    uint32_t a;
    asm("{ .reg .u64 t; cvta.to.shared.u64 t, %1; cvt.u32.u64 %0, t; }" : "=r"(a) : "l"(p));
    return a;
}

#define LDSM4(r0, r1, r2, r3, addr) \
    asm volatile("ldmatrix.sync.aligned.m8n8.x4.shared.b16 {%0,%1,%2,%3}, [%4];" \
        : "=r"(r0), "=r"(r1), "=r"(r2), "=r"(r3) : "r"(addr))

#define MMA16816(d, a0, a1, a2, a3, b0, b1) \
    asm volatile("mma.sync.aligned.m16n8k16.row.col.f32.f16.f16.f32 " \
        "{%0,%1,%2,%3}, {%4,%5,%6,%7}, {%8,%9}, {%0,%1,%2,%3};" \
        : "+f"((d)[0]), "+f"((d)[1]), "+f"((d)[2]), "+f"((d)[3]) \
        : "r"(a0), "r"(a1), "r"(a2), "r"(a3), "r"(b0), "r"(b1))

#define CP_ASYNC16(sa, ga) \
    asm volatile("cp.async.cg.shared.global [%0], [%1], 16;" :: "r"(sa), "l"(ga))
#define CP_COMMIT() asm volatile("cp.async.commit_group;")
#define CP_WAIT0()  asm volatile("cp.async.wait_group 0;")

// 128B-row swizzle (8 chunks of 16B): chunk ^= row&7
__device__ __forceinline__ uint32_t sw128(uint32_t row, uint32_t chunk) {
    return row * 128u + ((chunk * 16u) ^ ((row & 7u) << 4));
}

// ---------------------------------------------------------------------------
// Fused prep: all weight transposes/converts + x converts + w1v in ONE launch.
// grid (1024, 9), 256 threads.
// ---------------------------------------------------------------------------
__global__ void prep_fused(
    const float* __restrict__ Wd1, const float* __restrict__ Wd2,
    const float* __restrict__ Wc1, const float* __restrict__ Wc2,
    const float* __restrict__ Wm,  const float* __restrict__ Wb,
    const float* __restrict__ x0,  const float* __restrict__ x1,
    const float* __restrict__ Wp1, const float* __restrict__ vp,
    __half* __restrict__ HP, float* __restrict__ w1v)
{
    const int task = blockIdx.y;
    const int bx = blockIdx.x;
    const int tid = threadIdx.x;

    if (task < 5) {                       // W^T converts, N=HH (512 rows)
        if (bx >= HH) return;
        const float* W; __half* wt;
        switch (task) {
            case 0: W = Wd1; wt = HP + HW1; break;
            case 1: W = Wd2; wt = HP + HW2; break;
            case 2: W = Wc1; wt = HP + HC1; break;
            case 3: W = Wc2; wt = HP + HC2; break;
            default: W = Wm; wt = HP + HM; break;
        }
#pragma unroll
        for (int i = 0; i < 4; i++) {
            int d = tid + i * 256;
            wt[(size_t)bx * DD + d] = __float2half_rn(W[(size_t)d * HH + bx]);
        }
    } else if (task == 5) {               // Wb^T, N=DD (1024 rows)
        __half* wt = HP + HB;
#pragma unroll
        for (int i = 0; i < 4; i++) {
            int d = tid + i * 256;
            wt[(size_t)bx * DD + d] = __float2half_rn(Wb[(size_t)d * DD + bx]);
        }
    } else if (task < 8) {                // x fp32 -> fp16
        const float* x = (task == 6) ? x0 : x1;
        __half* xh = HP + ((task == 6) ? HX0 : HX1);
        int i = bx * 1024 + tid * 4;
        float4 v = *(const float4*)(x + i);
        __half2* o = (__half2*)(xh + i);
        o[0] = __floats2half2_rn(v.x, v.y);
        o[1] = __floats2half2_rn(v.z, v.w);
    } else {                              // w1v
        if (bx >= 256) return;
        int j = bx * 8 + (tid >> 5);
        int lane = tid & 31;
        const float* r = Wp1 + (size_t)j * HH;
        float acc = 0.0f;
#pragma unroll
        for (int h = lane; h < HH; h += 32) acc += r[h] * vp[h];
#pragma unroll
        for (int o = 16; o; o >>= 1) acc += __shfl_xor_sync(0xffffffffu, acc, o);
        if (lane == 0) w1v[j] = acc;
    }
}

// ---------------------------------------------------------------------------
// mma.sync fp16 dot-attention scores with m-pairing (W reuse).
// CTA per (hc 0..3, m-pair 0..63, b*2+att). 512 thr / 16 warps.
// CTA computes 2 m's x 128(n) x 128(h); K=1024 in kc=64 chunks, double-buffered.
// Traffic per CTA: x fp16 256KB + W 256KB (vs 1MB in round 6).
// ---------------------------------------------------------------------------
#define MOFF_Y  0            // 8192  (2 y rows fp32)
#define MOFF_V  8192         // 512
#define MOFF_S  8704         // 1024  (2 x 128 f32)
#define MOFF_A  9728         // 2 bufs x 2 m x 16384 -> 75264
#define MOFF_B  75264        // 2 bufs x 16384 -> 108032
#define MSMEM   108032

__global__ __launch_bounds__(512, 1) void dot_scores_mma(
    const __half* __restrict__ xh0, const __half* __restrict__ xh1,
    const float* __restrict__ x0f, const float* __restrict__ x1f,
    const __half* __restrict__ w1t, const __half* __restrict__ w2t,
    const float* __restrict__ vd1, const float* __restrict__ vd2,
    float* __restrict__ sp1, float* __restrict__ sp2)
{
    extern __shared__ char smc[];
    const uint32_t sb = smem_u32(smc);

    const int hc  = blockIdx.x;           // 0..3 (h chunk of 128)
    const int m0  = blockIdx.y * 2;       // m pair
    const int att = blockIdx.z & 1;
    const int b   = blockIdx.z >> 1;

    const __half* x = att ? xh1 : xh0;
    const float*  y = att ? x0f : x1f;
    const __half* wt = att ? w2t : w1t;
    const float*  v = att ? vd2 : vd1;
    float* spart = att ? sp2 : sp1;

    const int t = threadIdx.x;
    const int lane = t & 31, wid = t >> 5;
    const int mwarp = wid >> 3;                   // warp's m (0/1)
    const int wn = wid & 3, whi = (wid >> 2) & 1; // n-group, h-group
    const int lane15 = lane & 15, lhalf = lane >> 4;

    float* ysm = (float*)(smc + MOFF_Y);          // [2][1024]
    float* vsm = (float*)(smc + MOFF_V);
    float* ssm = (float*)(smc + MOFF_S);          // [2][128]

    // y rows m0, m0+1 are contiguous: one coalesced load of 2048 floats
    ((float4*)ysm)[t] = ((const float4*)(y + ((size_t)b * NN + m0) * DD))[t];
    if (t < 32) ((float4*)vsm)[t] = ((const float4*)(v + hc * 128))[t];
    if (t < 256) ssm[t] = 0.0f;

    const __half* xg = x + (size_t)b * NN * DD;
    const __half* wg = wt + (size_t)(hc * 128) * DD;

    // B tile (128 x 64): br = t>>2 (0..127), 2 chunks per thread
    const int br = t >> 2, bc2 = (t & 3) * 2;
    const uint32_t b_st0 = sw128(br, bc2), b_st1 = sw128(br, bc2 + 1);

    // A tiles (2 x 128 x 64): am = t>>8, an = (t&255)>>1, ah = t&1
    const int am = t >> 8, tt = t & 255, an = tt >> 1, ah = tt & 1;
    uint32_t a_st[4];
#pragma unroll
    for (int j = 0; j < 4; j++) a_st[j] = sw128(an, ah * 4 + j);

    uint4 xq[4];   // staged x (32 halves)

#define ISSUE_B(kt, buf) do { \
        const __half* bp_ = wg + (size_t)br * DD + (kt) * 64 + bc2 * 8; \
        uint32_t Bb_ = sb + MOFF_B + (buf) * 16384u; \
        CP_ASYNC16(Bb_ + b_st0, bp_); \
        CP_ASYNC16(Bb_ + b_st1, bp_ + 8); \
        CP_COMMIT(); \
    } while (0)

#define LOAD_X(kt) do { \
        const uint4* xp_ = (const uint4*)(xg + (size_t)an * DD + (kt) * 64 + ah * 32); \
        xq[0] = xp_[0]; xq[1] = xp_[1]; xq[2] = xp_[2]; xq[3] = xp_[3]; \
    } while (0)

#define STORE_A(kt, buf) do { \
        const int kb_ = (kt) * 64 + ah * 32; \
        const float* yb0_ = ysm + am * 1024 + kb_; \
        char* Ab_ = smc + MOFF_A + (buf) * 32768 + am * 16384; \
        _Pragma("unroll") \
        for (int j_ = 0; j_ < 4; j_++) { \
            const __half2* hp_ = (const __half2*)&xq[j_]; \
            const float* yb_ = yb0_ + j_ * 8; \
            float2 f0_ = __half22float2(hp_[0]); \
            float2 f1_ = __half22float2(hp_[1]); \
            float2 f2_ = __half22float2(hp_[2]); \
            float2 f3_ = __half22float2(hp_[3]); \
            union { __half2 h2[4]; uint4 q; } o_; \
            o_.h2[0] = __floats2half2_rn(f0_.x * yb_[0], f0_.y * yb_[1]); \
            o_.h2[1] = __floats2half2_rn(f1_.x * yb_[2], f1_.y * yb_[3]); \
            o_.h2[2] = __floats2half2_rn(f2_.x * yb_[4], f2_.y * yb_[5]); \
            o_.h2[3] = __floats2half2_rn(f3_.x * yb_[6], f3_.y * yb_[7]); \
            *(uint4*)(Ab_ + a_st[j_]) = o_.q; \
        } \
    } while (0)

    float acc[2][8][4];
#pragma unroll
    for (int i = 0; i < 2; i++)
#pragma unroll
        for (int j = 0; j < 8; j++)
#pragma unroll
            for (int k = 0; k < 4; k++) acc[i][j][k] = 0.0f;

    ISSUE_B(0, 0);
    LOAD_X(0);
    __syncthreads();            // ysm ready
    STORE_A(0, 0);
    CP_WAIT0();
    __syncthreads();

    uint32_t a_row[2], b_row[4];
#pragma unroll
    for (int mi = 0; mi < 2; mi++) a_row[mi] = wn * 32 + mi * 16 + lane15;
#pragma unroll
    for (int nj = 0; nj < 4; nj++) b_row[nj] = whi * 64 + nj * 16 + lane15;

    for (int kt = 0; kt < 16; kt++) {
        const int buf = kt & 1;
        if (kt < 15) { ISSUE_B(kt + 1, buf ^ 1); LOAD_X(kt + 1); }

        const uint32_t Ah = sb + MOFF_A + buf * 32768u + mwarp * 16384u;
        const uint32_t Bh = sb + MOFF_B + buf * 16384u;

#pragma unroll
        for (int ks = 0; ks < 4; ks++) {
            const uint32_t cidx = ks * 2 + lhalf;
            uint32_t a[2][4], bb[4][4];
#pragma unroll
            for (int mi = 0; mi < 2; mi++)
                LDSM4(a[mi][0], a[mi][1], a[mi][2], a[mi][3], Ah + sw128(a_row[mi], cidx));
#pragma unroll
            for (int nj = 0; nj < 4; nj++)
                LDSM4(bb[nj][0], bb[nj][1], bb[nj][2], bb[nj][3], Bh + sw128(b_row[nj], cidx));
#pragma unroll
            for (int mi = 0; mi < 2; mi++)
#pragma unroll
                for (int nj = 0; nj < 4; nj++) {
                    MMA16816(acc[mi][nj*2+0], a[mi][0], a[mi][1], a[mi][2], a[mi][3], bb[nj][0], bb[nj][2]);
                    MMA16816(acc[mi][nj*2+1], a[mi][0], a[mi][1], a[mi][2], a[mi][3], bb[nj][1], bb[nj][3]);
                }
        }

        if (kt < 15) { STORE_A(kt + 1, buf ^ 1); CP_WAIT0(); }
        __syncthreads();
    }

    // epilogue: tanh * v, reduce to s[mwarp][n]
    float rs[2][2] = {{0.0f, 0.0f}, {0.0f, 0.0f}};
#pragma unroll
    for (int mi = 0; mi < 2; mi++)
#pragma unroll
        for (int hj = 0; hj < 8; hj++) {
            int hcol = whi * 64 + hj * 8 + (lane & 3) * 2;
            float v0 = vsm[hcol], v1 = vsm[hcol + 1];
            rs[mi][0] += ftanh(acc[mi][hj][0]) * v0 + ftanh(acc[mi][hj][1]) * v1;
            rs[mi][1] += ftanh(acc[mi][hj][2]) * v0 + ftanh(acc[mi][hj][3]) * v1;
        }
#pragma unroll
    for (int o = 1; o <= 2; o <<= 1) {
        rs[0][0] += __shfl_xor_sync(0xffffffffu, rs[0][0], o);
        rs[0][1] += __shfl_xor_sync(0xffffffffu, rs[0][1], o);
        rs[1][0] += __shfl_xor_sync(0xffffffffu, rs[1][0], o);
        rs[1][1] += __shfl_xor_sync(0xffffffffu, rs[1][1], o);
    }
    if ((lane & 3) == 0) {
        int r = mwarp * 128 + wn * 32 + (lane >> 2);
        atomicAdd(&ssm[r],      rs[0][0]);
        atomicAdd(&ssm[r + 8],  rs[0][1]);
        atomicAdd(&ssm[r + 16], rs[1][0]);
        atomicAdd(&ssm[r + 24], rs[1][1]);
    }
    __syncthreads();
    if (t < 256) {
        int mi = t >> 7, n = t & 127;
        spart[(((size_t)b * NN + m0 + mi) * 4 + hc) * NN + n] = ssm[mi * 128 + n];
    }
#undef ISSUE_B
#undef LOAD_X
#undef STORE_A
}

// ---------------------------------------------------------------------------
// fp16 mma projections (unchanged)
// ---------------------------------------------------------------------------
#define POFF_A 0
#define POFF_B 32768
#define PSMEM  65536

__global__ __launch_bounds__(256, 1) void proj_mma(
    const __half* __restrict__ xh0, const __half* __restrict__ xh1,
    const __half* __restrict__ wc1t, const __half* __restrict__ wc2t,
    const __half* __restrict__ wmt,  const __half* __restrict__ wbt,
    float* __restrict__ S)
{
    const __half* A; const __half* W; float* C; int N;
    switch (blockIdx.z) {
        case 0: A = xh0; W = wc1t; C = S + OFF_XC; N = HH; break;
        case 1: A = xh1; W = wc2t; C = S + OFF_YC; N = HH; break;
        case 2: A = xh0; W = wmt;  C = S + OFF_XM; N = HH; break;
        case 3: A = xh1; W = wmt;  C = S + OFF_YM; N = HH; break;
        default: A = xh0; W = wbt; C = S + OFF_XB; N = DD; break;
    }
    const int bn = blockIdx.x * 128;
    if (bn >= N) return;
    const int bm = blockIdx.y * 128;

    extern __shared__ char smc[];
    const uint32_t sb = smem_u32(smc);
    const int t = threadIdx.x, lane = t & 31, wid = t >> 5;
    const int wm = wid & 3, whn = wid >> 2;
    const int lane15 = lane & 15, lhalf = lane >> 4;

    const int r = t >> 1, cc4 = (t & 1) * 4;
    uint32_t st_off[4];
#pragma unroll
    for (int j = 0; j < 4; j++) st_off[j] = sw128(r, cc4 + j);
    const __half* ag = A + (size_t)(bm + r) * DD + cc4 * 8;
    const __half* wgp = W + (size_t)(bn + r) * DD + cc4 * 8;

#define P_ISSUE(kt, buf) do { \
        uint32_t Ab_ = sb + POFF_A + (buf) * 16384u; \
        uint32_t Bb_ = sb + POFF_B + (buf) * 16384u; \
        const __half* ap_ = ag + (kt) * 64; \
        const __half* bp_ = wgp + (kt) * 64; \
        _Pragma("unroll") \
        for (int j_ = 0; j_ < 4; j_++) { \
            CP_ASYNC16(Ab_ + st_off[j_], ap_ + j_ * 8); \
            CP_ASYNC16(Bb_ + st_off[j_], bp_ + j_ * 8); \
        } \
        CP_COMMIT(); \
    } while (0)

    float acc[2][8][4];
#pragma unroll
    for (int i = 0; i < 2; i++)
#pragma unroll
        for (int j = 0; j < 8; j++)
#pragma unroll
            for (int k = 0; k < 4; k++) acc[i][j][k] = 0.0f;

    P_ISSUE(0, 0);
    CP_WAIT0();
    __syncthreads();

    uint32_t a_row[2], b_row[4];
#pragma unroll
    for (int mi = 0; mi < 2; mi++) a_row[mi] = wm * 32 + mi * 16 + lane15;
#pragma unroll
    for (int nj = 0; nj < 4; nj++) b_row[nj] = whn * 64 + nj * 16 + lane15;

    for (int kt = 0; kt < 16; kt++) {
        const int buf = kt & 1;
        if (kt < 15) P_ISSUE(kt + 1, buf ^ 1);

        const uint32_t Ah = sb + POFF_A + buf * 16384u;
        const uint32_t Bh = sb + POFF_B + buf * 16384u;

#pragma unroll
        for (int ks = 0; ks < 4; ks++) {
            const uint32_t cidx = ks * 2 + lhalf;
            uint32_t a[2][4], bb[4][4];
#pragma unroll
            for (int mi = 0; mi < 2; mi++)
                LDSM4(a[mi][0], a[mi][1], a[mi][2], a[mi][3], Ah + sw128(a_row[mi], cidx));
#pragma unroll
            for (int nj = 0; nj < 4; nj++)
                LDSM4(bb[nj][0], bb[nj][1], bb[nj][2], bb[nj][3], Bh + sw128(b_row[nj], cidx));
#pragma unroll
            for (int mi = 0; mi < 2; mi++)
#pragma unroll
                for (int nj = 0; nj < 4; nj++) {
                    MMA16816(acc[mi][nj*2+0], a[mi][0], a[mi][1], a[mi][2], a[mi][3], bb[nj][0], bb[nj][2]);
                    MMA16816(acc[mi][nj*2+1], a[mi][0], a[mi][1], a[mi][2], a[mi][3], bb[nj][1], bb[nj][3]);
                }
        }

        CP_WAIT0();
        __syncthreads();
    }

#pragma unroll
    for (int mi = 0; mi < 2; mi++) {
        int row = bm + wm * 32 + mi * 16 + (lane >> 2);
#pragma unroll
        for (int nj8 = 0; nj8 < 8; nj8++) {
            int col = bn + whn * 64 + nj8 * 8 + (lane & 3) * 2;
            C[(size_t)row * N + col]           = acc[mi][nj8][0];
            C[(size_t)row * N + col + 1]       = acc[mi][nj8][1];
            C[(size_t)(row + 8) * N + col]     = acc[mi][nj8][2];
            C[(size_t)(row + 8) * N + col + 1] = acc[mi][nj8][3];
        }
    }
#undef P_ISSUE
}

// ---------------------------------------------------------------------------
// Concat/minus scores
// ---------------------------------------------------------------------------
__global__ __launch_bounds__(256) void pair_scores(
    const float* __restrict__ p, const float* __restrict__ q,
    const float* __restrict__ v, float* __restrict__ s, float sign)
{
    const int m = blockIdx.x, b = blockIdx.y;
    const int t = threadIdx.x, lane = t & 31, w = t >> 5;
    __shared__ float qs[HH], vs[HH];
    if (t < 128) {
        ((float4*)qs)[t] = ((const float4*)(q + ((size_t)b * NN + m) * HH))[t];
        ((float4*)vs)[t] = ((const float4*)v)[t];
    }
    __syncthreads();
    const float* pb = p + (size_t)b * NN * HH;
    for (int n = w; n < NN; n += 8) {
        const float* pr = pb + (size_t)n * HH;
        float acc = 0.0f;
#pragma unroll
        for (int h = 0; h < HH; h += 32) {
            int hh = h + lane;
            acc += vs[hh] * ftanh(fmaf(sign, qs[hh], pr[hh]));
        }
#pragma unroll
        for (int o = 16; o; o >>= 1) acc += __shfl_xor_sync(0xffffffffu, acc, o);
        if (lane == 0) s[((size_t)b * NN + m) * NN + n] = acc;
    }
}

// ---------------------------------------------------------------------------
// Bilinear scores
// ---------------------------------------------------------------------------
__global__ __launch_bounds__(256) void bilin_scores(
    const float* __restrict__ y, const float* __restrict__ xb,
    float* __restrict__ s)
{
    const int m = blockIdx.x, b = blockIdx.y;
    const int t = threadIdx.x, lane = t & 31, w = t >> 5;
    __shared__ float ysm[DD];
    ((float4*)ysm)[t] = ((const float4*)(y + ((size_t)b * NN + m) * DD))[t];
    __syncthreads();
    const float* xbb = xb + (size_t)b * NN * DD;
    for (int n = w; n < NN; n += 8) {
        const float* xr = xbb + (size_t)n * DD;
        float acc = 0.0f;
#pragma unroll 8
        for (int d = lane; d < DD; d += 32) acc += ysm[d] * xr[d];
#pragma unroll
        for (int o = 16; o; o >>= 1) acc += __shfl_xor_sync(0xffffffffu, acc, o);
        if (lane == 0) s[((size_t)b * NN + m) * NN + n] = acc;
    }
}

// ---------------------------------------------------------------------------
// Fused: 5 softmaxes + 5 weighted sums + max + agg_rep write.
// ---------------------------------------------------------------------------
__global__ __launch_bounds__(256) void fuse_att(
    const float* __restrict__ sc,  const float* __restrict__ sb,
    const float* __restrict__ smn, const float* __restrict__ sd1,
    const float* __restrict__ sd2,
    const float* __restrict__ x0,  const float* __restrict__ x1,
    float* __restrict__ aggrep)
{
    const int m = blockIdx.x, b = blockIdx.y;
    const int t = threadIdx.x, lane = t & 31, w = t >> 5;
    const size_t bm = (size_t)b * NN + m;
    __shared__ float aw[5][NN];

    if (t < 128) {
        aw[0][t] = sc [bm * NN + t];
        aw[1][t] = sb [bm * NN + t];
        aw[2][t] = smn[bm * NN + t];
        float s1 = 0.0f, s2 = 0.0f;
#pragma unroll
        for (int hcx = 0; hcx < 4; hcx++) {
            s1 += sd1[(bm * 4 + hcx) * NN + t];
            s2 += sd2[(bm * 4 + hcx) * NN + t];
        }
        aw[3][t] = s1; aw[4][t] = s2;
    }
    __syncthreads();

    if (w < 5) {
        float v0 = aw[w][lane], v1 = aw[w][lane + 32];
        float v2 = aw[w][lane + 64], v3 = aw[w][lane + 96];
        float mx = fmaxf(fmaxf(v0, v1), fmaxf(v2, v3));
#pragma unroll
        for (int o = 16; o; o >>= 1) mx = fmaxf(mx, __shfl_xor_sync(0xffffffffu, mx, o));
        float e0 = __expf(v0 - mx), e1 = __expf(v1 - mx);
        float e2 = __expf(v2 - mx), e3 = __expf(v3 - mx);
        float sm = e0 + e1 + e2 + e3;
#pragma unroll
        for (int o = 16; o; o >>= 1) sm += __shfl_xor_sync(0xffffffffu, sm, o);
        float inv = 1.0f / sm;
        aw[w][lane]      = e0 * inv; aw[w][lane + 32] = e1 * inv;
        aw[w][lane + 64] = e2 * inv; aw[w][lane + 96] = e3 * inv;
    }
    __syncthreads();

    const int d = t * 4;
    float4 aC = {0,0,0,0}, aB = {0,0,0,0}, aS = {0,0,0,0}, aM = {0,0,0,0}, aD = {0,0,0,0};
    const float* x0b = x0 + (size_t)b * NN * DD;
    const float* x1b = x1 + (size_t)b * NN * DD;
    for (int n = 0; n < NN; n++) {
        float4 xv = *(const float4*)(x0b + (size_t)n * DD + d);
        float wc = aw[0][n], wb2 = aw[1][n], wm2 = aw[2][n], ws = aw[3][n];
        aC.x = fmaf(wc, xv.x, aC.x); aC.y = fmaf(wc, xv.y, aC.y);
        aC.z = fmaf(wc, xv.z, aC.z); aC.w = fmaf(wc, xv.w, aC.w);
        aB.x = fmaf(wb2, xv.x, aB.x); aB.y = fmaf(wb2, xv.y, aB.y);
        aB.z = fmaf(wb2, xv.z, aB.z); aB.w = fmaf(wb2, xv.w, aB.w);
        aM.x = fmaf(wm2, xv.x, aM.x); aM.y = fmaf(wm2, xv.y, aM.y);
        aM.z = fmaf(wm2, xv.z, aM.z); aM.w = fmaf(wm2, xv.w, aM.w);
        aS.x = fmaf(ws, xv.x, aS.x); aS.y = fmaf(ws, xv.y, aS.y);
        aS.z = fmaf(ws, xv.z, aS.z); aS.w = fmaf(ws, xv.w, aS.w);
        float4 yv = *(const float4*)(x1b + (size_t)n * DD + d);
        float wd = aw[4][n];
        aD.x = fmaf(wd, yv.x, aD.x); aD.y = fmaf(wd, yv.y, aD.y);
        aD.z = fmaf(wd, yv.z, aD.z); aD.w = fmaf(wd, yv.w, aD.w);
    }
    float4 xm1 = *(const float4*)(x1b + (size_t)m * DD + d);
    float4 ag;
    ag.x = fmaxf(xm1.x, fmaxf(fmaxf(aS.x, aC.x), fmaxf(fmaxf(aD.x, aB.x), aM.x)));
    ag.y = fmaxf(xm1.y, fmaxf(fmaxf(aS.y, aC.y), fmaxf(fmaxf(aD.y, aB.y), aM.y)));
    ag.z = fmaxf(xm1.z, fmaxf(fmaxf(aS.z, aC.z), fmaxf(fmaxf(aD.z, aB.z), aM.z)));
    ag.w = fmaxf(xm1.w, fmaxf(fmaxf(aS.w, aC.w), fmaxf(fmaxf(aD.w, aB.w), aM.w)));
    float* arow = aggrep + bm * (2 * DD);
    *(float4*)(arow + d)      = xm1;
    *(float4*)(arow + DD + d) = ag;
}

// ---------------------------------------------------------------------------
// Final head
// ---------------------------------------------------------------------------
__global__ __launch_bounds__(256) void final_kernel(
    const float* __restrict__ aggrep, const float* __restrict__ w1v,
    const float* __restrict__ Wpred,  const float* __restrict__ bpred,
    float* __restrict__ out)
{
    const int b = blockIdx.x;
    const int t = threadIdx.x, lane = t & 31, w = t >> 5;
    __shared__ float sp[NN];
    __shared__ float r0[8], r1[8];
    const float* ab = aggrep + (size_t)b * NN * (2 * DD);

    for (int mm = w; mm < NN; mm += 8) {
        const float* ar = ab + (size_t)mm * (2 * DD);
        float acc = 0.0f;
#pragma unroll
        for (int j = lane; j < 2 * DD; j += 32) acc += ar[j] * w1v[j];
#pragma unroll
        for (int o = 16; o; o >>= 1) acc += __shfl_xor_sync(0xffffffffu, acc, o);
        if (lane == 0) sp[mm] = acc;
    }
    __syncthreads();
    if (w == 0) {
        float v0 = sp[lane], v1 = sp[lane + 32], v2 = sp[lane + 64], v3 = sp[lane + 96];
        float mx = fmaxf(fmaxf(v0, v1), fmaxf(v2, v3));
#pragma unroll
        for (int o = 16; o; o >>= 1) mx = fmaxf(mx, __shfl_xor_sync(0xffffffffu, mx, o));
        float e0 = __expf(v0 - mx), e1 = __expf(v1 - mx);
        float e2 = __expf(v2 - mx), e3 = __expf(v3 - mx);
        float sm = e0 + e1 + e2 + e3;
#pragma unroll
        for (int o = 16; o; o >>= 1) sm += __shfl_xor_sync(0xffffffffu, sm, o);
        float inv = 1.0f / sm;
        sp[lane] = e0 * inv; sp[lane + 32] = e1 * inv;
        sp[lane + 64] = e2 * inv; sp[lane + 96] = e3 * inv;
    }
    __syncthreads();

    float rp[8];
#pragma unroll
    for (int k = 0; k < 8; k++) rp[k] = 0.0f;
    for (int mm = 0; mm < NN; mm++) {
        float wgt = sp[mm];
        const float* ar = ab + (size_t)mm * (2 * DD);
#pragma unroll
        for (int k = 0; k < 8; k++) rp[k] = fmaf(wgt, ar[t + k * 256], rp[k]);
    }
    float p0 = 0.0f, p1 = 0.0f;
#pragma unroll
    for (int k = 0; k < 8; k++) {
        int j = t + k * 256;
        p0 = fmaf(rp[k], Wpred[(size_t)j * 2 + 0], p0);
        p1 = fmaf(rp[k], Wpred[(size_t)j * 2 + 1], p1);
    }
#pragma unroll
    for (int o = 16; o; o >>= 1) {
        p0 += __shfl_xor_sync(0xffffffffu, p0, o);
        p1 += __shfl_xor_sync(0xffffffffu, p1, o);
    }
    if (lane == 0) { r0[w] = p0; r1[w] = p1; }
    __syncthreads();
    if (t == 0) {
        float s0 = 0.0f, s1 = 0.0f;
#pragma unroll
        for (int i = 0; i < 8; i++) { s0 += r0[i]; s1 += r1[i]; }
        out[b * 2 + 0] = fmaxf(s0 + bpred[0], 0.0f);
        out[b * 2 + 1] = fmaxf(s1 + bpred[1], 0.0f);
    }
}

// ---------------------------------------------------------------------------
extern "C" void kernel_launch(void* const* d_in, const int* in_sizes, int n_in,
                              void* d_out, int out_size)
{
    (void)in_sizes; (void)n_in; (void)out_size;
    float* S = nullptr;
    cudaGetSymbolAddress((void**)&S, g_scratch);
    __half* HP = nullptr;
    cudaGetSymbolAddress((void**)&HP, g_half);

    const float* x0    = (const float*)d_in[0];
    const float* x1    = (const float*)d_in[1];
    const float* Wc1   = (const float*)d_in[2];
    const float* Wc2   = (const float*)d_in[3];
    const float* vc    = (const float*)d_in[4];
    const float* Wb    = (const float*)d_in[5];
    const float* Wd1   = (const float*)d_in[6];
    const float* vd1   = (const float*)d_in[7];
    const float* Wd2   = (const float*)d_in[8];
    const float* vd2   = (const float*)d_in[9];
    const float* Wm    = (const float*)d_in[10];
    const float* vm    = (const float*)d_in[11];
    const float* Wp1   = (const float*)d_in[14];
    const float* vp    = (const float*)d_in[16];
    const float* Wpred = (const float*)d_in[17];
    const float* bpred = (const float*)d_in[18];
    float* out = (float*)d_out;

    cudaFuncSetAttribute(dot_scores_mma,
                         cudaFuncAttributeMaxDynamicSharedMemorySize, MSMEM);
    cudaFuncSetAttribute(proj_mma,
                         cudaFuncAttributeMaxDynamicSharedMemorySize, PSMEM);

    __half* w1t  = HP + HW1;
    __half* w2t  = HP + HW2;
    __half* xh0  = HP + HX0;
    __half* xh1  = HP + HX1;
    __half* wc1t = HP + HC1;
    __half* wc2t = HP + HC2;
    __half* wmt  = HP + HM;
    __half* wbt  = HP + HB;

    // Launch 0: all prep fused (weights transpose+fp16, x fp16, w1v)
    prep_fused<<<dim3(1024, 9), 256>>>(Wd1, Wd2, Wc1, Wc2, Wm, Wb,
                                       x0, x1, Wp1, vp, HP, S + OFF_W1V);

    // Launch 1: projections
    proj_mma<<<dim3(8, 8, 5), 256, PSMEM>>>(xh0, xh1, wc1t, wc2t, wmt, wbt, S);

    // Launches 2-4: pairwise scores (independent of dot)
    pair_scores<<<dim3(NN, BB), 256>>>(S + OFF_XC, S + OFF_YC, vc, S + OFF_SC,  1.0f);
    pair_scores<<<dim3(NN, BB), 256>>>(S + OFF_XM, S + OFF_YM, vm, S + OFF_SMN, -1.0f);
    bilin_scores<<<dim3(NN, BB), 256>>>(x1, S + OFF_XB, S + OFF_SB);

    // Launch 5 (ncu -s 5 -c 1 captures THIS): dominant dot-attention scores
    dot_scores_mma<<<dim3(4, 64, 2 * BB), 512, MSMEM>>>(
        xh0, xh1, x0, x1, w1t, w2t, vd1, vd2, S + OFF_SD1, S + OFF_SD2);

    // Fused softmax/weighted-sum/max + final head
    fuse_att<<<dim3(NN, BB), 256>>>(S + OFF_SC, S + OFF_SB, S + OFF_SMN,
                                    S + OFF_SD1, S + OFF_SD2, x0, x1, S + OFF_AGG);
    final_kernel<<<BB, 256>>>(S + OFF_AGG, S + OFF_W1V, Wpred, bpred, out);
}

// round 9
// speedup vs baseline: 1.0355x; 1.0355x over previous
#include <cuda_runtime.h>
#include <cuda_fp16.h>
#include <cstdint>
#include <cstddef>

// ---------------------------------------------------------------------------
// Problem constants: B=8, N=M=128, H=512, D=2H=1024
// ---------------------------------------------------------------------------
#define BB   8
#define NN   128
#define HH   512
#define DD   1024

// Scratch layout (floats)
#define SZ_PROJ (BB*NN*HH)
#define SZ_XB   (BB*NN*DD)
#define SZ_S    (BB*NN*NN)
#define SZ_SD   (BB*NN*2*NN)
#define SZ_AGG  (BB*NN*2*DD)

#define OFF_XC  0
#define OFF_YC  (OFF_XC + SZ_PROJ)
#define OFF_XM  (OFF_YC + SZ_PROJ)
#define OFF_YM  (OFF_XM + SZ_PROJ)
#define OFF_XB  (OFF_YM + SZ_PROJ)
#define OFF_SC  (OFF_XB + SZ_XB)
#define OFF_SB  (OFF_SC + SZ_S)
#define OFF_SMN (OFF_SB + SZ_S)
#define OFF_SD1 (OFF_SMN + SZ_S)
#define OFF_SD2 (OFF_SD1 + SZ_SD)
#define OFF_AGG (OFF_SD2 + SZ_SD)
#define OFF_W1V (OFF_AGG + SZ_AGG)
#define SCRATCH_TOTAL (OFF_W1V + 2*DD)

__device__ float g_scratch[SCRATCH_TOTAL];

// fp16 pool: dot W^T x2, x0/x1, proj W^T x4
#define HW1 0
#define HW2 (HW1 + HH*DD)
#define HX0 (HW2 + HH*DD)
#define HX1 (HX0 + NN*BB*DD)
#define HC1 (HX1 + NN*BB*DD)
#define HC2 (HC1 + HH*DD)
#define HM  (HC2 + HH*DD)
#define HB  (HM  + HH*DD)
#define HALF_TOTAL (HB + DD*DD)
__device__ __align__(16) __half g_half[HALF_TOTAL];

// tanh via MUFU.TANH
__device__ __forceinline__ float ftanh(float x) {
    float y;
    asm("tanh.approx.f32 %0, %1;" : "=f"(y) : "f"(x));
    return y;
}

__device__ __forceinline__ uint32_t smem_u32(const void* p) {
    uint32_t a;
    asm("{ .reg .u64 t; cvta.to.shared.u64 t, %1; cvt.u32.u64 %0, t; }" : "=r"(a) : "l"(p));
    return a;
}

#define LDSM4(r0, r1, r2, r3, addr) \
    asm volatile("ldmatrix.sync.aligned.m8n8.x4.shared.b16 {%0,%1,%2,%3}, [%4];" \
        : "=r"(r0), "=r"(r1), "=r"(r2), "=r"(r3) : "r"(addr))

#define MMA16816(d, a0, a1, a2, a3, b0, b1) \
    asm volatile("mma.sync.aligned.m16n8k16.row.col.f32.f16.f16.f32 " \
        "{%0,%1,%2,%3}, {%4,%5,%6,%7}, {%8,%9}, {%0,%1,%2,%3};" \
        : "+f"((d)[0]), "+f"((d)[1]), "+f"((d)[2]), "+f"((d)[3]) \
        : "r"(a0), "r"(a1), "r"(a2), "r"(a3), "r"(b0), "r"(b1))

#define CP_ASYNC16(sa, ga) \
    asm volatile("cp.async.cg.shared.global [%0], [%1], 16;" :: "r"(sa), "l"(ga))
#define CP_COMMIT() asm volatile("cp.async.commit_group;")
#define CP_WAIT0()  asm volatile("cp.async.wait_group 0;")

// 128B-row swizzle (8 chunks of 16B): chunk ^= row&7
__device__ __forceinline__ uint32_t sw128(uint32_t row, uint32_t chunk) {
    return row * 128u + ((chunk * 16u) ^ ((row & 7u) << 4));
}

// ---------------------------------------------------------------------------
// Fused prep: all weight transposes/converts + x converts + w1v in ONE launch.
// ---------------------------------------------------------------------------
__global__ void prep_fused(
    const float* __restrict__ Wd1, const float* __restrict__ Wd2,
    const float* __restrict__ Wc1, const float* __restrict__ Wc2,
    const float* __restrict__ Wm,  const float* __restrict__ Wb,
    const float* __restrict__ x0,  const float* __restrict__ x1,
    const float* __restrict__ Wp1, const float* __restrict__ vp,
    __half* __restrict__ HP, float* __restrict__ w1v)
{
    const int task = blockIdx.y;
    const int bx = blockIdx.x;
    const int tid = threadIdx.x;

    if (task < 5) {                       // W^T converts, N=HH (512 rows)
        if (bx >= HH) return;
        const float* W; __half* wt;
        switch (task) {
            case 0: W = Wd1; wt = HP + HW1; break;
            case 1: W = Wd2; wt = HP + HW2; break;
            case 2: W = Wc1; wt = HP + HC1; break;
            case 3: W = Wc2; wt = HP + HC2; break;
            default: W = Wm; wt = HP + HM; break;
        }
#pragma unroll
        for (int i = 0; i < 4; i++) {
            int d = tid + i * 256;
            wt[(size_t)bx * DD + d] = __float2half_rn(W[(size_t)d * HH + bx]);
        }
    } else if (task == 5) {               // Wb^T, N=DD (1024 rows)
        __half* wt = HP + HB;
#pragma unroll
        for (int i = 0; i < 4; i++) {
            int d = tid + i * 256;
            wt[(size_t)bx * DD + d] = __float2half_rn(Wb[(size_t)d * DD + bx]);
        }
    } else if (task < 8) {                // x fp32 -> fp16
        const float* x = (task == 6) ? x0 : x1;
        __half* xh = HP + ((task == 6) ? HX0 : HX1);
        int i = bx * 1024 + tid * 4;
        float4 v = *(const float4*)(x + i);
        __half2* o = (__half2*)(xh + i);
        o[0] = __floats2half2_rn(v.x, v.y);
        o[1] = __floats2half2_rn(v.z, v.w);
    } else {                              // w1v
        if (bx >= 256) return;
        int j = bx * 8 + (tid >> 5);
        int lane = tid & 31;
        const float* r = Wp1 + (size_t)j * HH;
        float acc = 0.0f;
#pragma unroll
        for (int h = lane; h < HH; h += 32) acc += r[h] * vp[h];
#pragma unroll
        for (int o = 16; o; o >>= 1) acc += __shfl_xor_sync(0xffffffffu, acc, o);
        if (lane == 0) w1v[j] = acc;
    }
}

// ---------------------------------------------------------------------------
// mma.sync fp16 dot-attention scores (R6-winning shape + half2 A-build).
// CTA per (hc 0..1, m, b*2+att). 512 thr / 16 warps, tile 128(n) x 256(h).
// K=1024 in kc=64 chunks, double-buffered cp.async for W.
// A-build: pure fp16 (HMUL2 of pre-converted x and y), ~14 ops/thread/kt.
// ---------------------------------------------------------------------------
#define MOFF_Y  0            // 2048  (y row fp16, 1024 halves)
#define MOFF_V  2048         // 1024  (v chunk fp32, 256)
#define MOFF_S  3072         // 512   (s reduction, 128 f32)
#define MOFF_A  4096         // 2 x 16384 -> 36864
#define MOFF_B  36864        // 2 x 32768 -> 102400
#define MSMEM   102400

__global__ __launch_bounds__(512, 1) void dot_scores_mma(
    const __half* __restrict__ xh0, const __half* __restrict__ xh1,
    const __half* __restrict__ w1t, const __half* __restrict__ w2t,
    const float* __restrict__ vd1, const float* __restrict__ vd2,
    float* __restrict__ sp1, float* __restrict__ sp2)
{
    extern __shared__ char smc[];
    const uint32_t sb = smem_u32(smc);

    const int hc  = blockIdx.x;           // 0..1 (h chunk of 256)
    const int m   = blockIdx.y;
    const int att = blockIdx.z & 1;
    const int b   = blockIdx.z >> 1;

    const __half* x = att ? xh1 : xh0;
    const __half* y = att ? xh0 : xh1;
    const __half* wt = att ? w2t : w1t;
    const float*  v = att ? vd2 : vd1;
    float* spart = att ? sp2 : sp1;

    const int t = threadIdx.x;
    const int lane = t & 31, wid = t >> 5;
    const int wn = wid & 3, whi = wid >> 2;       // 4 n-groups x 4 h-groups
    const int lane15 = lane & 15, lhalf = lane >> 4;

    __half* ysmh = (__half*)(smc + MOFF_Y);
    float* vsm = (float*)(smc + MOFF_V);
    float* ssm = (float*)(smc + MOFF_S);

    // y row (fp16, 1024 halves = 2KB), v chunk, zero s
    if (t < 128) ((uint4*)ysmh)[t] = ((const uint4*)(y + ((size_t)b * NN + m) * DD))[t];
    if (t < 64) ((float4*)vsm)[t] = ((const float4*)(v + hc * 256))[t];
    if (t < 128) ssm[t] = 0.0f;

    const __half* xg = x + (size_t)b * NN * DD;
    const __half* wg = wt + (size_t)(hc * 256) * DD;

    // A tile (128 x 64 fp16): an = t>>2 (0..127), chunks {ac, ac+4}
    const int an = t >> 2, ac = t & 3;
    const uint32_t a_st0 = sw128(an, ac);
    const uint32_t a_st1 = sw128(an, ac + 4);
    // B tile (256 x 64 fp16): br = t>>1 (0..255), chunks bc4..bc4+3
    const int br = t >> 1, bc4 = (t & 1) * 4;
    uint32_t b_st[4];
#pragma unroll
    for (int j = 0; j < 4; j++) b_st[j] = sw128(br, bc4 + j);

    uint4 xq[2];   // staged x (16 halves: k-offsets [ac*8, ac*8+8) and +32)

#define ISSUE_B(kt, buf) do { \
        const __half* bp_ = wg + (size_t)br * DD + (kt) * 64 + bc4 * 8; \
        uint32_t Bb_ = sb + MOFF_B + (buf) * 32768u; \
        CP_ASYNC16(Bb_ + b_st[0], bp_); \
        CP_ASYNC16(Bb_ + b_st[1], bp_ + 8); \
        CP_ASYNC16(Bb_ + b_st[2], bp_ + 16); \
        CP_ASYNC16(Bb_ + b_st[3], bp_ + 24); \
        CP_COMMIT(); \
    } while (0)

#define LOAD_X(kt) do { \
        const __half* xp_ = xg + (size_t)an * DD + (kt) * 64 + ac * 8; \
        xq[0] = *(const uint4*)xp_; \
        xq[1] = *(const uint4*)(xp_ + 32); \
    } while (0)

#define STORE_A(kt, buf) do { \
        char* Ab_ = smc + MOFF_A + (buf) * 16384; \
        _Pragma("unroll") \
        for (int c_ = 0; c_ < 2; c_++) { \
            int ko_ = (kt) * 64 + ac * 8 + c_ * 32; \
            uint4 yq_ = *(const uint4*)(ysmh + ko_); \
            const __half2* ya_ = (const __half2*)&yq_; \
            const __half2* xa_ = (const __half2*)&xq[c_]; \
            union { __half2 h2[4]; uint4 q; } o_; \
            o_.h2[0] = __hmul2(xa_[0], ya_[0]); \
            o_.h2[1] = __hmul2(xa_[1], ya_[1]); \
            o_.h2[2] = __hmul2(xa_[2], ya_[2]); \
            o_.h2[3] = __hmul2(xa_[3], ya_[3]); \
            *(uint4*)(Ab_ + (c_ ? a_st1 : a_st0)) = o_.q; \
        } \
    } while (0)

    float acc[2][8][4];
#pragma unroll
    for (int i = 0; i < 2; i++)
#pragma unroll
        for (int j = 0; j < 8; j++)
#pragma unroll
            for (int k = 0; k < 4; k++) acc[i][j][k] = 0.0f;

    ISSUE_B(0, 0);
    LOAD_X(0);
    __syncthreads();            // ysmh ready
    STORE_A(0, 0);
    CP_WAIT0();
    __syncthreads();

    uint32_t a_row[2], b_row[4];
#pragma unroll
    for (int mi = 0; mi < 2; mi++) a_row[mi] = wn * 32 + mi * 16 + lane15;
#pragma unroll
    for (int nj = 0; nj < 4; nj++) b_row[nj] = whi * 64 + nj * 16 + lane15;

    for (int kt = 0; kt < 16; kt++) {
        const int buf = kt & 1;
        if (kt < 15) { ISSUE_B(kt + 1, buf ^ 1); LOAD_X(kt + 1); }

        const uint32_t Ah = sb + MOFF_A + buf * 16384u;
        const uint32_t Bh = sb + MOFF_B + buf * 32768u;

#pragma unroll
        for (int ks = 0; ks < 4; ks++) {
            const uint32_t cidx = ks * 2 + lhalf;
            uint32_t a[2][4], bb[4][4];
#pragma unroll
            for (int mi = 0; mi < 2; mi++)
                LDSM4(a[mi][0], a[mi][1], a[mi][2], a[mi][3], Ah + sw128(a_row[mi], cidx));
#pragma unroll
            for (int nj = 0; nj < 4; nj++)
                LDSM4(bb[nj][0], bb[nj][1], bb[nj][2], bb[nj][3], Bh + sw128(b_row[nj], cidx));
#pragma unroll
            for (int mi = 0; mi < 2; mi++)
#pragma unroll
                for (int nj = 0; nj < 4; nj++) {
                    MMA16816(acc[mi][nj*2+0], a[mi][0], a[mi][1], a[mi][2], a[mi][3], bb[nj][0], bb[nj][2]);
                    MMA16816(acc[mi][nj*2+1], a[mi][0], a[mi][1], a[mi][2], a[mi][3], bb[nj][1], bb[nj][3]);
                }
        }

        if (kt < 15) { STORE_A(kt + 1, buf ^ 1); CP_WAIT0(); }
        __syncthreads();
    }

    // epilogue: tanh * v, reduce to s[n]
    float rs[2][2] = {{0.0f, 0.0f}, {0.0f, 0.0f}};
#pragma unroll
    for (int mi = 0; mi < 2; mi++)
#pragma unroll
        for (int hj = 0; hj < 8; hj++) {
            int hcol = whi * 64 + hj * 8 + (lane & 3) * 2;
            float v0 = vsm[hcol], v1 = vsm[hcol + 1];
            rs[mi][0] += ftanh(acc[mi][hj][0]) * v0 + ftanh(acc[mi][hj][1]) * v1;
            rs[mi][1] += ftanh(acc[mi][hj][2]) * v0 + ftanh(acc[mi][hj][3]) * v1;
        }
#pragma unroll
    for (int o = 1; o <= 2; o <<= 1) {
        rs[0][0] += __shfl_xor_sync(0xffffffffu, rs[0][0], o);
        rs[0][1] += __shfl_xor_sync(0xffffffffu, rs[0][1], o);
        rs[1][0] += __shfl_xor_sync(0xffffffffu, rs[1][0], o);
        rs[1][1] += __shfl_xor_sync(0xffffffffu, rs[1][1], o);
    }
    if ((lane & 3) == 0) {
        int r = wn * 32 + (lane >> 2);
        atomicAdd(&ssm[r],      rs[0][0]);
        atomicAdd(&ssm[r + 8],  rs[0][1]);
        atomicAdd(&ssm[r + 16], rs[1][0]);
        atomicAdd(&ssm[r + 24], rs[1][1]);
    }
    __syncthreads();
    if (t < 128)
        spart[(((size_t)b * NN + m) * 2 + hc) * NN + t] = ssm[t];
#undef ISSUE_B
#undef LOAD_X
#undef STORE_A
}

// ---------------------------------------------------------------------------
// fp16 mma projections (unchanged)
// ---------------------------------------------------------------------------
#define POFF_A 0
#define POFF_B 32768
#define PSMEM  65536

__global__ __launch_bounds__(256, 1) void proj_mma(
    const __half* __restrict__ xh0, const __half* __restrict__ xh1,
    const __half* __restrict__ wc1t, const __half* __restrict__ wc2t,
    const __half* __restrict__ wmt,  const __half* __restrict__ wbt,
    float* __restrict__ S)
{
    const __half* A; const __half* W; float* C; int N;
    switch (blockIdx.z) {
        case 0: A = xh0; W = wc1t; C = S + OFF_XC; N = HH; break;
        case 1: A = xh1; W = wc2t; C = S + OFF_YC; N = HH; break;
        case 2: A = xh0; W = wmt;  C = S + OFF_XM; N = HH; break;
        case 3: A = xh1; W = wmt;  C = S + OFF_YM; N = HH; break;
        default: A = xh0; W = wbt; C = S + OFF_XB; N = DD; break;
    }
    const int bn = blockIdx.x * 128;
    if (bn >= N) return;
    const int bm = blockIdx.y * 128;

    extern __shared__ char smc[];
    const uint32_t sb = smem_u32(smc);
    const int t = threadIdx.x, lane = t & 31, wid = t >> 5;
    const int wm = wid & 3, whn = wid >> 2;
    const int lane15 = lane & 15, lhalf = lane >> 4;

    const int r = t >> 1, cc4 = (t & 1) * 4;
    uint32_t st_off[4];
#pragma unroll
    for (int j = 0; j < 4; j++) st_off[j] = sw128(r, cc4 + j);
    const __half* ag = A + (size_t)(bm + r) * DD + cc4 * 8;
    const __half* wgp = W + (size_t)(bn + r) * DD + cc4 * 8;

#define P_ISSUE(kt, buf) do { \
        uint32_t Ab_ = sb + POFF_A + (buf) * 16384u; \
        uint32_t Bb_ = sb + POFF_B + (buf) * 16384u; \
        const __half* ap_ = ag + (kt) * 64; \
        const __half* bp_ = wgp + (kt) * 64; \
        _Pragma("unroll") \
        for (int j_ = 0; j_ < 4; j_++) { \
            CP_ASYNC16(Ab_ + st_off[j_], ap_ + j_ * 8); \
            CP_ASYNC16(Bb_ + st_off[j_], bp_ + j_ * 8); \
        } \
        CP_COMMIT(); \
    } while (0)

    float acc[2][8][4];
#pragma unroll
    for (int i = 0; i < 2; i++)
#pragma unroll
        for (int j = 0; j < 8; j++)
#pragma unroll
            for (int k = 0; k < 4; k++) acc[i][j][k] = 0.0f;

    P_ISSUE(0, 0);
    CP_WAIT0();
    __syncthreads();

    uint32_t a_row[2], b_row[4];
#pragma unroll
    for (int mi = 0; mi < 2; mi++) a_row[mi] = wm * 32 + mi * 16 + lane15;
#pragma unroll
    for (int nj = 0; nj < 4; nj++) b_row[nj] = whn * 64 + nj * 16 + lane15;

    for (int kt = 0; kt < 16; kt++) {
        const int buf = kt & 1;
        if (kt < 15) P_ISSUE(kt + 1, buf ^ 1);

        const uint32_t Ah = sb + POFF_A + buf * 16384u;
        const uint32_t Bh = sb + POFF_B + buf * 16384u;

#pragma unroll
        for (int ks = 0; ks < 4; ks++) {
            const uint32_t cidx = ks * 2 + lhalf;
            uint32_t a[2][4], bb[4][4];
#pragma unroll
            for (int mi = 0; mi < 2; mi++)
                LDSM4(a[mi][0], a[mi][1], a[mi][2], a[mi][3], Ah + sw128(a_row[mi], cidx));
#pragma unroll
            for (int nj = 0; nj < 4; nj++)
                LDSM4(bb[nj][0], bb[nj][1], bb[nj][2], bb[nj][3], Bh + sw128(b_row[nj], cidx));
#pragma unroll
            for (int mi = 0; mi < 2; mi++)
#pragma unroll
                for (int nj = 0; nj < 4; nj++) {
                    MMA16816(acc[mi][nj*2+0], a[mi][0], a[mi][1], a[mi][2], a[mi][3], bb[nj][0], bb[nj][2]);
                    MMA16816(acc[mi][nj*2+1], a[mi][0], a[mi][1], a[mi][2], a[mi][3], bb[nj][1], bb[nj][3]);
                }
        }

        CP_WAIT0();
        __syncthreads();
    }

#pragma unroll
    for (int mi = 0; mi < 2; mi++) {
        int row = bm + wm * 32 + mi * 16 + (lane >> 2);
#pragma unroll
        for (int nj8 = 0; nj8 < 8; nj8++) {
            int col = bn + whn * 64 + nj8 * 8 + (lane & 3) * 2;
            C[(size_t)row * N + col]           = acc[mi][nj8][0];
            C[(size_t)row * N + col + 1]       = acc[mi][nj8][1];
            C[(size_t)(row + 8) * N + col]     = acc[mi][nj8][2];
            C[(size_t)(row + 8) * N + col + 1] = acc[mi][nj8][3];
        }
    }
#undef P_ISSUE
}

// ---------------------------------------------------------------------------
// Concat/minus scores (2-row ILP per warp)
// ---------------------------------------------------------------------------
__global__ __launch_bounds__(256) void pair_scores(
    const float* __restrict__ p, const float* __restrict__ q,
    const float* __restrict__ v, float* __restrict__ s, float sign)
{
    const int m = blockIdx.x, b = blockIdx.y;
    const int t = threadIdx.x, lane = t & 31, w = t >> 5;
    __shared__ float qs[HH], vs[HH];
    if (t < 128) {
        ((float4*)qs)[t] = ((const float4*)(q + ((size_t)b * NN + m) * HH))[t];
        ((float4*)vs)[t] = ((const float4*)v)[t];
    }
    __syncthreads();
    const float* pb = p + (size_t)b * NN * HH;
    for (int n = w; n < NN; n += 16) {
        const float* pr0 = pb + (size_t)n * HH;
        const float* pr1 = pb + (size_t)(n + 8) * HH;
        float a0 = 0.0f, a1 = 0.0f;
#pragma unroll
        for (int h = 0; h < HH; h += 32) {
            int hh = h + lane;
            float qv = sign * qs[hh], vv = vs[hh];
            a0 += vv * ftanh(qv + pr0[hh]);
            a1 += vv * ftanh(qv + pr1[hh]);
        }
#pragma unroll
        for (int o = 16; o; o >>= 1) {
            a0 += __shfl_xor_sync(0xffffffffu, a0, o);
            a1 += __shfl_xor_sync(0xffffffffu, a1, o);
        }
        if (lane == 0) {
            s[((size_t)b * NN + m) * NN + n]     = a0;
            s[((size_t)b * NN + m) * NN + n + 8] = a1;
        }
    }
}

// ---------------------------------------------------------------------------
// Bilinear scores
// ---------------------------------------------------------------------------
__global__ __launch_bounds__(256) void bilin_scores(
    const float* __restrict__ y, const float* __restrict__ xb,
    float* __restrict__ s)
{
    const int m = blockIdx.x, b = blockIdx.y;
    const int t = threadIdx.x, lane = t & 31, w = t >> 5;
    __shared__ float ysm[DD];
    ((float4*)ysm)[t] = ((const float4*)(y + ((size_t)b * NN + m) * DD))[t];
    __syncthreads();
    const float* xbb = xb + (size_t)b * NN * DD;
    for (int n = w; n < NN; n += 8) {
        const float* xr = xbb + (size_t)n * DD;
        float acc = 0.0f;
#pragma unroll 8
        for (int d = lane; d < DD; d += 32) acc += ysm[d] * xr[d];
#pragma unroll
        for (int o = 16; o; o >>= 1) acc += __shfl_xor_sync(0xffffffffu, acc, o);
        if (lane == 0) s[((size_t)b * NN + m) * NN + n] = acc;
    }
}

// ---------------------------------------------------------------------------
// Fused: 5 softmaxes + 5 weighted sums + max + agg_rep write.
// ---------------------------------------------------------------------------
__global__ __launch_bounds__(256) void fuse_att(
    const float* __restrict__ sc,  const float* __restrict__ sb,
    const float* __restrict__ smn, const float* __restrict__ sd1,
    const float* __restrict__ sd2,
    const float* __restrict__ x0,  const float* __restrict__ x1,
    float* __restrict__ aggrep)
{
    const int m = blockIdx.x, b = blockIdx.y;
    const int t = threadIdx.x, lane = t & 31, w = t >> 5;
    const size_t bm = (size_t)b * NN + m;
    __shared__ float aw[5][NN];

    if (t < 128) {
        aw[0][t] = sc [bm * NN + t];
        aw[1][t] = sb [bm * NN + t];
        aw[2][t] = smn[bm * NN + t];
        aw[3][t] = sd1[(bm * 2 + 0) * NN + t] + sd1[(bm * 2 + 1) * NN + t];
        aw[4][t] = sd2[(bm * 2 + 0) * NN + t] + sd2[(bm * 2 + 1) * NN + t];
    }
    __syncthreads();

    if (w < 5) {
        float v0 = aw[w][lane], v1 = aw[w][lane + 32];
        float v2 = aw[w][lane + 64], v3 = aw[w][lane + 96];
        float mx = fmaxf(fmaxf(v0, v1), fmaxf(v2, v3));
#pragma unroll
        for (int o = 16; o; o >>= 1) mx = fmaxf(mx, __shfl_xor_sync(0xffffffffu, mx, o));
        float e0 = __expf(v0 - mx), e1 = __expf(v1 - mx);
        float e2 = __expf(v2 - mx), e3 = __expf(v3 - mx);
        float sm = e0 + e1 + e2 + e3;
#pragma unroll
        for (int o = 16; o; o >>= 1) sm += __shfl_xor_sync(0xffffffffu, sm, o);
        float inv = 1.0f / sm;
        aw[w][lane]      = e0 * inv; aw[w][lane + 32] = e1 * inv;
        aw[w][lane + 64] = e2 * inv; aw[w][lane + 96] = e3 * inv;
    }
    __syncthreads();

    const int d = t * 4;
    float4 aC = {0,0,0,0}, aB = {0,0,0,0}, aS = {0,0,0,0}, aM = {0,0,0,0}, aD = {0,0,0,0};
    const float* x0b = x0 + (size_t)b * NN * DD;
    const float* x1b = x1 + (size_t)b * NN * DD;
    for (int n = 0; n < NN; n++) {
        float4 xv = *(const float4*)(x0b + (size_t)n * DD + d);
        float wc = aw[0][n], wb2 = aw[1][n], wm2 = aw[2][n], ws = aw[3][n];
        aC.x = fmaf(wc, xv.x, aC.x); aC.y = fmaf(wc, xv.y, aC.y);
        aC.z = fmaf(wc, xv.z, aC.z); aC.w = fmaf(wc, xv.w, aC.w);
        aB.x = fmaf(wb2, xv.x, aB.x); aB.y = fmaf(wb2, xv.y, aB.y);
        aB.z = fmaf(wb2, xv.z, aB.z); aB.w = fmaf(wb2, xv.w, aB.w);
        aM.x = fmaf(wm2, xv.x, aM.x); aM.y = fmaf(wm2, xv.y, aM.y);
        aM.z = fmaf(wm2, xv.z, aM.z); aM.w = fmaf(wm2, xv.w, aM.w);
        aS.x = fmaf(ws, xv.x, aS.x); aS.y = fmaf(ws, xv.y, aS.y);
        aS.z = fmaf(ws, xv.z, aS.z); aS.w = fmaf(ws, xv.w, aS.w);
        float4 yv = *(const float4*)(x1b + (size_t)n * DD + d);
        float wd = aw[4][n];
        aD.x = fmaf(wd, yv.x, aD.x); aD.y = fmaf(wd, yv.y, aD.y);
        aD.z = fmaf(wd, yv.z, aD.z); aD.w = fmaf(wd, yv.w, aD.w);
    }
    float4 xm1 = *(const float4*)(x1b + (size_t)m * DD + d);
    float4 ag;
    ag.x = fmaxf(xm1.x, fmaxf(fmaxf(aS.x, aC.x), fmaxf(fmaxf(aD.x, aB.x), aM.x)));
    ag.y = fmaxf(xm1.y, fmaxf(fmaxf(aS.y, aC.y), fmaxf(fmaxf(aD.y, aB.y), aM.y)));
    ag.z = fmaxf(xm1.z, fmaxf(fmaxf(aS.z, aC.z), fmaxf(fmaxf(aD.z, aB.z), aM.z)));
    ag.w = fmaxf(xm1.w, fmaxf(fmaxf(aS.w, aC.w), fmaxf(fmaxf(aD.w, aB.w), aM.w)));
    float* arow = aggrep + bm * (2 * DD);
    *(float4*)(arow + d)      = xm1;
    *(float4*)(arow + DD + d) = ag;
}

// ---------------------------------------------------------------------------
// Final head
// ---------------------------------------------------------------------------
__global__ __launch_bounds__(256) void final_kernel(
    const float* __restrict__ aggrep, const float* __restrict__ w1v,
    const float* __restrict__ Wpred,  const float* __restrict__ bpred,
    float* __restrict__ out)
{
    const int b = blockIdx.x;
    const int t = threadIdx.x, lane = t & 31, w = t >> 5;
    __shared__ float sp[NN];
    __shared__ float r0[8], r1[8];
    const float* ab = aggrep + (size_t)b * NN * (2 * DD);

    for (int mm = w; mm < NN; mm += 8) {
        const float* ar = ab + (size_t)mm * (2 * DD);
        float acc = 0.0f;
#pragma unroll
        for (int j = lane; j < 2 * DD; j += 32) acc += ar[j] * w1v[j];
#pragma unroll
        for (int o = 16; o; o >>= 1) acc += __shfl_xor_sync(0xffffffffu, acc, o);
        if (lane == 0) sp[mm] = acc;
    }
    __syncthreads();
    if (w == 0) {
        float v0 = sp[lane], v1 = sp[lane + 32], v2 = sp[lane + 64], v3 = sp[lane + 96];
        float mx = fmaxf(fmaxf(v0, v1), fmaxf(v2, v3));
#pragma unroll
        for (int o = 16; o; o >>= 1) mx = fmaxf(mx, __shfl_xor_sync(0xffffffffu, mx, o));
        float e0 = __expf(v0 - mx), e1 = __expf(v1 - mx);
        float e2 = __expf(v2 - mx), e3 = __expf(v3 - mx);
        float sm = e0 + e1 + e2 + e3;
#pragma unroll
        for (int o = 16; o; o >>= 1) sm += __shfl_xor_sync(0xffffffffu, sm, o);
        float inv = 1.0f / sm;
        sp[lane] = e0 * inv; sp[lane + 32] = e1 * inv;
        sp[lane + 64] = e2 * inv; sp[lane + 96] = e3 * inv;
    }
    __syncthreads();

    float rp[8];
#pragma unroll
    for (int k = 0; k < 8; k++) rp[k] = 0.0f;
    for (int mm = 0; mm < NN; mm++) {
        float wgt = sp[mm];
        const float* ar = ab + (size_t)mm * (2 * DD);
#pragma unroll
        for (int k = 0; k < 8; k++) rp[k] = fmaf(wgt, ar[t + k * 256], rp[k]);
    }
    float p0 = 0.0f, p1 = 0.0f;
#pragma unroll
    for (int k = 0; k < 8; k++) {
        int j = t + k * 256;
        p0 = fmaf(rp[k], Wpred[(size_t)j * 2 + 0], p0);
        p1 = fmaf(rp[k], Wpred[(size_t)j * 2 + 1], p1);
    }
#pragma unroll
    for (int o = 16; o; o >>= 1) {
        p0 += __shfl_xor_sync(0xffffffffu, p0, o);
        p1 += __shfl_xor_sync(0xffffffffu, p1, o);
    }
    if (lane == 0) { r0[w] = p0; r1[w] = p1; }
    __syncthreads();
    if (t == 0) {
        float s0 = 0.0f, s1 = 0.0f;
#pragma unroll
        for (int i = 0; i < 8; i++) { s0 += r0[i]; s1 += r1[i]; }
        out[b * 2 + 0] = fmaxf(s0 + bpred[0], 0.0f);
        out[b * 2 + 1] = fmaxf(s1 + bpred[1], 0.0f);
    }
}

// ---------------------------------------------------------------------------
extern "C" void kernel_launch(void* const* d_in, const int* in_sizes, int n_in,
                              void* d_out, int out_size)
{
    (void)in_sizes; (void)n_in; (void)out_size;
    float* S = nullptr;
    cudaGetSymbolAddress((void**)&S, g_scratch);
    __half* HP = nullptr;
    cudaGetSymbolAddress((void**)&HP, g_half);

    const float* x0    = (const float*)d_in[0];
    const float* x1    = (const float*)d_in[1];
    const float* Wc1   = (const float*)d_in[2];
    const float* Wc2   = (const float*)d_in[3];
    const float* vc    = (const float*)d_in[4];
    const float* Wb    = (const float*)d_in[5];
    const float* Wd1   = (const float*)d_in[6];
    const float* vd1   = (const float*)d_in[7];
    const float* Wd2   = (const float*)d_in[8];
    const float* vd2   = (const float*)d_in[9];
    const float* Wm    = (const float*)d_in[10];
    const float* vm    = (const float*)d_in[11];
    const float* Wp1   = (const float*)d_in[14];
    const float* vp    = (const float*)d_in[16];
    const float* Wpred = (const float*)d_in[17];
    const float* bpred = (const float*)d_in[18];
    float* out = (float*)d_out;

    cudaFuncSetAttribute(dot_scores_mma,
                         cudaFuncAttributeMaxDynamicSharedMemorySize, MSMEM);
    cudaFuncSetAttribute(proj_mma,
                         cudaFuncAttributeMaxDynamicSharedMemorySize, PSMEM);

    __half* w1t  = HP + HW1;
    __half* w2t  = HP + HW2;
    __half* xh0  = HP + HX0;
    __half* xh1  = HP + HX1;
    __half* wc1t = HP + HC1;
    __half* wc2t = HP + HC2;
    __half* wmt  = HP + HM;
    __half* wbt  = HP + HB;

    // Launch 0: all prep fused
    prep_fused<<<dim3(1024, 9), 256>>>(Wd1, Wd2, Wc1, Wc2, Wm, Wb,
                                       x0, x1, Wp1, vp, HP, S + OFF_W1V);

    // Launch 1: projections
    proj_mma<<<dim3(8, 8, 5), 256, PSMEM>>>(xh0, xh1, wc1t, wc2t, wmt, wbt, S);

    // Launches 2-4: pairwise scores
    pair_scores<<<dim3(NN, BB), 256>>>(S + OFF_XC, S + OFF_YC, vc, S + OFF_SC,  1.0f);
    pair_scores<<<dim3(NN, BB), 256>>>(S + OFF_XM, S + OFF_YM, vm, S + OFF_SMN, -1.0f);
    bilin_scores<<<dim3(NN, BB), 256>>>(x1, S + OFF_XB, S + OFF_SB);

    // Launch 5: dominant dot-attention scores (R6 shape, half2 A-build)
    dot_scores_mma<<<dim3(2, NN, 2 * BB), 512, MSMEM>>>(
        xh0, xh1, w1t, w2t, vd1, vd2, S + OFF_SD1, S + OFF_SD2);

    // Fused softmax/weighted-sum/max + final head
    fuse_att<<<dim3(NN, BB), 256>>>(S + OFF_SC, S + OFF_SB, S + OFF_SMN,
                                    S + OFF_SD1, S + OFF_SD2, x0, x1, S + OFF_AGG);
    final_kernel<<<BB, 256>>>(S + OFF_AGG, S + OFF_W1V, Wpred, bpred, out);
}

// round 10
// speedup vs baseline: 1.0796x; 1.0426x over previous
#include <cuda_runtime.h>
#include <cuda_fp16.h>
#include <cstdint>
#include <cstddef>

// ---------------------------------------------------------------------------
// Problem constants: B=8, N=M=128, H=512, D=2H=1024
// ---------------------------------------------------------------------------
#define BB   8
#define NN   128
#define HH   512
#define DD   1024

// Scratch layout (floats)
#define SZ_PROJ (BB*NN*HH)
#define SZ_XB   (BB*NN*DD)
#define SZ_S    (BB*NN*NN)
#define SZ_SD   (BB*NN*2*NN)
#define SZ_AGG  (BB*NN*2*DD)

#define OFF_XC  0
#define OFF_YC  (OFF_XC + SZ_PROJ)
#define OFF_XM  (OFF_YC + SZ_PROJ)
#define OFF_YM  (OFF_XM + SZ_PROJ)
#define OFF_XB  (OFF_YM + SZ_PROJ)
#define OFF_SC  (OFF_XB + SZ_XB)
#define OFF_SB  (OFF_SC + SZ_S)
#define OFF_SMN (OFF_SB + SZ_S)
#define OFF_SD1 (OFF_SMN + SZ_S)
#define OFF_SD2 (OFF_SD1 + SZ_SD)
#define OFF_AGG (OFF_SD2 + SZ_SD)
#define OFF_W1V (OFF_AGG + SZ_AGG)
#define SCRATCH_TOTAL (OFF_W1V + 2*DD)

__device__ float g_scratch[SCRATCH_TOTAL];

// fp16 pool: dot W^T x2, x0/x1, proj W^T x4
#define HW1 0
#define HW2 (HW1 + HH*DD)
#define HX0 (HW2 + HH*DD)
#define HX1 (HX0 + NN*BB*DD)
#define HC1 (HX1 + NN*BB*DD)
#define HC2 (HC1 + HH*DD)
#define HM  (HC2 + HH*DD)
#define HB  (HM  + HH*DD)
#define HALF_TOTAL (HB + DD*DD)
__device__ __align__(16) __half g_half[HALF_TOTAL];

// tanh via MUFU.TANH
__device__ __forceinline__ float ftanh(float x) {
    float y;
    asm("tanh.approx.f32 %0, %1;" : "=f"(y) : "f"(x));
    return y;
}

__device__ __forceinline__ uint32_t smem_u32(const void* p) {
    uint32_t a;
    asm("{ .reg .u64 t; cvta.to.shared.u64 t, %1; cvt.u32.u64 %0, t; }" : "=r"(a) : "l"(p));
    return a;
}

#define LDSM4(r0, r1, r2, r3, addr) \
    asm volatile("ldmatrix.sync.aligned.m8n8.x4.shared.b16 {%0,%1,%2,%3}, [%4];" \
        : "=r"(r0), "=r"(r1), "=r"(r2), "=r"(r3) : "r"(addr))

#define MMA16816(d, a0, a1, a2, a3, b0, b1) \
    asm volatile("mma.sync.aligned.m16n8k16.row.col.f32.f16.f16.f32 " \
        "{%0,%1,%2,%3}, {%4,%5,%6,%7}, {%8,%9}, {%0,%1,%2,%3};" \
        : "+f"((d)[0]), "+f"((d)[1]), "+f"((d)[2]), "+f"((d)[3]) \
        : "r"(a0), "r"(a1), "r"(a2), "r"(a3), "r"(b0), "r"(b1))

#define CP_ASYNC16(sa, ga) \
    asm volatile("cp.async.cg.shared.global [%0], [%1], 16;" :: "r"(sa), "l"(ga))
#define CP_COMMIT() asm volatile("cp.async.commit_group;")
#define CP_WAIT0()  asm volatile("cp.async.wait_group 0;")

// 128B-row swizzle (8 chunks of 16B): chunk ^= row&7
__device__ __forceinline__ uint32_t sw128(uint32_t row, uint32_t chunk) {
    return row * 128u + ((chunk * 16u) ^ ((row & 7u) << 4));
}

// ---------------------------------------------------------------------------
// Fused prep: all weight transposes/converts + x converts + w1v in ONE launch.
// ---------------------------------------------------------------------------
__global__ void prep_fused(
    const float* __restrict__ Wd1, const float* __restrict__ Wd2,
    const float* __restrict__ Wc1, const float* __restrict__ Wc2,
    const float* __restrict__ Wm,  const float* __restrict__ Wb,
    const float* __restrict__ x0,  const float* __restrict__ x1,
    const float* __restrict__ Wp1, const float* __restrict__ vp,
    __half* __restrict__ HP, float* __restrict__ w1v)
{
    const int task = blockIdx.y;
    const int bx = blockIdx.x;
    const int tid = threadIdx.x;

    if (task < 5) {                       // W^T converts, N=HH (512 rows)
        if (bx >= HH) return;
        const float* W; __half* wt;
        switch (task) {
            case 0: W = Wd1; wt = HP + HW1; break;
            case 1: W = Wd2; wt = HP + HW2; break;
            case 2: W = Wc1; wt = HP + HC1; break;
            case 3: W = Wc2; wt = HP + HC2; break;
            default: W = Wm; wt = HP + HM; break;
        }
#pragma unroll
        for (int i = 0; i < 4; i++) {
            int d = tid + i * 256;
            wt[(size_t)bx * DD + d] = __float2half_rn(W[(size_t)d * HH + bx]);
        }
    } else if (task == 5) {               // Wb^T, N=DD (1024 rows)
        __half* wt = HP + HB;
#pragma unroll
        for (int i = 0; i < 4; i++) {
            int d = tid + i * 256;
            wt[(size_t)bx * DD + d] = __float2half_rn(Wb[(size_t)d * DD + bx]);
        }
    } else if (task < 8) {                // x fp32 -> fp16
        const float* x = (task == 6) ? x0 : x1;
        __half* xh = HP + ((task == 6) ? HX0 : HX1);
        int i = bx * 1024 + tid * 4;
        float4 v = *(const float4*)(x + i);
        __half2* o = (__half2*)(xh + i);
        o[0] = __floats2half2_rn(v.x, v.y);
        o[1] = __floats2half2_rn(v.z, v.w);
    } else {                              // w1v
        if (bx >= 256) return;
        int j = bx * 8 + (tid >> 5);
        int lane = tid & 31;
        const float* r = Wp1 + (size_t)j * HH;
        float acc = 0.0f;
#pragma unroll
        for (int h = lane; h < HH; h += 32) acc += r[h] * vp[h];
#pragma unroll
        for (int o = 16; o; o >>= 1) acc += __shfl_xor_sync(0xffffffffu, acc, o);
        if (lane == 0) w1v[j] = acc;
    }
}

// ---------------------------------------------------------------------------
// mma.sync fp16 dot-attention scores — EXACT R6 best-measured variant.
// CTA per (hc 0..1, m, b*2+att). 512 thr / 16 warps, tile 128(n) x 256(h).
// K=1024 in kc=64 chunks, double-buffered cp.async for W; A from fp32 x*y.
// ---------------------------------------------------------------------------
#define MOFF_Y  0            // 4096
#define MOFF_V  4096         // 1024
#define MOFF_S  5120         // 512
#define MOFF_A  8192         // 2 x 16384 -> 40960
#define MOFF_B  40960        // 2 x 32768 -> 106496
#define MSMEM   106496

__global__ __launch_bounds__(512, 1) void dot_scores_mma(
    const float* __restrict__ x0, const float* __restrict__ x1,
    const __half* __restrict__ w1t, const __half* __restrict__ w2t,
    const float* __restrict__ vd1, const float* __restrict__ vd2,
    float* __restrict__ sp1, float* __restrict__ sp2)
{
    extern __shared__ char smc[];
    const uint32_t sb = smem_u32(smc);

    const int hc  = blockIdx.x;
    const int m   = blockIdx.y;
    const int att = blockIdx.z & 1;
    const int b   = blockIdx.z >> 1;

    const float* x = att ? x1 : x0;
    const float* y = att ? x0 : x1;
    const __half* wt = att ? w2t : w1t;
    const float* v = att ? vd2 : vd1;
    float* spart = att ? sp2 : sp1;

    const int t = threadIdx.x;
    const int lane = t & 31, wid = t >> 5;
    const int wn = wid & 3, whi = wid >> 2;
    const int lane15 = lane & 15, lhalf = lane >> 4;

    float* ysm = (float*)(smc + MOFF_Y);
    float* vsm = (float*)(smc + MOFF_V);
    float* ssm = (float*)(smc + MOFF_S);

    ((float2*)ysm)[t] = ((const float2*)(y + ((size_t)b * NN + m) * DD))[t];
    if (t < 64) ((float4*)vsm)[t] = ((const float4*)(v + hc * 256))[t];
    if (t < 128) ssm[t] = 0.0f;

    const float* xg = x + (size_t)b * NN * DD;
    const __half* wg = wt + (size_t)(hc * 256) * DD;

    // A tile (128 x 64 fp16, 128B rows): an = t>>2 (0..127), chunks {ac, ac+4}
    const int an = t >> 2, ac = t & 3;
    const uint32_t a_st0 = sw128(an, ac);
    const uint32_t a_st1 = sw128(an, ac + 4);
    // B tile (256 x 64 fp16): br = t>>1 (0..255), chunks bc4..bc4+3
    const int br = t >> 1, bc4 = (t & 1) * 4;
    uint32_t b_st[4];
#pragma unroll
    for (int j = 0; j < 4; j++) b_st[j] = sw128(br, bc4 + j);

    float xs[16];   // staged x (2 chunks x 8)

#define ISSUE_B(kt, buf) do { \
        const __half* bp_ = wg + (size_t)br * DD + (kt) * 64 + bc4 * 8; \
        uint32_t Bb_ = sb + MOFF_B + (buf) * 32768u; \
        CP_ASYNC16(Bb_ + b_st[0], bp_); \
        CP_ASYNC16(Bb_ + b_st[1], bp_ + 8); \
        CP_ASYNC16(Bb_ + b_st[2], bp_ + 16); \
        CP_ASYNC16(Bb_ + b_st[3], bp_ + 24); \
        CP_COMMIT(); \
    } while (0)

#define LOAD_X(kt) do { \
        const float* xp_ = xg + (size_t)an * DD + (kt) * 64 + ac * 8; \
        *(float4*)&xs[0]  = *(const float4*)xp_; \
        *(float4*)&xs[4]  = *(const float4*)(xp_ + 4); \
        *(float4*)&xs[8]  = *(const float4*)(xp_ + 32); \
        *(float4*)&xs[12] = *(const float4*)(xp_ + 36); \
    } while (0)

#define STORE_A(kt, buf) do { \
        int kb_ = (kt) * 64 + ac * 8; \
        union { __half h[8]; uint4 q; } u0_, u1_; \
        _Pragma("unroll") \
        for (int j_ = 0; j_ < 8; j_++) { \
            u0_.h[j_] = __float2half_rn(xs[j_]     * ysm[kb_ + j_]); \
            u1_.h[j_] = __float2half_rn(xs[j_ + 8] * ysm[kb_ + 32 + j_]); \
        } \
        char* Ab_ = smc + MOFF_A + (buf) * 16384; \
        *(uint4*)(Ab_ + a_st0) = u0_.q; \
        *(uint4*)(Ab_ + a_st1) = u1_.q; \
    } while (0)

    float acc[2][8][4];
#pragma unroll
    for (int i = 0; i < 2; i++)
#pragma unroll
        for (int j = 0; j < 8; j++)
#pragma unroll
            for (int k = 0; k < 4; k++) acc[i][j][k] = 0.0f;

    ISSUE_B(0, 0);
    LOAD_X(0);
    __syncthreads();
    STORE_A(0, 0);
    CP_WAIT0();
    __syncthreads();

    uint32_t a_row[2], b_row[4];
#pragma unroll
    for (int mi = 0; mi < 2; mi++) a_row[mi] = wn * 32 + mi * 16 + lane15;
#pragma unroll
    for (int nj = 0; nj < 4; nj++) b_row[nj] = whi * 64 + nj * 16 + lane15;

    for (int kt = 0; kt < 16; kt++) {
        const int buf = kt & 1;
        if (kt < 15) { ISSUE_B(kt + 1, buf ^ 1); LOAD_X(kt + 1); }

        const uint32_t Ah = sb + MOFF_A + buf * 16384u;
        const uint32_t Bh = sb + MOFF_B + buf * 32768u;

#pragma unroll
        for (int ks = 0; ks < 4; ks++) {
            const uint32_t cidx = ks * 2 + lhalf;
            uint32_t a[2][4], bb[4][4];
#pragma unroll
            for (int mi = 0; mi < 2; mi++)
                LDSM4(a[mi][0], a[mi][1], a[mi][2], a[mi][3], Ah + sw128(a_row[mi], cidx));
#pragma unroll
            for (int nj = 0; nj < 4; nj++)
                LDSM4(bb[nj][0], bb[nj][1], bb[nj][2], bb[nj][3], Bh + sw128(b_row[nj], cidx));
#pragma unroll
            for (int mi = 0; mi < 2; mi++)
#pragma unroll
                for (int nj = 0; nj < 4; nj++) {
                    MMA16816(acc[mi][nj*2+0], a[mi][0], a[mi][1], a[mi][2], a[mi][3], bb[nj][0], bb[nj][2]);
                    MMA16816(acc[mi][nj*2+1], a[mi][0], a[mi][1], a[mi][2], a[mi][3], bb[nj][1], bb[nj][3]);
                }
        }

        if (kt < 15) { STORE_A(kt + 1, buf ^ 1); CP_WAIT0(); }
        __syncthreads();
    }

    // epilogue: tanh * v, reduce to s[n]
    float rs[2][2] = {{0.0f, 0.0f}, {0.0f, 0.0f}};
#pragma unroll
    for (int mi = 0; mi < 2; mi++)
#pragma unroll
        for (int hj = 0; hj < 8; hj++) {
            int hcol = whi * 64 + hj * 8 + (lane & 3) * 2;
            float v0 = vsm[hcol], v1 = vsm[hcol + 1];
            rs[mi][0] += ftanh(acc[mi][hj][0]) * v0 + ftanh(acc[mi][hj][1]) * v1;
            rs[mi][1] += ftanh(acc[mi][hj][2]) * v0 + ftanh(acc[mi][hj][3]) * v1;
        }
#pragma unroll
    for (int o = 1; o <= 2; o <<= 1) {
        rs[0][0] += __shfl_xor_sync(0xffffffffu, rs[0][0], o);
        rs[0][1] += __shfl_xor_sync(0xffffffffu, rs[0][1], o);
        rs[1][0] += __shfl_xor_sync(0xffffffffu, rs[1][0], o);
        rs[1][1] += __shfl_xor_sync(0xffffffffu, rs[1][1], o);
    }
    if ((lane & 3) == 0) {
        int r = wn * 32 + (lane >> 2);
        atomicAdd(&ssm[r],      rs[0][0]);
        atomicAdd(&ssm[r + 8],  rs[0][1]);
        atomicAdd(&ssm[r + 16], rs[1][0]);
        atomicAdd(&ssm[r + 24], rs[1][1]);
    }
    __syncthreads();
    if (t < 128)
        spart[(((size_t)b * NN + m) * 2 + hc) * NN + t] = ssm[t];
#undef ISSUE_B
#undef LOAD_X
#undef STORE_A
}

// ---------------------------------------------------------------------------
// fp16 mma projections (unchanged)
// ---------------------------------------------------------------------------
#define POFF_A 0
#define POFF_B 32768
#define PSMEM  65536

__global__ __launch_bounds__(256, 1) void proj_mma(
    const __half* __restrict__ xh0, const __half* __restrict__ xh1,
    const __half* __restrict__ wc1t, const __half* __restrict__ wc2t,
    const __half* __restrict__ wmt,  const __half* __restrict__ wbt,
    float* __restrict__ S)
{
    const __half* A; const __half* W; float* C; int N;
    switch (blockIdx.z) {
        case 0: A = xh0; W = wc1t; C = S + OFF_XC; N = HH; break;
        case 1: A = xh1; W = wc2t; C = S + OFF_YC; N = HH; break;
        case 2: A = xh0; W = wmt;  C = S + OFF_XM; N = HH; break;
        case 3: A = xh1; W = wmt;  C = S + OFF_YM; N = HH; break;
        default: A = xh0; W = wbt; C = S + OFF_XB; N = DD; break;
    }
    const int bn = blockIdx.x * 128;
    if (bn >= N) return;
    const int bm = blockIdx.y * 128;

    extern __shared__ char smc[];
    const uint32_t sb = smem_u32(smc);
    const int t = threadIdx.x, lane = t & 31, wid = t >> 5;
    const int wm = wid & 3, whn = wid >> 2;
    const int lane15 = lane & 15, lhalf = lane >> 4;

    const int r = t >> 1, cc4 = (t & 1) * 4;
    uint32_t st_off[4];
#pragma unroll
    for (int j = 0; j < 4; j++) st_off[j] = sw128(r, cc4 + j);
    const __half* ag = A + (size_t)(bm + r) * DD + cc4 * 8;
    const __half* wgp = W + (size_t)(bn + r) * DD + cc4 * 8;

#define P_ISSUE(kt, buf) do { \
        uint32_t Ab_ = sb + POFF_A + (buf) * 16384u; \
        uint32_t Bb_ = sb + POFF_B + (buf) * 16384u; \
        const __half* ap_ = ag + (kt) * 64; \
        const __half* bp_ = wgp + (kt) * 64; \
        _Pragma("unroll") \
        for (int j_ = 0; j_ < 4; j_++) { \
            CP_ASYNC16(Ab_ + st_off[j_], ap_ + j_ * 8); \
            CP_ASYNC16(Bb_ + st_off[j_], bp_ + j_ * 8); \
        } \
        CP_COMMIT(); \
    } while (0)

    float acc[2][8][4];
#pragma unroll
    for (int i = 0; i < 2; i++)
#pragma unroll
        for (int j = 0; j < 8; j++)
#pragma unroll
            for (int k = 0; k < 4; k++) acc[i][j][k] = 0.0f;

    P_ISSUE(0, 0);
    CP_WAIT0();
    __syncthreads();

    uint32_t a_row[2], b_row[4];
#pragma unroll
    for (int mi = 0; mi < 2; mi++) a_row[mi] = wm * 32 + mi * 16 + lane15;
#pragma unroll
    for (int nj = 0; nj < 4; nj++) b_row[nj] = whn * 64 + nj * 16 + lane15;

    for (int kt = 0; kt < 16; kt++) {
        const int buf = kt & 1;
        if (kt < 15) P_ISSUE(kt + 1, buf ^ 1);

        const uint32_t Ah = sb + POFF_A + buf * 16384u;
        const uint32_t Bh = sb + POFF_B + buf * 16384u;

#pragma unroll
        for (int ks = 0; ks < 4; ks++) {
            const uint32_t cidx = ks * 2 + lhalf;
            uint32_t a[2][4], bb[4][4];
#pragma unroll
            for (int mi = 0; mi < 2; mi++)
                LDSM4(a[mi][0], a[mi][1], a[mi][2], a[mi][3], Ah + sw128(a_row[mi], cidx));
#pragma unroll
            for (int nj = 0; nj < 4; nj++)
                LDSM4(bb[nj][0], bb[nj][1], bb[nj][2], bb[nj][3], Bh + sw128(b_row[nj], cidx));
#pragma unroll
            for (int mi = 0; mi < 2; mi++)
#pragma unroll
                for (int nj = 0; nj < 4; nj++) {
                    MMA16816(acc[mi][nj*2+0], a[mi][0], a[mi][1], a[mi][2], a[mi][3], bb[nj][0], bb[nj][2]);
                    MMA16816(acc[mi][nj*2+1], a[mi][0], a[mi][1], a[mi][2], a[mi][3], bb[nj][1], bb[nj][3]);
                }
        }

        CP_WAIT0();
        __syncthreads();
    }

#pragma unroll
    for (int mi = 0; mi < 2; mi++) {
        int row = bm + wm * 32 + mi * 16 + (lane >> 2);
#pragma unroll
        for (int nj8 = 0; nj8 < 8; nj8++) {
            int col = bn + whn * 64 + nj8 * 8 + (lane & 3) * 2;
            C[(size_t)row * N + col]           = acc[mi][nj8][0];
            C[(size_t)row * N + col + 1]       = acc[mi][nj8][1];
            C[(size_t)(row + 8) * N + col]     = acc[mi][nj8][2];
            C[(size_t)(row + 8) * N + col + 1] = acc[mi][nj8][3];
        }
    }
#undef P_ISSUE
}

// ---------------------------------------------------------------------------
// Concat/minus scores (R6 variant)
// ---------------------------------------------------------------------------
__global__ __launch_bounds__(256) void pair_scores(
    const float* __restrict__ p, const float* __restrict__ q,
    const float* __restrict__ v, float* __restrict__ s, float sign)
{
    const int m = blockIdx.x, b = blockIdx.y;
    const int t = threadIdx.x, lane = t & 31, w = t >> 5;
    __shared__ float qs[HH], vs[HH];
    if (t < 128) {
        ((float4*)qs)[t] = ((const float4*)(q + ((size_t)b * NN + m) * HH))[t];
        ((float4*)vs)[t] = ((const float4*)v)[t];
    }
    __syncthreads();
    const float* pb = p + (size_t)b * NN * HH;
    for (int n = w; n < NN; n += 8) {
        const float* pr = pb + (size_t)n * HH;
        float acc = 0.0f;
#pragma unroll
        for (int h = 0; h < HH; h += 32) {
            int hh = h + lane;
            acc += vs[hh] * ftanh(fmaf(sign, qs[hh], pr[hh]));
        }
#pragma unroll
        for (int o = 16; o; o >>= 1) acc += __shfl_xor_sync(0xffffffffu, acc, o);
        if (lane == 0) s[((size_t)b * NN + m) * NN + n] = acc;
    }
}

// ---------------------------------------------------------------------------
// Bilinear scores
// ---------------------------------------------------------------------------
__global__ __launch_bounds__(256) void bilin_scores(
    const float* __restrict__ y, const float* __restrict__ xb,
    float* __restrict__ s)
{
    const int m = blockIdx.x, b = blockIdx.y;
    const int t = threadIdx.x, lane = t & 31, w = t >> 5;
    __shared__ float ysm[DD];
    ((float4*)ysm)[t] = ((const float4*)(y + ((size_t)b * NN + m) * DD))[t];
    __syncthreads();
    const float* xbb = xb + (size_t)b * NN * DD;
    for (int n = w; n < NN; n += 8) {
        const float* xr = xbb + (size_t)n * DD;
        float acc = 0.0f;
#pragma unroll 8
        for (int d = lane; d < DD; d += 32) acc += ysm[d] * xr[d];
#pragma unroll
        for (int o = 16; o; o >>= 1) acc += __shfl_xor_sync(0xffffffffu, acc, o);
        if (lane == 0) s[((size_t)b * NN + m) * NN + n] = acc;
    }
}

// ---------------------------------------------------------------------------
// Fused: 5 softmaxes + 5 weighted sums + max + agg_rep write.
// ---------------------------------------------------------------------------
__global__ __launch_bounds__(256) void fuse_att(
    const float* __restrict__ sc,  const float* __restrict__ sb,
    const float* __restrict__ smn, const float* __restrict__ sd1,
    const float* __restrict__ sd2,
    const float* __restrict__ x0,  const float* __restrict__ x1,
    float* __restrict__ aggrep)
{
    const int m = blockIdx.x, b = blockIdx.y;
    const int t = threadIdx.x, lane = t & 31, w = t >> 5;
    const size_t bm = (size_t)b * NN + m;
    __shared__ float aw[5][NN];

    if (t < 128) {
        aw[0][t] = sc [bm * NN + t];
        aw[1][t] = sb [bm * NN + t];
        aw[2][t] = smn[bm * NN + t];
        aw[3][t] = sd1[(bm * 2 + 0) * NN + t] + sd1[(bm * 2 + 1) * NN + t];
        aw[4][t] = sd2[(bm * 2 + 0) * NN + t] + sd2[(bm * 2 + 1) * NN + t];
    }
    __syncthreads();

    if (w < 5) {
        float v0 = aw[w][lane], v1 = aw[w][lane + 32];
        float v2 = aw[w][lane + 64], v3 = aw[w][lane + 96];
        float mx = fmaxf(fmaxf(v0, v1), fmaxf(v2, v3));
#pragma unroll
        for (int o = 16; o; o >>= 1) mx = fmaxf(mx, __shfl_xor_sync(0xffffffffu, mx, o));
        float e0 = __expf(v0 - mx), e1 = __expf(v1 - mx);
        float e2 = __expf(v2 - mx), e3 = __expf(v3 - mx);
        float sm = e0 + e1 + e2 + e3;
#pragma unroll
        for (int o = 16; o; o >>= 1) sm += __shfl_xor_sync(0xffffffffu, sm, o);
        float inv = 1.0f / sm;
        aw[w][lane]      = e0 * inv; aw[w][lane + 32] = e1 * inv;
        aw[w][lane + 64] = e2 * inv; aw[w][lane + 96] = e3 * inv;
    }
    __syncthreads();

    const int d = t * 4;
    float4 aC = {0,0,0,0}, aB = {0,0,0,0}, aS = {0,0,0,0}, aM = {0,0,0,0}, aD = {0,0,0,0};
    const float* x0b = x0 + (size_t)b * NN * DD;
    const float* x1b = x1 + (size_t)b * NN * DD;
    for (int n = 0; n < NN; n++) {
        float4 xv = *(const float4*)(x0b + (size_t)n * DD + d);
        float wc = aw[0][n], wb2 = aw[1][n], wm2 = aw[2][n], ws = aw[3][n];
        aC.x = fmaf(wc, xv.x, aC.x); aC.y = fmaf(wc, xv.y, aC.y);
        aC.z = fmaf(wc, xv.z, aC.z); aC.w = fmaf(wc, xv.w, aC.w);
        aB.x = fmaf(wb2, xv.x, aB.x); aB.y = fmaf(wb2, xv.y, aB.y);
        aB.z = fmaf(wb2, xv.z, aB.z); aB.w = fmaf(wb2, xv.w, aB.w);
        aM.x = fmaf(wm2, xv.x, aM.x); aM.y = fmaf(wm2, xv.y, aM.y);
        aM.z = fmaf(wm2, xv.z, aM.z); aM.w = fmaf(wm2, xv.w, aM.w);
        aS.x = fmaf(ws, xv.x, aS.x); aS.y = fmaf(ws, xv.y, aS.y);
        aS.z = fmaf(ws, xv.z, aS.z); aS.w = fmaf(ws, xv.w, aS.w);
        float4 yv = *(const float4*)(x1b + (size_t)n * DD + d);
        float wd = aw[4][n];
        aD.x = fmaf(wd, yv.x, aD.x); aD.y = fmaf(wd, yv.y, aD.y);
        aD.z = fmaf(wd, yv.z, aD.z); aD.w = fmaf(wd, yv.w, aD.w);
    }
    float4 xm1 = *(const float4*)(x1b + (size_t)m * DD + d);
    float4 ag;
    ag.x = fmaxf(xm1.x, fmaxf(fmaxf(aS.x, aC.x), fmaxf(fmaxf(aD.x, aB.x), aM.x)));
    ag.y = fmaxf(xm1.y, fmaxf(fmaxf(aS.y, aC.y), fmaxf(fmaxf(aD.y, aB.y), aM.y)));
    ag.z = fmaxf(xm1.z, fmaxf(fmaxf(aS.z, aC.z), fmaxf(fmaxf(aD.z, aB.z), aM.z)));
    ag.w = fmaxf(xm1.w, fmaxf(fmaxf(aS.w, aC.w), fmaxf(fmaxf(aD.w, aB.w), aM.w)));
    float* arow = aggrep + bm * (2 * DD);
    *(float4*)(arow + d)      = xm1;
    *(float4*)(arow + DD + d) = ag;
}

// ---------------------------------------------------------------------------
// Final head
// ---------------------------------------------------------------------------
__global__ __launch_bounds__(256) void final_kernel(
    const float* __restrict__ aggrep, const float* __restrict__ w1v,
    const float* __restrict__ Wpred,  const float* __restrict__ bpred,
    float* __restrict__ out)
{
    const int b = blockIdx.x;
    const int t = threadIdx.x, lane = t & 31, w = t >> 5;
    __shared__ float sp[NN];
    __shared__ float r0[8], r1[8];
    const float* ab = aggrep + (size_t)b * NN * (2 * DD);

    for (int mm = w; mm < NN; mm += 8) {
        const float* ar = ab + (size_t)mm * (2 * DD);
        float acc = 0.0f;
#pragma unroll
        for (int j = lane; j < 2 * DD; j += 32) acc += ar[j] * w1v[j];
#pragma unroll
        for (int o = 16; o; o >>= 1) acc += __shfl_xor_sync(0xffffffffu, acc, o);
        if (lane == 0) sp[mm] = acc;
    }
    __syncthreads();
    if (w == 0) {
        float v0 = sp[lane], v1 = sp[lane + 32], v2 = sp[lane + 64], v3 = sp[lane + 96];
        float mx = fmaxf(fmaxf(v0, v1), fmaxf(v2, v3));
#pragma unroll
        for (int o = 16; o; o >>= 1) mx = fmaxf(mx, __shfl_xor_sync(0xffffffffu, mx, o));
        float e0 = __expf(v0 - mx), e1 = __expf(v1 - mx);
        float e2 = __expf(v2 - mx), e3 = __expf(v3 - mx);
        float sm = e0 + e1 + e2 + e3;
#pragma unroll
        for (int o = 16; o; o >>= 1) sm += __shfl_xor_sync(0xffffffffu, sm, o);
        float inv = 1.0f / sm;
        sp[lane] = e0 * inv; sp[lane + 32] = e1 * inv;
        sp[lane + 64] = e2 * inv; sp[lane + 96] = e3 * inv;
    }
    __syncthreads();

    float rp[8];
#pragma unroll
    for (int k = 0; k < 8; k++) rp[k] = 0.0f;
    for (int mm = 0; mm < NN; mm++) {
        float wgt = sp[mm];
        const float* ar = ab + (size_t)mm * (2 * DD);
#pragma unroll
        for (int k = 0; k < 8; k++) rp[k] = fmaf(wgt, ar[t + k * 256], rp[k]);
    }
    float p0 = 0.0f, p1 = 0.0f;
#pragma unroll
    for (int k = 0; k < 8; k++) {
        int j = t + k * 256;
        p0 = fmaf(rp[k], Wpred[(size_t)j * 2 + 0], p0);
        p1 = fmaf(rp[k], Wpred[(size_t)j * 2 + 1], p1);
    }
#pragma unroll
    for (int o = 16; o; o >>= 1) {
        p0 += __shfl_xor_sync(0xffffffffu, p0, o);
        p1 += __shfl_xor_sync(0xffffffffu, p1, o);
    }
    if (lane == 0) { r0[w] = p0; r1[w] = p1; }
    __syncthreads();
    if (t == 0) {
        float s0 = 0.0f, s1 = 0.0f;
#pragma unroll
        for (int i = 0; i < 8; i++) { s0 += r0[i]; s1 += r1[i]; }
        out[b * 2 + 0] = fmaxf(s0 + bpred[0], 0.0f);
        out[b * 2 + 1] = fmaxf(s1 + bpred[1], 0.0f);
    }
}

// ---------------------------------------------------------------------------
extern "C" void kernel_launch(void* const* d_in, const int* in_sizes, int n_in,
                              void* d_out, int out_size)
{
    (void)in_sizes; (void)n_in; (void)out_size;
    float* S = nullptr;
    cudaGetSymbolAddress((void**)&S, g_scratch);
    __half* HP = nullptr;
    cudaGetSymbolAddress((void**)&HP, g_half);

    const float* x0    = (const float*)d_in[0];
    const float* x1    = (const float*)d_in[1];
    const float* Wc1   = (const float*)d_in[2];
    const float* Wc2   = (const float*)d_in[3];
    const float* vc    = (const float*)d_in[4];
    const float* Wb    = (const float*)d_in[5];
    const float* Wd1   = (const float*)d_in[6];
    const float* vd1   = (const float*)d_in[7];
    const float* Wd2   = (const float*)d_in[8];
    const float* vd2   = (const float*)d_in[9];
    const float* Wm    = (const float*)d_in[10];
    const float* vm    = (const float*)d_in[11];
    const float* Wp1   = (const float*)d_in[14];
    const float* vp    = (const float*)d_in[16];
    const float* Wpred = (const float*)d_in[17];
    const float* bpred = (const float*)d_in[18];
    float* out = (float*)d_out;

    // One-time host objects (created on the first, un-captured correctness
    // call; no device memory involved).
    static cudaStream_t s_dot = nullptr;
    static cudaEvent_t ev_prep = nullptr, ev_dot = nullptr;
    static bool attrs_set = false;
    if (!attrs_set) {
        cudaFuncSetAttribute(dot_scores_mma,
                             cudaFuncAttributeMaxDynamicSharedMemorySize, MSMEM);
        cudaFuncSetAttribute(proj_mma,
                             cudaFuncAttributeMaxDynamicSharedMemorySize, PSMEM);
        cudaStreamCreateWithFlags(&s_dot, cudaStreamNonBlocking);
        cudaEventCreateWithFlags(&ev_prep, cudaEventDisableTiming);
        cudaEventCreateWithFlags(&ev_dot, cudaEventDisableTiming);
        attrs_set = true;
    }

    __half* w1t  = HP + HW1;
    __half* w2t  = HP + HW2;
    __half* xh0  = HP + HX0;
    __half* xh1  = HP + HX1;
    __half* wc1t = HP + HC1;
    __half* wc2t = HP + HC2;
    __half* wmt  = HP + HM;
    __half* wbt  = HP + HB;

    // Prep (main stream): everything downstream depends on it.
    prep_fused<<<dim3(1024, 9), 256>>>(Wd1, Wd2, Wc1, Wc2, Wm, Wb,
                                       x0, x1, Wp1, vp, HP, S + OFF_W1V);
    cudaEventRecord(ev_prep, 0);

    // Fork: the ~870us dot kernel runs concurrently with the small kernels.
    cudaStreamWaitEvent(s_dot, ev_prep, 0);
    dot_scores_mma<<<dim3(2, NN, 2 * BB), 512, MSMEM, s_dot>>>(
        x0, x1, w1t, w2t, vd1, vd2, S + OFF_SD1, S + OFF_SD2);
    cudaEventRecord(ev_dot, s_dot);

    // Main stream: projections + other scores (independent of dot).
    proj_mma<<<dim3(8, 8, 5), 256, PSMEM>>>(xh0, xh1, wc1t, wc2t, wmt, wbt, S);
    pair_scores<<<dim3(NN, BB), 256>>>(S + OFF_XC, S + OFF_YC, vc, S + OFF_SC,  1.0f);
    pair_scores<<<dim3(NN, BB), 256>>>(S + OFF_XM, S + OFF_YM, vm, S + OFF_SMN, -1.0f);
    bilin_scores<<<dim3(NN, BB), 256>>>(x1, S + OFF_XB, S + OFF_SB);

    // Join: fuse needs the dot scores.
    cudaStreamWaitEvent(0, ev_dot, 0);
    fuse_att<<<dim3(NN, BB), 256>>>(S + OFF_SC, S + OFF_SB, S + OFF_SMN,
                                    S + OFF_SD1, S + OFF_SD2, x0, x1, S + OFF_AGG);
    final_kernel<<<BB, 256>>>(S + OFF_AGG, S + OFF_W1V, Wpred, bpred, out);
}

// round 11
// speedup vs baseline: 1.1157x; 1.0334x over previous
#include <cuda_runtime.h>
#include <cuda_fp16.h>
#include <cstdint>
#include <cstddef>

// ---------------------------------------------------------------------------
// Problem constants: B=8, N=M=128, H=512, D=2H=1024
// ---------------------------------------------------------------------------
#define BB   8
#define NN   128
#define HH   512
#define DD   1024

// Scratch layout (floats)
#define SZ_PROJ (BB*NN*HH)
#define SZ_XB   (BB*NN*DD)
#define SZ_S    (BB*NN*NN)
#define SZ_SD   (BB*NN*2*NN)
#define SZ_AGG  (BB*NN*2*DD)

#define OFF_XC  0
#define OFF_YC  (OFF_XC + SZ_PROJ)
#define OFF_XM  (OFF_YC + SZ_PROJ)
#define OFF_YM  (OFF_XM + SZ_PROJ)
#define OFF_XB  (OFF_YM + SZ_PROJ)
#define OFF_SC  (OFF_XB + SZ_XB)
#define OFF_SB  (OFF_SC + SZ_S)
#define OFF_SMN (OFF_SB + SZ_S)
#define OFF_SD1 (OFF_SMN + SZ_S)
#define OFF_SD2 (OFF_SD1 + SZ_SD)
#define OFF_AGG (OFF_SD2 + SZ_SD)
#define OFF_W1V (OFF_AGG + SZ_AGG)
#define SCRATCH_TOTAL (OFF_W1V + 2*DD)

__device__ float g_scratch[SCRATCH_TOTAL];

// fp16 pool: dot W^T x2, x0/x1, proj W^T x4, xb fp16
#define HW1 0
#define HW2 (HW1 + HH*DD)
#define HX0 (HW2 + HH*DD)
#define HX1 (HX0 + NN*BB*DD)
#define HC1 (HX1 + NN*BB*DD)
#define HC2 (HC1 + HH*DD)
#define HM  (HC2 + HH*DD)
#define HB  (HM  + HH*DD)
#define HXB (HB  + DD*DD)
#define HALF_TOTAL (HXB + NN*BB*DD)
__device__ __align__(16) __half g_half[HALF_TOTAL];

// tanh via MUFU.TANH
__device__ __forceinline__ float ftanh(float x) {
    float y;
    asm("tanh.approx.f32 %0, %1;" : "=f"(y) : "f"(x));
    return y;
}

__device__ __forceinline__ uint32_t smem_u32(const void* p) {
    uint32_t a;
    asm("{ .reg .u64 t; cvta.to.shared.u64 t, %1; cvt.u32.u64 %0, t; }" : "=r"(a) : "l"(p));
    return a;
}

#define LDSM4(r0, r1, r2, r3, addr) \
    asm volatile("ldmatrix.sync.aligned.m8n8.x4.shared.b16 {%0,%1,%2,%3}, [%4];" \
        : "=r"(r0), "=r"(r1), "=r"(r2), "=r"(r3) : "r"(addr))

#define MMA16816(d, a0, a1, a2, a3, b0, b1) \
    asm volatile("mma.sync.aligned.m16n8k16.row.col.f32.f16.f16.f32 " \
        "{%0,%1,%2,%3}, {%4,%5,%6,%7}, {%8,%9}, {%0,%1,%2,%3};" \
        : "+f"((d)[0]), "+f"((d)[1]), "+f"((d)[2]), "+f"((d)[3]) \
        : "r"(a0), "r"(a1), "r"(a2), "r"(a3), "r"(b0), "r"(b1))

#define CP_ASYNC16(sa, ga) \
    asm volatile("cp.async.cg.shared.global [%0], [%1], 16;" :: "r"(sa), "l"(ga))
#define CP_COMMIT() asm volatile("cp.async.commit_group;")
#define CP_WAIT0()  asm volatile("cp.async.wait_group 0;")

// 128B-row swizzle (8 chunks of 16B): chunk ^= row&7
__device__ __forceinline__ uint32_t sw128(uint32_t row, uint32_t chunk) {
    return row * 128u + ((chunk * 16u) ^ ((row & 7u) << 4));
}

// ---------------------------------------------------------------------------
// Fused prep
// ---------------------------------------------------------------------------
__global__ void prep_fused(
    const float* __restrict__ Wd1, const float* __restrict__ Wd2,
    const float* __restrict__ Wc1, const float* __restrict__ Wc2,
    const float* __restrict__ Wm,  const float* __restrict__ Wb,
    const float* __restrict__ x0,  const float* __restrict__ x1,
    const float* __restrict__ Wp1, const float* __restrict__ vp,
    __half* __restrict__ HP, float* __restrict__ w1v)
{
    const int task = blockIdx.y;
    const int bx = blockIdx.x;
    const int tid = threadIdx.x;

    if (task < 5) {
        if (bx >= HH) return;
        const float* W; __half* wt;
        switch (task) {
            case 0: W = Wd1; wt = HP + HW1; break;
            case 1: W = Wd2; wt = HP + HW2; break;
            case 2: W = Wc1; wt = HP + HC1; break;
            case 3: W = Wc2; wt = HP + HC2; break;
            default: W = Wm; wt = HP + HM; break;
        }
#pragma unroll
        for (int i = 0; i < 4; i++) {
            int d = tid + i * 256;
            wt[(size_t)bx * DD + d] = __float2half_rn(W[(size_t)d * HH + bx]);
        }
    } else if (task == 5) {
        __half* wt = HP + HB;
#pragma unroll
        for (int i = 0; i < 4; i++) {
            int d = tid + i * 256;
            wt[(size_t)bx * DD + d] = __float2half_rn(Wb[(size_t)d * DD + bx]);
        }
    } else if (task < 8) {
        const float* x = (task == 6) ? x0 : x1;
        __half* xh = HP + ((task == 6) ? HX0 : HX1);
        int i = bx * 1024 + tid * 4;
        float4 v = *(const float4*)(x + i);
        __half2* o = (__half2*)(xh + i);
        o[0] = __floats2half2_rn(v.x, v.y);
        o[1] = __floats2half2_rn(v.z, v.w);
    } else {
        if (bx >= 256) return;
        int j = bx * 8 + (tid >> 5);
        int lane = tid & 31;
        const float* r = Wp1 + (size_t)j * HH;
        float acc = 0.0f;
#pragma unroll
        for (int h = lane; h < HH; h += 32) acc += r[h] * vp[h];
#pragma unroll
        for (int o = 16; o; o >>= 1) acc += __shfl_xor_sync(0xffffffffu, acc, o);
        if (lane == 0) w1v[j] = acc;
    }
}

// ---------------------------------------------------------------------------
// mma.sync fp16 dot-attention scores — R6 best-measured variant (unchanged).
// ---------------------------------------------------------------------------
#define MOFF_Y  0
#define MOFF_V  4096
#define MOFF_S  5120
#define MOFF_A  8192
#define MOFF_B  40960
#define MSMEM   106496

__global__ __launch_bounds__(512, 1) void dot_scores_mma(
    const float* __restrict__ x0, const float* __restrict__ x1,
    const __half* __restrict__ w1t, const __half* __restrict__ w2t,
    const float* __restrict__ vd1, const float* __restrict__ vd2,
    float* __restrict__ sp1, float* __restrict__ sp2)
{
    extern __shared__ char smc[];
    const uint32_t sb = smem_u32(smc);

    const int hc  = blockIdx.x;
    const int m   = blockIdx.y;
    const int att = blockIdx.z & 1;
    const int b   = blockIdx.z >> 1;

    const float* x = att ? x1 : x0;
    const float* y = att ? x0 : x1;
    const __half* wt = att ? w2t : w1t;
    const float* v = att ? vd2 : vd1;
    float* spart = att ? sp2 : sp1;

    const int t = threadIdx.x;
    const int lane = t & 31, wid = t >> 5;
    const int wn = wid & 3, whi = wid >> 2;
    const int lane15 = lane & 15, lhalf = lane >> 4;

    float* ysm = (float*)(smc + MOFF_Y);
    float* vsm = (float*)(smc + MOFF_V);
    float* ssm = (float*)(smc + MOFF_S);

    ((float2*)ysm)[t] = ((const float2*)(y + ((size_t)b * NN + m) * DD))[t];
    if (t < 64) ((float4*)vsm)[t] = ((const float4*)(v + hc * 256))[t];
    if (t < 128) ssm[t] = 0.0f;

    const float* xg = x + (size_t)b * NN * DD;
    const __half* wg = wt + (size_t)(hc * 256) * DD;

    const int an = t >> 2, ac = t & 3;
    const uint32_t a_st0 = sw128(an, ac);
    const uint32_t a_st1 = sw128(an, ac + 4);
    const int br = t >> 1, bc4 = (t & 1) * 4;
    uint32_t b_st[4];
#pragma unroll
    for (int j = 0; j < 4; j++) b_st[j] = sw128(br, bc4 + j);

    float xs[16];

#define ISSUE_B(kt, buf) do { \
        const __half* bp_ = wg + (size_t)br * DD + (kt) * 64 + bc4 * 8; \
        uint32_t Bb_ = sb + MOFF_B + (buf) * 32768u; \
        CP_ASYNC16(Bb_ + b_st[0], bp_); \
        CP_ASYNC16(Bb_ + b_st[1], bp_ + 8); \
        CP_ASYNC16(Bb_ + b_st[2], bp_ + 16); \
        CP_ASYNC16(Bb_ + b_st[3], bp_ + 24); \
        CP_COMMIT(); \
    } while (0)

#define LOAD_X(kt) do { \
        const float* xp_ = xg + (size_t)an * DD + (kt) * 64 + ac * 8; \
        *(float4*)&xs[0]  = *(const float4*)xp_; \
        *(float4*)&xs[4]  = *(const float4*)(xp_ + 4); \
        *(float4*)&xs[8]  = *(const float4*)(xp_ + 32); \
        *(float4*)&xs[12] = *(const float4*)(xp_ + 36); \
    } while (0)

#define STORE_A(kt, buf) do { \
        int kb_ = (kt) * 64 + ac * 8; \
        union { __half h[8]; uint4 q; } u0_, u1_; \
        _Pragma("unroll") \
        for (int j_ = 0; j_ < 8; j_++) { \
            u0_.h[j_] = __float2half_rn(xs[j_]     * ysm[kb_ + j_]); \
            u1_.h[j_] = __float2half_rn(xs[j_ + 8] * ysm[kb_ + 32 + j_]); \
        } \
        char* Ab_ = smc + MOFF_A + (buf) * 16384; \
        *(uint4*)(Ab_ + a_st0) = u0_.q; \
        *(uint4*)(Ab_ + a_st1) = u1_.q; \
    } while (0)

    float acc[2][8][4];
#pragma unroll
    for (int i = 0; i < 2; i++)
#pragma unroll
        for (int j = 0; j < 8; j++)
#pragma unroll
            for (int k = 0; k < 4; k++) acc[i][j][k] = 0.0f;

    ISSUE_B(0, 0);
    LOAD_X(0);
    __syncthreads();
    STORE_A(0, 0);
    CP_WAIT0();
    __syncthreads();

    uint32_t a_row[2], b_row[4];
#pragma unroll
    for (int mi = 0; mi < 2; mi++) a_row[mi] = wn * 32 + mi * 16 + lane15;
#pragma unroll
    for (int nj = 0; nj < 4; nj++) b_row[nj] = whi * 64 + nj * 16 + lane15;

    for (int kt = 0; kt < 16; kt++) {
        const int buf = kt & 1;
        if (kt < 15) { ISSUE_B(kt + 1, buf ^ 1); LOAD_X(kt + 1); }

        const uint32_t Ah = sb + MOFF_A + buf * 16384u;
        const uint32_t Bh = sb + MOFF_B + buf * 32768u;

#pragma unroll
        for (int ks = 0; ks < 4; ks++) {
            const uint32_t cidx = ks * 2 + lhalf;
            uint32_t a[2][4], bb[4][4];
#pragma unroll
            for (int mi = 0; mi < 2; mi++)
                LDSM4(a[mi][0], a[mi][1], a[mi][2], a[mi][3], Ah + sw128(a_row[mi], cidx));
#pragma unroll
            for (int nj = 0; nj < 4; nj++)
                LDSM4(bb[nj][0], bb[nj][1], bb[nj][2], bb[nj][3], Bh + sw128(b_row[nj], cidx));
#pragma unroll
            for (int mi = 0; mi < 2; mi++)
#pragma unroll
                for (int nj = 0; nj < 4; nj++) {
                    MMA16816(acc[mi][nj*2+0], a[mi][0], a[mi][1], a[mi][2], a[mi][3], bb[nj][0], bb[nj][2]);
                    MMA16816(acc[mi][nj*2+1], a[mi][0], a[mi][1], a[mi][2], a[mi][3], bb[nj][1], bb[nj][3]);
                }
        }

        if (kt < 15) { STORE_A(kt + 1, buf ^ 1); CP_WAIT0(); }
        __syncthreads();
    }

    float rs[2][2] = {{0.0f, 0.0f}, {0.0f, 0.0f}};
#pragma unroll
    for (int mi = 0; mi < 2; mi++)
#pragma unroll
        for (int hj = 0; hj < 8; hj++) {
            int hcol = whi * 64 + hj * 8 + (lane & 3) * 2;
            float v0 = vsm[hcol], v1 = vsm[hcol + 1];
            rs[mi][0] += ftanh(acc[mi][hj][0]) * v0 + ftanh(acc[mi][hj][1]) * v1;
            rs[mi][1] += ftanh(acc[mi][hj][2]) * v0 + ftanh(acc[mi][hj][3]) * v1;
        }
#pragma unroll
    for (int o = 1; o <= 2; o <<= 1) {
        rs[0][0] += __shfl_xor_sync(0xffffffffu, rs[0][0], o);
        rs[0][1] += __shfl_xor_sync(0xffffffffu, rs[0][1], o);
        rs[1][0] += __shfl_xor_sync(0xffffffffu, rs[1][0], o);
        rs[1][1] += __shfl_xor_sync(0xffffffffu, rs[1][1], o);
    }
    if ((lane & 3) == 0) {
        int r = wn * 32 + (lane >> 2);
        atomicAdd(&ssm[r],      rs[0][0]);
        atomicAdd(&ssm[r + 8],  rs[0][1]);
        atomicAdd(&ssm[r + 16], rs[1][0]);
        atomicAdd(&ssm[r + 24], rs[1][1]);
    }
    __syncthreads();
    if (t < 128)
        spart[(((size_t)b * NN + m) * 2 + hc) * NN + t] = ssm[t];
#undef ISSUE_B
#undef LOAD_X
#undef STORE_A
}

// ---------------------------------------------------------------------------
// fp16 mma projections; z==4 additionally emits fp16 xb for the bilin kernel.
// ---------------------------------------------------------------------------
#define POFF_A 0
#define POFF_B 32768
#define PSMEM  65536

__global__ __launch_bounds__(256, 1) void proj_mma(
    const __half* __restrict__ xh0, const __half* __restrict__ xh1,
    const __half* __restrict__ wc1t, const __half* __restrict__ wc2t,
    const __half* __restrict__ wmt,  const __half* __restrict__ wbt,
    float* __restrict__ S, __half* __restrict__ xbh)
{
    const __half* A; const __half* W; float* C; int N;
    switch (blockIdx.z) {
        case 0: A = xh0; W = wc1t; C = S + OFF_XC; N = HH; break;
        case 1: A = xh1; W = wc2t; C = S + OFF_YC; N = HH; break;
        case 2: A = xh0; W = wmt;  C = S + OFF_XM; N = HH; break;
        case 3: A = xh1; W = wmt;  C = S + OFF_YM; N = HH; break;
        default: A = xh0; W = wbt; C = S + OFF_XB; N = DD; break;
    }
    const int bn = blockIdx.x * 128;
    if (bn >= N) return;
    const int bm = blockIdx.y * 128;
    const bool isXB = (blockIdx.z == 4);

    extern __shared__ char smc[];
    const uint32_t sb = smem_u32(smc);
    const int t = threadIdx.x, lane = t & 31, wid = t >> 5;
    const int wm = wid & 3, whn = wid >> 2;
    const int lane15 = lane & 15, lhalf = lane >> 4;

    const int r = t >> 1, cc4 = (t & 1) * 4;
    uint32_t st_off[4];
#pragma unroll
    for (int j = 0; j < 4; j++) st_off[j] = sw128(r, cc4 + j);
    const __half* ag = A + (size_t)(bm + r) * DD + cc4 * 8;
    const __half* wgp = W + (size_t)(bn + r) * DD + cc4 * 8;

#define P_ISSUE(kt, buf) do { \
        uint32_t Ab_ = sb + POFF_A + (buf) * 16384u; \
        uint32_t Bb_ = sb + POFF_B + (buf) * 16384u; \
        const __half* ap_ = ag + (kt) * 64; \
        const __half* bp_ = wgp + (kt) * 64; \
        _Pragma("unroll") \
        for (int j_ = 0; j_ < 4; j_++) { \
            CP_ASYNC16(Ab_ + st_off[j_], ap_ + j_ * 8); \
            CP_ASYNC16(Bb_ + st_off[j_], bp_ + j_ * 8); \
        } \
        CP_COMMIT(); \
    } while (0)

    float acc[2][8][4];
#pragma unroll
    for (int i = 0; i < 2; i++)
#pragma unroll
        for (int j = 0; j < 8; j++)
#pragma unroll
            for (int k = 0; k < 4; k++) acc[i][j][k] = 0.0f;

    P_ISSUE(0, 0);
    CP_WAIT0();
    __syncthreads();

    uint32_t a_row[2], b_row[4];
#pragma unroll
    for (int mi = 0; mi < 2; mi++) a_row[mi] = wm * 32 + mi * 16 + lane15;
#pragma unroll
    for (int nj = 0; nj < 4; nj++) b_row[nj] = whn * 64 + nj * 16 + lane15;

    for (int kt = 0; kt < 16; kt++) {
        const int buf = kt & 1;
        if (kt < 15) P_ISSUE(kt + 1, buf ^ 1);

        const uint32_t Ah = sb + POFF_A + buf * 16384u;
        const uint32_t Bh = sb + POFF_B + buf * 16384u;

#pragma unroll
        for (int ks = 0; ks < 4; ks++) {
            const uint32_t cidx = ks * 2 + lhalf;
            uint32_t a[2][4], bb[4][4];
#pragma unroll
            for (int mi = 0; mi < 2; mi++)
                LDSM4(a[mi][0], a[mi][1], a[mi][2], a[mi][3], Ah + sw128(a_row[mi], cidx));
#pragma unroll
            for (int nj = 0; nj < 4; nj++)
                LDSM4(bb[nj][0], bb[nj][1], bb[nj][2], bb[nj][3], Bh + sw128(b_row[nj], cidx));
#pragma unroll
            for (int mi = 0; mi < 2; mi++)
#pragma unroll
                for (int nj = 0; nj < 4; nj++) {
                    MMA16816(acc[mi][nj*2+0], a[mi][0], a[mi][1], a[mi][2], a[mi][3], bb[nj][0], bb[nj][2]);
                    MMA16816(acc[mi][nj*2+1], a[mi][0], a[mi][1], a[mi][2], a[mi][3], bb[nj][1], bb[nj][3]);
                }
        }

        CP_WAIT0();
        __syncthreads();
    }

#pragma unroll
    for (int mi = 0; mi < 2; mi++) {
        int row = bm + wm * 32 + mi * 16 + (lane >> 2);
#pragma unroll
        for (int nj8 = 0; nj8 < 8; nj8++) {
            int col = bn + whn * 64 + nj8 * 8 + (lane & 3) * 2;
            float c0 = acc[mi][nj8][0], c1 = acc[mi][nj8][1];
            float c2 = acc[mi][nj8][2], c3 = acc[mi][nj8][3];
            C[(size_t)row * N + col]           = c0;
            C[(size_t)row * N + col + 1]       = c1;
            C[(size_t)(row + 8) * N + col]     = c2;
            C[(size_t)(row + 8) * N + col + 1] = c3;
            if (isXB) {
                *(__half2*)&xbh[(size_t)row * DD + col]       = __floats2half2_rn(c0, c1);
                *(__half2*)&xbh[(size_t)(row + 8) * DD + col] = __floats2half2_rn(c2, c3);
            }
        }
    }
#undef P_ISSUE
}

// ---------------------------------------------------------------------------
// Bilinear scores on tensor cores: s[b] = x1h[b] @ xbh[b]^T. One CTA per b.
// ---------------------------------------------------------------------------
__global__ __launch_bounds__(256, 1) void bilin_tc(
    const __half* __restrict__ xh1, const __half* __restrict__ xbh,
    float* __restrict__ sbuf)
{
    const int b = blockIdx.x;
    const __half* A = xh1 + (size_t)b * NN * DD;
    const __half* Bq = xbh + (size_t)b * NN * DD;

    extern __shared__ char smc[];
    const uint32_t sb = smem_u32(smc);
    const int t = threadIdx.x, lane = t & 31, wid = t >> 5;
    const int wm = wid & 3, whn = wid >> 2;
    const int lane15 = lane & 15, lhalf = lane >> 4;

    const int r = t >> 1, cc4 = (t & 1) * 4;
    uint32_t st_off[4];
#pragma unroll
    for (int j = 0; j < 4; j++) st_off[j] = sw128(r, cc4 + j);
    const __half* ag = A + (size_t)r * DD + cc4 * 8;
    const __half* bg = Bq + (size_t)r * DD + cc4 * 8;

#define BL_ISSUE(kt, buf) do { \
        uint32_t Ab_ = sb + POFF_A + (buf) * 16384u; \
        uint32_t Bb_ = sb + POFF_B + (buf) * 16384u; \
        const __half* ap_ = ag + (kt) * 64; \
        const __half* bp_ = bg + (kt) * 64; \
        _Pragma("unroll") \
        for (int j_ = 0; j_ < 4; j_++) { \
            CP_ASYNC16(Ab_ + st_off[j_], ap_ + j_ * 8); \
            CP_ASYNC16(Bb_ + st_off[j_], bp_ + j_ * 8); \
        } \
        CP_COMMIT(); \
    } while (0)

    float acc[2][8][4];
#pragma unroll
    for (int i = 0; i < 2; i++)
#pragma unroll
        for (int j = 0; j < 8; j++)
#pragma unroll
            for (int k = 0; k < 4; k++) acc[i][j][k] = 0.0f;

    BL_ISSUE(0, 0);
    CP_WAIT0();
    __syncthreads();

    uint32_t a_row[2], b_row[4];
#pragma unroll
    for (int mi = 0; mi < 2; mi++) a_row[mi] = wm * 32 + mi * 16 + lane15;
#pragma unroll
    for (int nj = 0; nj < 4; nj++) b_row[nj] = whn * 64 + nj * 16 + lane15;

    for (int kt = 0; kt < 16; kt++) {
        const int buf = kt & 1;
        if (kt < 15) BL_ISSUE(kt + 1, buf ^ 1);

        const uint32_t Ah = sb + POFF_A + buf * 16384u;
        const uint32_t Bh = sb + POFF_B + buf * 16384u;

#pragma unroll
        for (int ks = 0; ks < 4; ks++) {
            const uint32_t cidx = ks * 2 + lhalf;
            uint32_t a[2][4], bb[4][4];
#pragma unroll
            for (int mi = 0; mi < 2; mi++)
                LDSM4(a[mi][0], a[mi][1], a[mi][2], a[mi][3], Ah + sw128(a_row[mi], cidx));
#pragma unroll
            for (int nj = 0; nj < 4; nj++)
                LDSM4(bb[nj][0], bb[nj][1], bb[nj][2], bb[nj][3], Bh + sw128(b_row[nj], cidx));
#pragma unroll
            for (int mi = 0; mi < 2; mi++)
#pragma unroll
                for (int nj = 0; nj < 4; nj++) {
                    MMA16816(acc[mi][nj*2+0], a[mi][0], a[mi][1], a[mi][2], a[mi][3], bb[nj][0], bb[nj][2]);
                    MMA16816(acc[mi][nj*2+1], a[mi][0], a[mi][1], a[mi][2], a[mi][3], bb[nj][1], bb[nj][3]);
                }
        }

        CP_WAIT0();
        __syncthreads();
    }

#pragma unroll
    for (int mi = 0; mi < 2; mi++) {
        int row = wm * 32 + mi * 16 + (lane >> 2);
#pragma unroll
        for (int nj8 = 0; nj8 < 8; nj8++) {
            int col = whn * 64 + nj8 * 8 + (lane & 3) * 2;
            sbuf[((size_t)b * NN + row) * NN + col]           = acc[mi][nj8][0];
            sbuf[((size_t)b * NN + row) * NN + col + 1]       = acc[mi][nj8][1];
            sbuf[((size_t)b * NN + row + 8) * NN + col]       = acc[mi][nj8][2];
            sbuf[((size_t)b * NN + row + 8) * NN + col + 1]   = acc[mi][nj8][3];
        }
    }
#undef BL_ISSUE
}

// ---------------------------------------------------------------------------
// Concat + minus scores, one launch (z selects which).
// ---------------------------------------------------------------------------
__global__ __launch_bounds__(256) void pair_scores2(
    const float* __restrict__ pc, const float* __restrict__ qc,
    const float* __restrict__ vcv, float* __restrict__ sc,
    const float* __restrict__ pm, const float* __restrict__ qm,
    const float* __restrict__ vmv, float* __restrict__ smn)
{
    const int m = blockIdx.x, b = blockIdx.y, z = blockIdx.z;
    const float* p = z ? pm : pc;
    const float* q = z ? qm : qc;
    const float* v = z ? vmv : vcv;
    float* s = z ? smn : sc;
    const float sign = z ? -1.0f : 1.0f;

    const int t = threadIdx.x, lane = t & 31, w = t >> 5;
    __shared__ float qs[HH], vs[HH];
    if (t < 128) {
        ((float4*)qs)[t] = ((const float4*)(q + ((size_t)b * NN + m) * HH))[t];
        ((float4*)vs)[t] = ((const float4*)v)[t];
    }
    __syncthreads();
    const float* pb = p + (size_t)b * NN * HH;
    for (int n = w; n < NN; n += 8) {
        const float* pr = pb + (size_t)n * HH;
        float acc = 0.0f;
#pragma unroll
        for (int h = 0; h < HH; h += 32) {
            int hh = h + lane;
            acc += vs[hh] * ftanh(fmaf(sign, qs[hh], pr[hh]));
        }
#pragma unroll
        for (int o = 16; o; o >>= 1) acc += __shfl_xor_sync(0xffffffffu, acc, o);
        if (lane == 0) s[((size_t)b * NN + m) * NN + n] = acc;
    }
}

// ---------------------------------------------------------------------------
// Fused: 20 softmaxes + weighted sums + max + agg_rep, 4 m's per CTA (x reuse).
// grid (32, 8), 256 threads.
// ---------------------------------------------------------------------------
__global__ __launch_bounds__(256) void fuse_att4(
    const float* __restrict__ sc,  const float* __restrict__ sb,
    const float* __restrict__ smn, const float* __restrict__ sd1,
    const float* __restrict__ sd2,
    const float* __restrict__ x0,  const float* __restrict__ x1,
    float* __restrict__ aggrep)
{
    const int m0 = blockIdx.x * 4, b = blockIdx.y;
    const int t = threadIdx.x, lane = t & 31, w = t >> 5;
    __shared__ float aw[20][NN];   // row = att*4 + mi

    if (t < 128) {
        const int n = t;
#pragma unroll
        for (int mi = 0; mi < 4; mi++) {
            const size_t bm = (size_t)b * NN + m0 + mi;
            aw[0 * 4 + mi][n] = sc [bm * NN + n];
            aw[1 * 4 + mi][n] = sb [bm * NN + n];
            aw[2 * 4 + mi][n] = smn[bm * NN + n];
            aw[3 * 4 + mi][n] = sd1[(bm * 2 + 0) * NN + n] + sd1[(bm * 2 + 1) * NN + n];
            aw[4 * 4 + mi][n] = sd2[(bm * 2 + 0) * NN + n] + sd2[(bm * 2 + 1) * NN + n];
        }
    }
    __syncthreads();

    for (int row = w; row < 20; row += 8) {
        float v0 = aw[row][lane], v1 = aw[row][lane + 32];
        float v2 = aw[row][lane + 64], v3 = aw[row][lane + 96];
        float mx = fmaxf(fmaxf(v0, v1), fmaxf(v2, v3));
#pragma unroll
        for (int o = 16; o; o >>= 1) mx = fmaxf(mx, __shfl_xor_sync(0xffffffffu, mx, o));
        float e0 = __expf(v0 - mx), e1 = __expf(v1 - mx);
        float e2 = __expf(v2 - mx), e3 = __expf(v3 - mx);
        float sm = e0 + e1 + e2 + e3;
#pragma unroll
        for (int o = 16; o; o >>= 1) sm += __shfl_xor_sync(0xffffffffu, sm, o);
        float inv = 1.0f / sm;
        aw[row][lane]      = e0 * inv; aw[row][lane + 32] = e1 * inv;
        aw[row][lane + 64] = e2 * inv; aw[row][lane + 96] = e3 * inv;
    }
    __syncthreads();

    const int d = t * 4;
    float4 acc[5][4];
#pragma unroll
    for (int a = 0; a < 5; a++)
#pragma unroll
        for (int mi = 0; mi < 4; mi++) acc[a][mi] = make_float4(0.f, 0.f, 0.f, 0.f);

    const float* x0b = x0 + (size_t)b * NN * DD;
    const float* x1b = x1 + (size_t)b * NN * DD;
    for (int n = 0; n < NN; n++) {
        float4 xv = *(const float4*)(x0b + (size_t)n * DD + d);
        float4 yv = *(const float4*)(x1b + (size_t)n * DD + d);
#pragma unroll
        for (int mi = 0; mi < 4; mi++) {
            float w0 = aw[0 * 4 + mi][n], w1 = aw[1 * 4 + mi][n];
            float w2 = aw[2 * 4 + mi][n], w3 = aw[3 * 4 + mi][n];
            float w4 = aw[4 * 4 + mi][n];
            acc[0][mi].x = fmaf(w0, xv.x, acc[0][mi].x); acc[0][mi].y = fmaf(w0, xv.y, acc[0][mi].y);
            acc[0][mi].z = fmaf(w0, xv.z, acc[0][mi].z); acc[0][mi].w = fmaf(w0, xv.w, acc[0][mi].w);
            acc[1][mi].x = fmaf(w1, xv.x, acc[1][mi].x); acc[1][mi].y = fmaf(w1, xv.y, acc[1][mi].y);
            acc[1][mi].z = fmaf(w1, xv.z, acc[1][mi].z); acc[1][mi].w = fmaf(w1, xv.w, acc[1][mi].w);
            acc[2][mi].x = fmaf(w2, xv.x, acc[2][mi].x); acc[2][mi].y = fmaf(w2, xv.y, acc[2][mi].y);
            acc[2][mi].z = fmaf(w2, xv.z, acc[2][mi].z); acc[2][mi].w = fmaf(w2, xv.w, acc[2][mi].w);
            acc[3][mi].x = fmaf(w3, xv.x, acc[3][mi].x); acc[3][mi].y = fmaf(w3, xv.y, acc[3][mi].y);
            acc[3][mi].z = fmaf(w3, xv.z, acc[3][mi].z); acc[3][mi].w = fmaf(w3, xv.w, acc[3][mi].w);
            acc[4][mi].x = fmaf(w4, yv.x, acc[4][mi].x); acc[4][mi].y = fmaf(w4, yv.y, acc[4][mi].y);
            acc[4][mi].z = fmaf(w4, yv.z, acc[4][mi].z); acc[4][mi].w = fmaf(w4, yv.w, acc[4][mi].w);
        }
    }

#pragma unroll
    for (int mi = 0; mi < 4; mi++) {
        const size_t bm = (size_t)b * NN + m0 + mi;
        float4 xm1 = *(const float4*)(x1b + (size_t)(m0 + mi) * DD + d);
        float4 ag;
        ag.x = fmaxf(xm1.x, fmaxf(fmaxf(acc[3][mi].x, acc[0][mi].x),
                                  fmaxf(fmaxf(acc[4][mi].x, acc[1][mi].x), acc[2][mi].x)));
        ag.y = fmaxf(xm1.y, fmaxf(fmaxf(acc[3][mi].y, acc[0][mi].y),
                                  fmaxf(fmaxf(acc[4][mi].y, acc[1][mi].y), acc[2][mi].y)));
        ag.z = fmaxf(xm1.z, fmaxf(fmaxf(acc[3][mi].z, acc[0][mi].z),
                                  fmaxf(fmaxf(acc[4][mi].z, acc[1][mi].z), acc[2][mi].z)));
        ag.w = fmaxf(xm1.w, fmaxf(fmaxf(acc[3][mi].w, acc[0][mi].w),
                                  fmaxf(fmaxf(acc[4][mi].w, acc[1][mi].w), acc[2][mi].w)));
        float* arow = aggrep + bm * (2 * DD);
        *(float4*)(arow + d)      = xm1;
        *(float4*)(arow + DD + d) = ag;
    }
}

// ---------------------------------------------------------------------------
// Final head
// ---------------------------------------------------------------------------
__global__ __launch_bounds__(256) void final_kernel(
    const float* __restrict__ aggrep, const float* __restrict__ w1v,
    const float* __restrict__ Wpred,  const float* __restrict__ bpred,
    float* __restrict__ out)
{
    const int b = blockIdx.x;
    const int t = threadIdx.x, lane = t & 31, w = t >> 5;
    __shared__ float sp[NN];
    __shared__ float r0[8], r1[8];
    const float* ab = aggrep + (size_t)b * NN * (2 * DD);

    for (int mm = w; mm < NN; mm += 8) {
        const float* ar = ab + (size_t)mm * (2 * DD);
        float acc = 0.0f;
#pragma unroll
        for (int j = lane; j < 2 * DD; j += 32) acc += ar[j] * w1v[j];
#pragma unroll
        for (int o = 16; o; o >>= 1) acc += __shfl_xor_sync(0xffffffffu, acc, o);
        if (lane == 0) sp[mm] = acc;
    }
    __syncthreads();
    if (w == 0) {
        float v0 = sp[lane], v1 = sp[lane + 32], v2 = sp[lane + 64], v3 = sp[lane + 96];
        float mx = fmaxf(fmaxf(v0, v1), fmaxf(v2, v3));
#pragma unroll
        for (int o = 16; o; o >>= 1) mx = fmaxf(mx, __shfl_xor_sync(0xffffffffu, mx, o));
        float e0 = __expf(v0 - mx), e1 = __expf(v1 - mx);
        float e2 = __expf(v2 - mx), e3 = __expf(v3 - mx);
        float sm = e0 + e1 + e2 + e3;
#pragma unroll
        for (int o = 16; o; o >>= 1) sm += __shfl_xor_sync(0xffffffffu, sm, o);
        float inv = 1.0f / sm;
        sp[lane] = e0 * inv; sp[lane + 32] = e1 * inv;
        sp[lane + 64] = e2 * inv; sp[lane + 96] = e3 * inv;
    }
    __syncthreads();

    float rp[8];
#pragma unroll
    for (int k = 0; k < 8; k++) rp[k] = 0.0f;
    for (int mm = 0; mm < NN; mm++) {
        float wgt = sp[mm];
        const float* ar = ab + (size_t)mm * (2 * DD);
#pragma unroll
        for (int k = 0; k < 8; k++) rp[k] = fmaf(wgt, ar[t + k * 256], rp[k]);
    }
    float p0 = 0.0f, p1 = 0.0f;
#pragma unroll
    for (int k = 0; k < 8; k++) {
        int j = t + k * 256;
        p0 = fmaf(rp[k], Wpred[(size_t)j * 2 + 0], p0);
        p1 = fmaf(rp[k], Wpred[(size_t)j * 2 + 1], p1);
    }
#pragma unroll
    for (int o = 16; o; o >>= 1) {
        p0 += __shfl_xor_sync(0xffffffffu, p0, o);
        p1 += __shfl_xor_sync(0xffffffffu, p1, o);
    }
    if (lane == 0) { r0[w] = p0; r1[w] = p1; }
    __syncthreads();
    if (t == 0) {
        float s0 = 0.0f, s1 = 0.0f;
#pragma unroll
        for (int i = 0; i < 8; i++) { s0 += r0[i]; s1 += r1[i]; }
        out[b * 2 + 0] = fmaxf(s0 + bpred[0], 0.0f);
        out[b * 2 + 1] = fmaxf(s1 + bpred[1], 0.0f);
    }
}

// ---------------------------------------------------------------------------
extern "C" void kernel_launch(void* const* d_in, const int* in_sizes, int n_in,
                              void* d_out, int out_size)
{
    (void)in_sizes; (void)n_in; (void)out_size;
    float* S = nullptr;
    cudaGetSymbolAddress((void**)&S, g_scratch);
    __half* HP = nullptr;
    cudaGetSymbolAddress((void**)&HP, g_half);

    const float* x0    = (const float*)d_in[0];
    const float* x1    = (const float*)d_in[1];
    const float* Wc1   = (const float*)d_in[2];
    const float* Wc2   = (const float*)d_in[3];
    const float* vc    = (const float*)d_in[4];
    const float* Wb    = (const float*)d_in[5];
    const float* Wd1   = (const float*)d_in[6];
    const float* vd1   = (const float*)d_in[7];
    const float* Wd2   = (const float*)d_in[8];
    const float* vd2   = (const float*)d_in[9];
    const float* Wm    = (const float*)d_in[10];
    const float* vm    = (const float*)d_in[11];
    const float* Wp1   = (const float*)d_in[14];
    const float* vp    = (const float*)d_in[16];
    const float* Wpred = (const float*)d_in[17];
    const float* bpred = (const float*)d_in[18];
    float* out = (float*)d_out;

    static cudaStream_t s_dot = nullptr;
    static cudaEvent_t ev_prep = nullptr, ev_dot = nullptr;
    static bool attrs_set = false;
    if (!attrs_set) {
        cudaFuncSetAttribute(dot_scores_mma,
                             cudaFuncAttributeMaxDynamicSharedMemorySize, MSMEM);
        cudaFuncSetAttribute(proj_mma,
                             cudaFuncAttributeMaxDynamicSharedMemorySize, PSMEM);
        cudaFuncSetAttribute(bilin_tc,
                             cudaFuncAttributeMaxDynamicSharedMemorySize, PSMEM);
        cudaStreamCreateWithFlags(&s_dot, cudaStreamNonBlocking);
        cudaEventCreateWithFlags(&ev_prep, cudaEventDisableTiming);
        cudaEventCreateWithFlags(&ev_dot, cudaEventDisableTiming);
        attrs_set = true;
    }

    __half* w1t  = HP + HW1;
    __half* w2t  = HP + HW2;
    __half* xh0  = HP + HX0;
    __half* xh1  = HP + HX1;
    __half* wc1t = HP + HC1;
    __half* wc2t = HP + HC2;
    __half* wmt  = HP + HM;
    __half* wbt  = HP + HB;
    __half* xbh  = HP + HXB;

    // Prep (main stream)
    prep_fused<<<dim3(1024, 9), 256>>>(Wd1, Wd2, Wc1, Wc2, Wm, Wb,
                                       x0, x1, Wp1, vp, HP, S + OFF_W1V);
    cudaEventRecord(ev_prep, 0);

    // Fork: dominant dot kernel
    cudaStreamWaitEvent(s_dot, ev_prep, 0);
    dot_scores_mma<<<dim3(2, NN, 2 * BB), 512, MSMEM, s_dot>>>(
        x0, x1, w1t, w2t, vd1, vd2, S + OFF_SD1, S + OFF_SD2);
    cudaEventRecord(ev_dot, s_dot);

    // Main: projections (also emits xb fp16), bilin on TC, merged pair scores
    proj_mma<<<dim3(8, 8, 5), 256, PSMEM>>>(xh0, xh1, wc1t, wc2t, wmt, wbt, S, xbh);
    bilin_tc<<<BB, 256, PSMEM>>>(xh1, xbh, S + OFF_SB);
    pair_scores2<<<dim3(NN, BB, 2), 256>>>(
        S + OFF_XC, S + OFF_YC, vc, S + OFF_SC,
        S + OFF_XM, S + OFF_YM, vm, S + OFF_SMN);

    // Join + fused aggregation (4 m's per CTA) + final head
    cudaStreamWaitEvent(0, ev_dot, 0);
    fuse_att4<<<dim3(NN / 4, BB), 256>>>(S + OFF_SC, S + OFF_SB, S + OFF_SMN,
                                         S + OFF_SD1, S + OFF_SD2, x0, x1, S + OFF_AGG);
    final_kernel<<<BB, 256>>>(S + OFF_AGG, S + OFF_W1V, Wpred, bpred, out);
}

// round 13
// speedup vs baseline: 1.1420x; 1.0236x over previous
#include <cuda_runtime.h>
#include <cuda_fp16.h>
#include <cstdint>
#include <cstddef>

// ---------------------------------------------------------------------------
// Problem constants: B=8, N=M=128, H=512, D=2H=1024
// ---------------------------------------------------------------------------
#define BB   8
#define NN   128
#define HH   512
#define DD   1024

// Scratch layout (floats)
#define SZ_PROJ (BB*NN*HH)
#define SZ_XB   (BB*NN*DD)
#define SZ_S    (BB*NN*NN)
#define SZ_SD   (BB*NN*2*NN)
#define SZ_AGG  (BB*NN*2*DD)

#define OFF_XC  0
#define OFF_YC  (OFF_XC + SZ_PROJ)
#define OFF_XM  (OFF_YC + SZ_PROJ)
#define OFF_YM  (OFF_XM + SZ_PROJ)
#define OFF_XB  (OFF_YM + SZ_PROJ)
#define OFF_SC  (OFF_XB + SZ_XB)
#define OFF_SB  (OFF_SC + SZ_S)
#define OFF_SMN (OFF_SB + SZ_S)
#define OFF_SD1 (OFF_SMN + SZ_S)
#define OFF_SD2 (OFF_SD1 + SZ_SD)
#define OFF_AGG (OFF_SD2 + SZ_SD)
#define OFF_W1V (OFF_AGG + SZ_AGG)
#define SCRATCH_TOTAL (OFF_W1V + 2*DD)

__device__ float g_scratch[SCRATCH_TOTAL];

// fp16 pool
#define HW1 0
#define HW2 (HW1 + HH*DD)
#define HX0 (HW2 + HH*DD)
#define HX1 (HX0 + NN*BB*DD)
#define HC1 (HX1 + NN*BB*DD)
#define HC2 (HC1 + HH*DD)
#define HM  (HC2 + HH*DD)
#define HB  (HM  + HH*DD)
#define HXB (HB  + DD*DD)
#define HALF_TOTAL (HXB + NN*BB*DD)
__device__ __align__(16) __half g_half[HALF_TOTAL];

// tanh via MUFU.TANH
__device__ __forceinline__ float ftanh(float x) {
    float y;
    asm("tanh.approx.f32 %0, %1;" : "=f"(y) : "f"(x));
    return y;
}

__device__ __forceinline__ uint32_t smem_u32(const void* p) {
    uint32_t a;
    asm("{ .reg .u64 t; cvta.to.shared.u64 t, %1; cvt.u32.u64 %0, t; }" : "=r"(a) : "l"(p));
    return a;
}

#define LDSM4(r0, r1, r2, r3, addr) \
    asm volatile("ldmatrix.sync.aligned.m8n8.x4.shared.b16 {%0,%1,%2,%3}, [%4];" \
        : "=r"(r0), "=r"(r1), "=r"(r2), "=r"(r3) : "r"(addr))

#define MMA16816(d, a0, a1, a2, a3, b0, b1) \
    asm volatile("mma.sync.aligned.m16n8k16.row.col.f32.f16.f16.f32 " \
        "{%0,%1,%2,%3}, {%4,%5,%6,%7}, {%8,%9}, {%0,%1,%2,%3};" \
        : "+f"((d)[0]), "+f"((d)[1]), "+f"((d)[2]), "+f"((d)[3]) \
        : "r"(a0), "r"(a1), "r"(a2), "r"(a3), "r"(b0), "r"(b1))

#define CP_ASYNC16(sa, ga) \
    asm volatile("cp.async.cg.shared.global [%0], [%1], 16;" :: "r"(sa), "l"(ga))
#define CP_COMMIT() asm volatile("cp.async.commit_group;")
#define CP_WAIT0()  asm volatile("cp.async.wait_group 0;")

// 128B-row swizzle
__device__ __forceinline__ uint32_t sw128(uint32_t row, uint32_t chunk) {
    return row * 128u + ((chunk * 16u) ^ ((row & 7u) << 4));
}

// ---------------------------------------------------------------------------
// Fused prep
// ---------------------------------------------------------------------------
__global__ void prep_fused(
    const float* __restrict__ Wd1, const float* __restrict__ Wd2,
    const float* __restrict__ Wc1, const float* __restrict__ Wc2,
    const float* __restrict__ Wm,  const float* __restrict__ Wb,
    const float* __restrict__ x0,  const float* __restrict__ x1,
    const float* __restrict__ Wp1, const float* __restrict__ vp,
    __half* __restrict__ HP, float* __restrict__ w1v)
{
    const int task = blockIdx.y;
    const int bx = blockIdx.x;
    const int tid = threadIdx.x;

    if (task < 5) {
        if (bx >= HH) return;
        const float* W; __half* wt;
        switch (task) {
            case 0: W = Wd1; wt = HP + HW1; break;
            case 1: W = Wd2; wt = HP + HW2; break;
            case 2: W = Wc1; wt = HP + HC1; break;
            case 3: W = Wc2; wt = HP + HC2; break;
            default: W = Wm; wt = HP + HM; break;
        }
#pragma unroll
        for (int i = 0; i < 4; i++) {
            int d = tid + i * 256;
            wt[(size_t)bx * DD + d] = __float2half_rn(W[(size_t)d * HH + bx]);
        }
    } else if (task == 5) {
        __half* wt = HP + HB;
#pragma unroll
        for (int i = 0; i < 4; i++) {
            int d = tid + i * 256;
            wt[(size_t)bx * DD + d] = __float2half_rn(Wb[(size_t)d * DD + bx]);
        }
    } else if (task < 8) {
        const float* x = (task == 6) ? x0 : x1;
        __half* xh = HP + ((task == 6) ? HX0 : HX1);
        int i = bx * 1024 + tid * 4;
        float4 v = *(const float4*)(x + i);
        __half2* o = (__half2*)(xh + i);
        o[0] = __floats2half2_rn(v.x, v.y);
        o[1] = __floats2half2_rn(v.z, v.w);
    } else {
        if (bx >= 256) return;
        int j = bx * 8 + (tid >> 5);
        int lane = tid & 31;
        const float* r = Wp1 + (size_t)j * HH;
        float acc = 0.0f;
#pragma unroll
        for (int h = lane; h < HH; h += 32) acc += r[h] * vp[h];
#pragma unroll
        for (int o = 16; o; o >>= 1) acc += __shfl_xor_sync(0xffffffffu, acc, o);
        if (lane == 0) w1v[j] = acc;
    }
}

// ---------------------------------------------------------------------------
// mma.sync fp16 dot-attention scores — R6 best-measured variant (unchanged).
// ---------------------------------------------------------------------------
#define MOFF_Y  0
#define MOFF_V  4096
#define MOFF_S  5120
#define MOFF_A  8192
#define MOFF_B  40960
#define MSMEM   106496

__global__ __launch_bounds__(512, 1) void dot_scores_mma(
    const float* __restrict__ x0, const float* __restrict__ x1,
    const __half* __restrict__ w1t, const __half* __restrict__ w2t,
    const float* __restrict__ vd1, const float* __restrict__ vd2,
    float* __restrict__ sp1, float* __restrict__ sp2)
{
    extern __shared__ char smc[];
    const uint32_t sb = smem_u32(smc);

    const int hc  = blockIdx.x;
    const int m   = blockIdx.y;
    const int att = blockIdx.z & 1;
    const int b   = blockIdx.z >> 1;

    const float* x = att ? x1 : x0;
    const float* y = att ? x0 : x1;
    const __half* wt = att ? w2t : w1t;
    const float* v = att ? vd2 : vd1;
    float* spart = att ? sp2 : sp1;

    const int t = threadIdx.x;
    const int lane = t & 31, wid = t >> 5;
    const int wn = wid & 3, whi = wid >> 2;
    const int lane15 = lane & 15, lhalf = lane >> 4;

    float* ysm = (float*)(smc + MOFF_Y);
    float* vsm = (float*)(smc + MOFF_V);
    float* ssm = (float*)(smc + MOFF_S);

    ((float2*)ysm)[t] = ((const float2*)(y + ((size_t)b * NN + m) * DD))[t];
    if (t < 64) ((float4*)vsm)[t] = ((const float4*)(v + hc * 256))[t];
    if (t < 128) ssm[t] = 0.0f;

    const float* xg = x + (size_t)b * NN * DD;
    const __half* wg = wt + (size_t)(hc * 256) * DD;

    const int an = t >> 2, ac = t & 3;
    const uint32_t a_st0 = sw128(an, ac);
    const uint32_t a_st1 = sw128(an, ac + 4);
    const int br = t >> 1, bc4 = (t & 1) * 4;
    uint32_t b_st[4];
#pragma unroll
    for (int j = 0; j < 4; j++) b_st[j] = sw128(br, bc4 + j);

    float xs[16];

#define ISSUE_B(kt, buf) do { \
        const __half* bp_ = wg + (size_t)br * DD + (kt) * 64 + bc4 * 8; \
        uint32_t Bb_ = sb + MOFF_B + (buf) * 32768u; \
        CP_ASYNC16(Bb_ + b_st[0], bp_); \
        CP_ASYNC16(Bb_ + b_st[1], bp_ + 8); \
        CP_ASYNC16(Bb_ + b_st[2], bp_ + 16); \
        CP_ASYNC16(Bb_ + b_st[3], bp_ + 24); \
        CP_COMMIT(); \
    } while (0)

#define LOAD_X(kt) do { \
        const float* xp_ = xg + (size_t)an * DD + (kt) * 64 + ac * 8; \
        *(float4*)&xs[0]  = *(const float4*)xp_; \
        *(float4*)&xs[4]  = *(const float4*)(xp_ + 4); \
        *(float4*)&xs[8]  = *(const float4*)(xp_ + 32); \
        *(float4*)&xs[12] = *(const float4*)(xp_ + 36); \
    } while (0)

#define STORE_A(kt, buf) do { \
        int kb_ = (kt) * 64 + ac * 8; \
        union { __half h[8]; uint4 q; } u0_, u1_; \
        _Pragma("unroll") \
        for (int j_ = 0; j_ < 8; j_++) { \
            u0_.h[j_] = __float2half_rn(xs[j_]     * ysm[kb_ + j_]); \
            u1_.h[j_] = __float2half_rn(xs[j_ + 8] * ysm[kb_ + 32 + j_]); \
        } \
        char* Ab_ = smc + MOFF_A + (buf) * 16384; \
        *(uint4*)(Ab_ + a_st0) = u0_.q; \
        *(uint4*)(Ab_ + a_st1) = u1_.q; \
    } while (0)

    float acc[2][8][4];
#pragma unroll
    for (int i = 0; i < 2; i++)
#pragma unroll
        for (int j = 0; j < 8; j++)
#pragma unroll
            for (int k = 0; k < 4; k++) acc[i][j][k] = 0.0f;

    ISSUE_B(0, 0);
    LOAD_X(0);
    __syncthreads();
    STORE_A(0, 0);
    CP_WAIT0();
    __syncthreads();

    uint32_t a_row[2], b_row[4];
#pragma unroll
    for (int mi = 0; mi < 2; mi++) a_row[mi] = wn * 32 + mi * 16 + lane15;
#pragma unroll
    for (int nj = 0; nj < 4; nj++) b_row[nj] = whi * 64 + nj * 16 + lane15;

    for (int kt = 0; kt < 16; kt++) {
        const int buf = kt & 1;
        if (kt < 15) { ISSUE_B(kt + 1, buf ^ 1); LOAD_X(kt + 1); }

        const uint32_t Ah = sb + MOFF_A + buf * 16384u;
        const uint32_t Bh = sb + MOFF_B + buf * 32768u;

#pragma unroll
        for (int ks = 0; ks < 4; ks++) {
            const uint32_t cidx = ks * 2 + lhalf;
            uint32_t a[2][4], bb[4][4];
#pragma unroll
            for (int mi = 0; mi < 2; mi++)
                LDSM4(a[mi][0], a[mi][1], a[mi][2], a[mi][3], Ah + sw128(a_row[mi], cidx));
#pragma unroll
            for (int nj = 0; nj < 4; nj++)
                LDSM4(bb[nj][0], bb[nj][1], bb[nj][2], bb[nj][3], Bh + sw128(b_row[nj], cidx));
#pragma unroll
            for (int mi = 0; mi < 2; mi++)
#pragma unroll
                for (int nj = 0; nj < 4; nj++) {
                    MMA16816(acc[mi][nj*2+0], a[mi][0], a[mi][1], a[mi][2], a[mi][3], bb[nj][0], bb[nj][2]);
                    MMA16816(acc[mi][nj*2+1], a[mi][0], a[mi][1], a[mi][2], a[mi][3], bb[nj][1], bb[nj][3]);
                }
        }

        if (kt < 15) { STORE_A(kt + 1, buf ^ 1); CP_WAIT0(); }
        __syncthreads();
    }

    float rs[2][2] = {{0.0f, 0.0f}, {0.0f, 0.0f}};
#pragma unroll
    for (int mi = 0; mi < 2; mi++)
#pragma unroll
        for (int hj = 0; hj < 8; hj++) {
            int hcol = whi * 64 + hj * 8 + (lane & 3) * 2;
            float v0 = vsm[hcol], v1 = vsm[hcol + 1];
            rs[mi][0] += ftanh(acc[mi][hj][0]) * v0 + ftanh(acc[mi][hj][1]) * v1;
            rs[mi][1] += ftanh(acc[mi][hj][2]) * v0 + ftanh(acc[mi][hj][3]) * v1;
        }
#pragma unroll
    for (int o = 1; o <= 2; o <<= 1) {
        rs[0][0] += __shfl_xor_sync(0xffffffffu, rs[0][0], o);
        rs[0][1] += __shfl_xor_sync(0xffffffffu, rs[0][1], o);
        rs[1][0] += __shfl_xor_sync(0xffffffffu, rs[1][0], o);
        rs[1][1] += __shfl_xor_sync(0xffffffffu, rs[1][1], o);
    }
    if ((lane & 3) == 0) {
        int r = wn * 32 + (lane >> 2);
        atomicAdd(&ssm[r],      rs[0][0]);
        atomicAdd(&ssm[r + 8],  rs[0][1]);
        atomicAdd(&ssm[r + 16], rs[1][0]);
        atomicAdd(&ssm[r + 24], rs[1][1]);
    }
    __syncthreads();
    if (t < 128)
        spart[(((size_t)b * NN + m) * 2 + hc) * NN + t] = ssm[t];
#undef ISSUE_B
#undef LOAD_X
#undef STORE_A
}

// ---------------------------------------------------------------------------
// fp16 mma projections; z==4 additionally emits fp16 xb.
// ---------------------------------------------------------------------------
#define POFF_A 0
#define POFF_B 32768
#define PSMEM  65536

__global__ __launch_bounds__(256, 1) void proj_mma(
    const __half* __restrict__ xh0, const __half* __restrict__ xh1,
    const __half* __restrict__ wc1t, const __half* __restrict__ wc2t,
    const __half* __restrict__ wmt,  const __half* __restrict__ wbt,
    float* __restrict__ S, __half* __restrict__ xbh)
{
    const __half* A; const __half* W; float* C; int N;
    switch (blockIdx.z) {
        case 0: A = xh0; W = wc1t; C = S + OFF_XC; N = HH; break;
        case 1: A = xh1; W = wc2t; C = S + OFF_YC; N = HH; break;
        case 2: A = xh0; W = wmt;  C = S + OFF_XM; N = HH; break;
        case 3: A = xh1; W = wmt;  C = S + OFF_YM; N = HH; break;
        default: A = xh0; W = wbt; C = S + OFF_XB; N = DD; break;
    }
    const int bn = blockIdx.x * 128;
    if (bn >= N) return;
    const int bm = blockIdx.y * 128;
    const bool isXB = (blockIdx.z == 4);

    extern __shared__ char smc[];
    const uint32_t sb = smem_u32(smc);
    const int t = threadIdx.x, lane = t & 31, wid = t >> 5;
    const int wm = wid & 3, whn = wid >> 2;
    const int lane15 = lane & 15, lhalf = lane >> 4;

    const int r = t >> 1, cc4 = (t & 1) * 4;
    uint32_t st_off[4];
#pragma unroll
    for (int j = 0; j < 4; j++) st_off[j] = sw128(r, cc4 + j);
    const __half* ag = A + (size_t)(bm + r) * DD + cc4 * 8;
    const __half* wgp = W + (size_t)(bn + r) * DD + cc4 * 8;

#define P_ISSUE(kt, buf) do { \
        uint32_t Ab_ = sb + POFF_A + (buf) * 16384u; \
        uint32_t Bb_ = sb + POFF_B + (buf) * 16384u; \
        const __half* ap_ = ag + (kt) * 64; \
        const __half* bp_ = wgp + (kt) * 64; \
        _Pragma("unroll") \
        for (int j_ = 0; j_ < 4; j_++) { \
            CP_ASYNC16(Ab_ + st_off[j_], ap_ + j_ * 8); \
            CP_ASYNC16(Bb_ + st_off[j_], bp_ + j_ * 8); \
        } \
        CP_COMMIT(); \
    } while (0)

    float acc[2][8][4];
#pragma unroll
    for (int i = 0; i < 2; i++)
#pragma unroll
        for (int j = 0; j < 8; j++)
#pragma unroll
            for (int k = 0; k < 4; k++) acc[i][j][k] = 0.0f;

    P_ISSUE(0, 0);
    CP_WAIT0();
    __syncthreads();

    uint32_t a_row[2], b_row[4];
#pragma unroll
    for (int mi = 0; mi < 2; mi++) a_row[mi] = wm * 32 + mi * 16 + lane15;
#pragma unroll
    for (int nj = 0; nj < 4; nj++) b_row[nj] = whn * 64 + nj * 16 + lane15;

    for (int kt = 0; kt < 16; kt++) {
        const int buf = kt & 1;
        if (kt < 15) P_ISSUE(kt + 1, buf ^ 1);

        const uint32_t Ah = sb + POFF_A + buf * 16384u;
        const uint32_t Bh = sb + POFF_B + buf * 16384u;

#pragma unroll
        for (int ks = 0; ks < 4; ks++) {
            const uint32_t cidx = ks * 2 + lhalf;
            uint32_t a[2][4], bb[4][4];
#pragma unroll
            for (int mi = 0; mi < 2; mi++)
                LDSM4(a[mi][0], a[mi][1], a[mi][2], a[mi][3], Ah + sw128(a_row[mi], cidx));
#pragma unroll
            for (int nj = 0; nj < 4; nj++)
                LDSM4(bb[nj][0], bb[nj][1], bb[nj][2], bb[nj][3], Bh + sw128(b_row[nj], cidx));
#pragma unroll
            for (int mi = 0; mi < 2; mi++)
#pragma unroll
                for (int nj = 0; nj < 4; nj++) {
                    MMA16816(acc[mi][nj*2+0], a[mi][0], a[mi][1], a[mi][2], a[mi][3], bb[nj][0], bb[nj][2]);
                    MMA16816(acc[mi][nj*2+1], a[mi][0], a[mi][1], a[mi][2], a[mi][3], bb[nj][1], bb[nj][3]);
                }
        }

        CP_WAIT0();
        __syncthreads();
    }

#pragma unroll
    for (int mi = 0; mi < 2; mi++) {
        int row = bm + wm * 32 + mi * 16 + (lane >> 2);
#pragma unroll
        for (int nj8 = 0; nj8 < 8; nj8++) {
            int col = bn + whn * 64 + nj8 * 8 + (lane & 3) * 2;
            float c0 = acc[mi][nj8][0], c1 = acc[mi][nj8][1];
            float c2 = acc[mi][nj8][2], c3 = acc[mi][nj8][3];
            C[(size_t)row * N + col]           = c0;
            C[(size_t)row * N + col + 1]       = c1;
            C[(size_t)(row + 8) * N + col]     = c2;
            C[(size_t)(row + 8) * N + col + 1] = c3;
            if (isXB) {
                *(__half2*)&xbh[(size_t)row * DD + col]       = __floats2half2_rn(c0, c1);
                *(__half2*)&xbh[(size_t)(row + 8) * DD + col] = __floats2half2_rn(c2, c3);
            }
        }
    }
#undef P_ISSUE
}

// ---------------------------------------------------------------------------
// Bilinear scores on tensor cores, N-split: grid (2, BB), tile 128m x 64n.
// ---------------------------------------------------------------------------
#define BOFF_A 0
#define BOFF_B 32768
#define BSMEM  49152

__global__ __launch_bounds__(256, 1) void bilin_tc(
    const __half* __restrict__ xh1, const __half* __restrict__ xbh,
    float* __restrict__ sbuf)
{
    const int half_n = blockIdx.x;
    const int b = blockIdx.y;
    const __half* A = xh1 + (size_t)b * NN * DD;
    const __half* Bq = xbh + (size_t)b * NN * DD + (size_t)half_n * 64 * DD;

    extern __shared__ char smc[];
    const uint32_t sb = smem_u32(smc);
    const int t = threadIdx.x, lane = t & 31, wid = t >> 5;
    const int wm = wid & 3, whn = wid >> 2;
    const int lane15 = lane & 15, lhalf = lane >> 4;

    const int ra = t >> 1, ca4 = (t & 1) * 4;
    uint32_t a_off[4];
#pragma unroll
    for (int j = 0; j < 4; j++) a_off[j] = sw128(ra, ca4 + j);
    const __half* ag = A + (size_t)ra * DD + ca4 * 8;
    const int rb = t >> 2, cb2 = (t & 3) * 2;
    const uint32_t b_off0 = sw128(rb, cb2), b_off1 = sw128(rb, cb2 + 1);
    const __half* bg = Bq + (size_t)rb * DD + cb2 * 8;

#define BL_ISSUE(kt, buf) do { \
        uint32_t Ab_ = sb + BOFF_A + (buf) * 16384u; \
        uint32_t Bb_ = sb + BOFF_B + (buf) * 8192u; \
        const __half* ap_ = ag + (kt) * 64; \
        const __half* bp_ = bg + (kt) * 64; \
        _Pragma("unroll") \
        for (int j_ = 0; j_ < 4; j_++) CP_ASYNC16(Ab_ + a_off[j_], ap_ + j_ * 8); \
        CP_ASYNC16(Bb_ + b_off0, bp_); \
        CP_ASYNC16(Bb_ + b_off1, bp_ + 8); \
        CP_COMMIT(); \
    } while (0)

    float acc[2][4][4];
#pragma unroll
    for (int i = 0; i < 2; i++)
#pragma unroll
        for (int j = 0; j < 4; j++)
#pragma unroll
            for (int k = 0; k < 4; k++) acc[i][j][k] = 0.0f;

    BL_ISSUE(0, 0);
    CP_WAIT0();
    __syncthreads();

    uint32_t a_row[2], b_row[2];
#pragma unroll
    for (int mi = 0; mi < 2; mi++) a_row[mi] = wm * 32 + mi * 16 + lane15;
#pragma unroll
    for (int nj = 0; nj < 2; nj++) b_row[nj] = whn * 32 + nj * 16 + lane15;

    for (int kt = 0; kt < 16; kt++) {
        const int buf = kt & 1;
        if (kt < 15) BL_ISSUE(kt + 1, buf ^ 1);

        const uint32_t Ah = sb + BOFF_A + buf * 16384u;
        const uint32_t Bh = sb + BOFF_B + buf * 8192u;

#pragma unroll
        for (int ks = 0; ks < 4; ks++) {
            const uint32_t cidx = ks * 2 + lhalf;
            uint32_t a[2][4], bb[2][4];
#pragma unroll
            for (int mi = 0; mi < 2; mi++)
                LDSM4(a[mi][0], a[mi][1], a[mi][2], a[mi][3], Ah + sw128(a_row[mi], cidx));
#pragma unroll
            for (int nj = 0; nj < 2; nj++)
                LDSM4(bb[nj][0], bb[nj][1], bb[nj][2], bb[nj][3], Bh + sw128(b_row[nj], cidx));
#pragma unroll
            for (int mi = 0; mi < 2; mi++)
#pragma unroll
                for (int nj = 0; nj < 2; nj++) {
                    MMA16816(acc[mi][nj*2+0], a[mi][0], a[mi][1], a[mi][2], a[mi][3], bb[nj][0], bb[nj][2]);
                    MMA16816(acc[mi][nj*2+1], a[mi][0], a[mi][1], a[mi][2], a[mi][3], bb[nj][1], bb[nj][3]);
                }
        }

        CP_WAIT0();
        __syncthreads();
    }

#pragma unroll
    for (int mi = 0; mi < 2; mi++) {
        int row = wm * 32 + mi * 16 + (lane >> 2);
#pragma unroll
        for (int nj8 = 0; nj8 < 4; nj8++) {
            int col = half_n * 64 + whn * 32 + nj8 * 8 + (lane & 3) * 2;
            sbuf[((size_t)b * NN + row) * NN + col]         = acc[mi][nj8][0];
            sbuf[((size_t)b * NN + row) * NN + col + 1]     = acc[mi][nj8][1];
            sbuf[((size_t)b * NN + row + 8) * NN + col]     = acc[mi][nj8][2];
            sbuf[((size_t)b * NN + row + 8) * NN + col + 1] = acc[mi][nj8][3];
        }
    }
#undef BL_ISSUE
}

// ---------------------------------------------------------------------------
// Concat + minus scores with 4-m blocking. grid (32 mblk, 8 b, 2 z).
// FIXED: q staging now copies all 4 rows (2048 floats = 512 float4).
// ---------------------------------------------------------------------------
__global__ __launch_bounds__(256) void pair_scores4(
    const float* __restrict__ pc, const float* __restrict__ qc,
    const float* __restrict__ vcv, float* __restrict__ sc,
    const float* __restrict__ pm, const float* __restrict__ qm,
    const float* __restrict__ vmv, float* __restrict__ smn)
{
    const int m0 = blockIdx.x * 4, b = blockIdx.y, z = blockIdx.z;
    const float* p = z ? pm : pc;
    const float* q = z ? qm : qc;
    const float* v = z ? vmv : vcv;
    float* s = z ? smn : sc;
    const float sign = z ? -1.0f : 1.0f;

    const int t = threadIdx.x, lane = t & 31, w = t >> 5;
    __shared__ float qs[4][HH], vs[HH];
    {   // load 4 q rows (contiguous 2048 floats = 512 float4) + v
        const float4* qb4 = (const float4*)(q + ((size_t)b * NN + m0) * HH);
        ((float4*)qs)[t]       = qb4[t];
        ((float4*)qs)[t + 256] = qb4[t + 256];
        if (t < 128) ((float4*)vs)[t] = ((const float4*)v)[t];
    }
    __syncthreads();

    const float* pb = p + (size_t)b * NN * HH;
    for (int n = w; n < NN; n += 8) {
        const float* pr = pb + (size_t)n * HH;
        float a0 = 0.0f, a1 = 0.0f, a2 = 0.0f, a3 = 0.0f;
#pragma unroll
        for (int h = 0; h < HH; h += 32) {
            int hh = h + lane;
            float pv = pr[hh], vv = vs[hh];
            a0 += vv * ftanh(fmaf(sign, qs[0][hh], pv));
            a1 += vv * ftanh(fmaf(sign, qs[1][hh], pv));
            a2 += vv * ftanh(fmaf(sign, qs[2][hh], pv));
            a3 += vv * ftanh(fmaf(sign, qs[3][hh], pv));
        }
#pragma unroll
        for (int o = 16; o; o >>= 1) {
            a0 += __shfl_xor_sync(0xffffffffu, a0, o);
            a1 += __shfl_xor_sync(0xffffffffu, a1, o);
            a2 += __shfl_xor_sync(0xffffffffu, a2, o);
            a3 += __shfl_xor_sync(0xffffffffu, a3, o);
        }
        if (lane == 0) {
            s[((size_t)b * NN + m0 + 0) * NN + n] = a0;
            s[((size_t)b * NN + m0 + 1) * NN + n] = a1;
            s[((size_t)b * NN + m0 + 2) * NN + n] = a2;
            s[((size_t)b * NN + m0 + 3) * NN + n] = a3;
        }
    }
}

// ---------------------------------------------------------------------------
// Fused: 20 softmaxes + weighted sums + max + agg_rep, 4 m's per CTA.
// ---------------------------------------------------------------------------
__global__ __launch_bounds__(256) void fuse_att4(
    const float* __restrict__ sc,  const float* __restrict__ sb,
    const float* __restrict__ smn, const float* __restrict__ sd1,
    const float* __restrict__ sd2,
    const float* __restrict__ x0,  const float* __restrict__ x1,
    float* __restrict__ aggrep)
{
    const int m0 = blockIdx.x * 4, b = blockIdx.y;
    const int t = threadIdx.x, lane = t & 31, w = t >> 5;
    __shared__ float aw[20][NN];

    if (t < 128) {
        const int n = t;
#pragma unroll
        for (int mi = 0; mi < 4; mi++) {
            const size_t bm = (size_t)b * NN + m0 + mi;
            aw[0 * 4 + mi][n] = sc [bm * NN + n];
            aw[1 * 4 + mi][n] = sb [bm * NN + n];
            aw[2 * 4 + mi][n] = smn[bm * NN + n];
            aw[3 * 4 + mi][n] = sd1[(bm * 2 + 0) * NN + n] + sd1[(bm * 2 + 1) * NN + n];
            aw[4 * 4 + mi][n] = sd2[(bm * 2 + 0) * NN + n] + sd2[(bm * 2 + 1) * NN + n];
        }
    }
    __syncthreads();

    for (int row = w; row < 20; row += 8) {
        float v0 = aw[row][lane], v1 = aw[row][lane + 32];
        float v2 = aw[row][lane + 64], v3 = aw[row][lane + 96];
        float mx = fmaxf(fmaxf(v0, v1), fmaxf(v2, v3));
#pragma unroll
        for (int o = 16; o; o >>= 1) mx = fmaxf(mx, __shfl_xor_sync(0xffffffffu, mx, o));
        float e0 = __expf(v0 - mx), e1 = __expf(v1 - mx);
        float e2 = __expf(v2 - mx), e3 = __expf(v3 - mx);
        float sm = e0 + e1 + e2 + e3;
#pragma unroll
        for (int o = 16; o; o >>= 1) sm += __shfl_xor_sync(0xffffffffu, sm, o);
        float inv = 1.0f / sm;
        aw[row][lane]      = e0 * inv; aw[row][lane + 32] = e1 * inv;
        aw[row][lane + 64] = e2 * inv; aw[row][lane + 96] = e3 * inv;
    }
    __syncthreads();

    const int d = t * 4;
    float4 acc[5][4];
#pragma unroll
    for (int a = 0; a < 5; a++)
#pragma unroll
        for (int mi = 0; mi < 4; mi++) acc[a][mi] = make_float4(0.f, 0.f, 0.f, 0.f);

    const float* x0b = x0 + (size_t)b * NN * DD;
    const float* x1b = x1 + (size_t)b * NN * DD;
    for (int n = 0; n < NN; n++) {
        float4 xv = *(const float4*)(x0b + (size_t)n * DD + d);
        float4 yv = *(const float4*)(x1b + (size_t)n * DD + d);
#pragma unroll
        for (int mi = 0; mi < 4; mi++) {
            float w0 = aw[0 * 4 + mi][n], w1 = aw[1 * 4 + mi][n];
            float w2 = aw[2 * 4 + mi][n], w3 = aw[3 * 4 + mi][n];
            float w4 = aw[4 * 4 + mi][n];
            acc[0][mi].x = fmaf(w0, xv.x, acc[0][mi].x); acc[0][mi].y = fmaf(w0, xv.y, acc[0][mi].y);
            acc[0][mi].z = fmaf(w0, xv.z, acc[0][mi].z); acc[0][mi].w = fmaf(w0, xv.w, acc[0][mi].w);
            acc[1][mi].x = fmaf(w1, xv.x, acc[1][mi].x); acc[1][mi].y = fmaf(w1, xv.y, acc[1][mi].y);
            acc[1][mi].z = fmaf(w1, xv.z, acc[1][mi].z); acc[1][mi].w = fmaf(w1, xv.w, acc[1][mi].w);
            acc[2][mi].x = fmaf(w2, xv.x, acc[2][mi].x); acc[2][mi].y = fmaf(w2, xv.y, acc[2][mi].y);
            acc[2][mi].z = fmaf(w2, xv.z, acc[2][mi].z); acc[2][mi].w = fmaf(w2, xv.w, acc[2][mi].w);
            acc[3][mi].x = fmaf(w3, xv.x, acc[3][mi].x); acc[3][mi].y = fmaf(w3, xv.y, acc[3][mi].y);
            acc[3][mi].z = fmaf(w3, xv.z, acc[3][mi].z); acc[3][mi].w = fmaf(w3, xv.w, acc[3][mi].w);
            acc[4][mi].x = fmaf(w4, yv.x, acc[4][mi].x); acc[4][mi].y = fmaf(w4, yv.y, acc[4][mi].y);
            acc[4][mi].z = fmaf(w4, yv.z, acc[4][mi].z); acc[4][mi].w = fmaf(w4, yv.w, acc[4][mi].w);
        }
    }

#pragma unroll
    for (int mi = 0; mi < 4; mi++) {
        const size_t bm = (size_t)b * NN + m0 + mi;
        float4 xm1 = *(const float4*)(x1b + (size_t)(m0 + mi) * DD + d);
        float4 ag;
        ag.x = fmaxf(xm1.x, fmaxf(fmaxf(acc[3][mi].x, acc[0][mi].x),
                                  fmaxf(fmaxf(acc[4][mi].x, acc[1][mi].x), acc[2][mi].x)));
        ag.y = fmaxf(xm1.y, fmaxf(fmaxf(acc[3][mi].y, acc[0][mi].y),
                                  fmaxf(fmaxf(acc[4][mi].y, acc[1][mi].y), acc[2][mi].y)));
        ag.z = fmaxf(xm1.z, fmaxf(fmaxf(acc[3][mi].z, acc[0][mi].z),
                                  fmaxf(fmaxf(acc[4][mi].z, acc[1][mi].z), acc[2][mi].z)));
        ag.w = fmaxf(xm1.w, fmaxf(fmaxf(acc[3][mi].w, acc[0][mi].w),
                                  fmaxf(fmaxf(acc[4][mi].w, acc[1][mi].w), acc[2][mi].w)));
        float* arow = aggrep + bm * (2 * DD);
        *(float4*)(arow + d)      = xm1;
        *(float4*)(arow + DD + d) = ag;
    }
}

// ---------------------------------------------------------------------------
// Final head
// ---------------------------------------------------------------------------
__global__ __launch_bounds__(256) void final_kernel(
    const float* __restrict__ aggrep, const float* __restrict__ w1v,
    const float* __restrict__ Wpred,  const float* __restrict__ bpred,
    float* __restrict__ out)
{
    const int b = blockIdx.x;
    const int t = threadIdx.x, lane = t & 31, w = t >> 5;
    __shared__ float sp[NN];
    __shared__ float r0[8], r1[8];
    const float* ab = aggrep + (size_t)b * NN * (2 * DD);

    for (int mm = w; mm < NN; mm += 8) {
        const float* ar = ab + (size_t)mm * (2 * DD);
        float acc = 0.0f;
#pragma unroll
        for (int j = lane; j < 2 * DD; j += 32) acc += ar[j] * w1v[j];
#pragma unroll
        for (int o = 16; o; o >>= 1) acc += __shfl_xor_sync(0xffffffffu, acc, o);
        if (lane == 0) sp[mm] = acc;
    }
    __syncthreads();
    if (w == 0) {
        float v0 = sp[lane], v1 = sp[lane + 32], v2 = sp[lane + 64], v3 = sp[lane + 96];
        float mx = fmaxf(fmaxf(v0, v1), fmaxf(v2, v3));
#pragma unroll
        for (int o = 16; o; o >>= 1) mx = fmaxf(mx, __shfl_xor_sync(0xffffffffu, mx, o));
        float e0 = __expf(v0 - mx), e1 = __expf(v1 - mx);
        float e2 = __expf(v2 - mx), e3 = __expf(v3 - mx);
        float sm = e0 + e1 + e2 + e3;
#pragma unroll
        for (int o = 16; o; o >>= 1) sm += __shfl_xor_sync(0xffffffffu, sm, o);
        float inv = 1.0f / sm;
        sp[lane] = e0 * inv; sp[lane + 32] = e1 * inv;
        sp[lane + 64] = e2 * inv; sp[lane + 96] = e3 * inv;
    }
    __syncthreads();

    float rp[8];
#pragma unroll
    for (int k = 0; k < 8; k++) rp[k] = 0.0f;
    for (int mm = 0; mm < NN; mm++) {
        float wgt = sp[mm];
        const float* ar = ab + (size_t)mm * (2 * DD);
#pragma unroll
        for (int k = 0; k < 8; k++) rp[k] = fmaf(wgt, ar[t + k * 256], rp[k]);
    }
    float p0 = 0.0f, p1 = 0.0f;
#pragma unroll
    for (int k = 0; k < 8; k++) {
        int j = t + k * 256;
        p0 = fmaf(rp[k], Wpred[(size_t)j * 2 + 0], p0);
        p1 = fmaf(rp[k], Wpred[(size_t)j * 2 + 1], p1);
    }
#pragma unroll
    for (int o = 16; o; o >>= 1) {
        p0 += __shfl_xor_sync(0xffffffffu, p0, o);
        p1 += __shfl_xor_sync(0xffffffffu, p1, o);
    }
    if (lane == 0) { r0[w] = p0; r1[w] = p1; }
    __syncthreads();
    if (t == 0) {
        float s0 = 0.0f, s1 = 0.0f;
#pragma unroll
        for (int i = 0; i < 8; i++) { s0 += r0[i]; s1 += r1[i]; }
        out[b * 2 + 0] = fmaxf(s0 + bpred[0], 0.0f);
        out[b * 2 + 1] = fmaxf(s1 + bpred[1], 0.0f);
    }
}

// ---------------------------------------------------------------------------
extern "C" void kernel_launch(void* const* d_in, const int* in_sizes, int n_in,
                              void* d_out, int out_size)
{
    (void)in_sizes; (void)n_in; (void)out_size;
    float* S = nullptr;
    cudaGetSymbolAddress((void**)&S, g_scratch);
    __half* HP = nullptr;
    cudaGetSymbolAddress((void**)&HP, g_half);

    const float* x0    = (const float*)d_in[0];
    const float* x1    = (const float*)d_in[1];
    const float* Wc1   = (const float*)d_in[2];
    const float* Wc2   = (const float*)d_in[3];
    const float* vc    = (const float*)d_in[4];
    const float* Wb    = (const float*)d_in[5];
    const float* Wd1   = (const float*)d_in[6];
    const float* vd1   = (const float*)d_in[7];
    const float* Wd2   = (const float*)d_in[8];
    const float* vd2   = (const float*)d_in[9];
    const float* Wm    = (const float*)d_in[10];
    const float* vm    = (const float*)d_in[11];
    const float* Wp1   = (const float*)d_in[14];
    const float* vp    = (const float*)d_in[16];
    const float* Wpred = (const float*)d_in[17];
    const float* bpred = (const float*)d_in[18];
    float* out = (float*)d_out;

    static cudaStream_t s_dot = nullptr;
    static cudaEvent_t ev_prep = nullptr, ev_dot = nullptr;
    static bool attrs_set = false;
    if (!attrs_set) {
        cudaFuncSetAttribute(dot_scores_mma,
                             cudaFuncAttributeMaxDynamicSharedMemorySize, MSMEM);
        cudaFuncSetAttribute(proj_mma,
                             cudaFuncAttributeMaxDynamicSharedMemorySize, PSMEM);
        cudaFuncSetAttribute(bilin_tc,
                             cudaFuncAttributeMaxDynamicSharedMemorySize, BSMEM);
        cudaStreamCreateWithFlags(&s_dot, cudaStreamNonBlocking);
        cudaEventCreateWithFlags(&ev_prep, cudaEventDisableTiming);
        cudaEventCreateWithFlags(&ev_dot, cudaEventDisableTiming);
        attrs_set = true;
    }

    __half* w1t  = HP + HW1;
    __half* w2t  = HP + HW2;
    __half* xh0  = HP + HX0;
    __half* xh1  = HP + HX1;
    __half* wc1t = HP + HC1;
    __half* wc2t = HP + HC2;
    __half* wmt  = HP + HM;
    __half* wbt  = HP + HB;
    __half* xbh  = HP + HXB;

    // Prep (main stream)
    prep_fused<<<dim3(1024, 9), 256>>>(Wd1, Wd2, Wc1, Wc2, Wm, Wb,
                                       x0, x1, Wp1, vp, HP, S + OFF_W1V);
    cudaEventRecord(ev_prep, 0);

    // Fork: dominant dot kernel
    cudaStreamWaitEvent(s_dot, ev_prep, 0);
    dot_scores_mma<<<dim3(2, NN, 2 * BB), 512, MSMEM, s_dot>>>(
        x0, x1, w1t, w2t, vd1, vd2, S + OFF_SD1, S + OFF_SD2);
    cudaEventRecord(ev_dot, s_dot);

    // Main: projections, bilin on TC (16 CTAs), pair scores (4-m blocked)
    proj_mma<<<dim3(8, 8, 5), 256, PSMEM>>>(xh0, xh1, wc1t, wc2t, wmt, wbt, S, xbh);
    bilin_tc<<<dim3(2, BB), 256, BSMEM>>>(xh1, xbh, S + OFF_SB);
    pair_scores4<<<dim3(NN / 4, BB, 2), 256>>>(
        S + OFF_XC, S + OFF_YC, vc, S + OFF_SC,
        S + OFF_XM, S + OFF_YM, vm, S + OFF_SMN);

    // Join + fused aggregation + final head
    cudaStreamWaitEvent(0, ev_dot, 0);
    fuse_att4<<<dim3(NN / 4, BB), 256>>>(S + OFF_SC, S + OFF_SB, S + OFF_SMN,
                                         S + OFF_SD1, S + OFF_SD2, x0, x1, S + OFF_AGG);
    final_kernel<<<BB, 256>>>(S + OFF_AGG, S + OFF_W1V, Wpred, bpred, out);
}

// round 14
// speedup vs baseline: 1.1572x; 1.0133x over previous
#include <cuda_runtime.h>
#include <cuda_fp16.h>
#include <cstdint>
#include <cstddef>

// ---------------------------------------------------------------------------
// Problem constants: B=8, N=M=128, H=512, D=2H=1024
// ---------------------------------------------------------------------------
#define BB   8
#define NN   128
#define HH   512
#define DD   1024

// Float scratch (scores + agg + w1v)
#define SZ_S    (BB*NN*NN)
#define SZ_SD   (BB*NN*2*NN)
#define SZ_AGG  (BB*NN*2*DD)
#define OFF_SC  0
#define OFF_SB  (OFF_SC + SZ_S)
#define OFF_SMN (OFF_SB + SZ_S)
#define OFF_SD1 (OFF_SMN + SZ_S)
#define OFF_SD2 (OFF_SD1 + SZ_SD)
#define OFF_AGG (OFF_SD2 + SZ_SD)
#define OFF_W1V (OFF_AGG + SZ_AGG)
#define SCRATCH_TOTAL (OFF_W1V + 2*DD)

__device__ float g_scratch[SCRATCH_TOTAL];

// fp16 pool
#define HW1 0
#define HW2 (HW1 + HH*DD)
#define HX0 (HW2 + HH*DD)
#define HX1 (HX0 + NN*BB*DD)
#define HC1 (HX1 + NN*BB*DD)
#define HC2 (HC1 + HH*DD)
#define HM  (HC2 + HH*DD)
#define HB  (HM  + HH*DD)
#define HXB (HB  + DD*DD)
#define HXC (HXB + NN*BB*DD)
#define HYC (HXC + NN*BB*HH)
#define HXM (HYC + NN*BB*HH)
#define HYM (HXM + NN*BB*HH)
#define HALF_TOTAL (HYM + NN*BB*HH)
__device__ __align__(16) __half g_half[HALF_TOTAL];

// tanh via MUFU.TANH
__device__ __forceinline__ float ftanh(float x) {
    float y;
    asm("tanh.approx.f32 %0, %1;" : "=f"(y) : "f"(x));
    return y;
}

__device__ __forceinline__ uint32_t smem_u32(const void* p) {
    uint32_t a;
    asm("{ .reg .u64 t; cvta.to.shared.u64 t, %1; cvt.u32.u64 %0, t; }" : "=r"(a) : "l"(p));
    return a;
}

#define LDSM4(r0, r1, r2, r3, addr) \
    asm volatile("ldmatrix.sync.aligned.m8n8.x4.shared.b16 {%0,%1,%2,%3}, [%4];" \
        : "=r"(r0), "=r"(r1), "=r"(r2), "=r"(r3) : "r"(addr))

#define MMA16816(d, a0, a1, a2, a3, b0, b1) \
    asm volatile("mma.sync.aligned.m16n8k16.row.col.f32.f16.f16.f32 " \
        "{%0,%1,%2,%3}, {%4,%5,%6,%7}, {%8,%9}, {%0,%1,%2,%3};" \
        : "+f"((d)[0]), "+f"((d)[1]), "+f"((d)[2]), "+f"((d)[3]) \
        : "r"(a0), "r"(a1), "r"(a2), "r"(a3), "r"(b0), "r"(b1))

#define CP_ASYNC16(sa, ga) \
    asm volatile("cp.async.cg.shared.global [%0], [%1], 16;" :: "r"(sa), "l"(ga))
#define CP_COMMIT() asm volatile("cp.async.commit_group;")
#define CP_WAIT0()  asm volatile("cp.async.wait_group 0;")

// 128B-row swizzle
__device__ __forceinline__ uint32_t sw128(uint32_t row, uint32_t chunk) {
    return row * 128u + ((chunk * 16u) ^ ((row & 7u) << 4));
}

// ---------------------------------------------------------------------------
// Coalesced weight transpose+convert: wt[h*DD+d] = (half)W[d*N+h].
// 64x64 tiles via smem. grid (16, 16, 6), 256 threads.
// ---------------------------------------------------------------------------
__global__ void wtrans(
    const float* __restrict__ Wd1, const float* __restrict__ Wd2,
    const float* __restrict__ Wc1, const float* __restrict__ Wc2,
    const float* __restrict__ Wm,  const float* __restrict__ Wb,
    __half* __restrict__ HP)
{
    const int z = blockIdx.z;
    const float* W; __half* wt; int N;
    switch (z) {
        case 0: W = Wd1; wt = HP + HW1; N = HH; break;
        case 1: W = Wd2; wt = HP + HW2; N = HH; break;
        case 2: W = Wc1; wt = HP + HC1; N = HH; break;
        case 3: W = Wc2; wt = HP + HC2; N = HH; break;
        case 4: W = Wm;  wt = HP + HM;  N = HH; break;
        default: W = Wb; wt = HP + HB;  N = DD; break;
    }
    const int h0 = blockIdx.x * 64;
    if (h0 >= N) return;
    const int d0 = blockIdx.y * 64;
    const int t = threadIdx.x;

    __shared__ __half tile[64][66];
#pragma unroll
    for (int i = 0; i < 16; i++) {
        int idx = i * 256 + t;
        int dr = idx >> 6, hc = idx & 63;
        tile[hc][dr] = __float2half_rn(W[(size_t)(d0 + dr) * N + h0 + hc]);
    }
    __syncthreads();
#pragma unroll
    for (int i = 0; i < 16; i++) {
        int idx = i * 256 + t;
        int hr = idx >> 6, dc = idx & 63;
        wt[(size_t)(h0 + hr) * DD + d0 + dc] = tile[hr][dc];
    }
}

// ---------------------------------------------------------------------------
// Remaining prep: x converts + w1v. grid (1024, 3), 256 threads.
// ---------------------------------------------------------------------------
__global__ void prep_rest(
    const float* __restrict__ x0, const float* __restrict__ x1,
    const float* __restrict__ Wp1, const float* __restrict__ vp,
    __half* __restrict__ HP, float* __restrict__ w1v)
{
    const int task = blockIdx.y;
    const int bx = blockIdx.x;
    const int tid = threadIdx.x;

    if (task < 2) {
        const float* x = (task == 0) ? x0 : x1;
        __half* xh = HP + ((task == 0) ? HX0 : HX1);
        int i = bx * 1024 + tid * 4;
        float4 v = *(const float4*)(x + i);
        __half2* o = (__half2*)(xh + i);
        o[0] = __floats2half2_rn(v.x, v.y);
        o[1] = __floats2half2_rn(v.z, v.w);
    } else {
        if (bx >= 256) return;
        int j = bx * 8 + (tid >> 5);
        int lane = tid & 31;
        const float* r = Wp1 + (size_t)j * HH;
        float acc = 0.0f;
#pragma unroll
        for (int h = lane; h < HH; h += 32) acc += r[h] * vp[h];
#pragma unroll
        for (int o = 16; o; o >>= 1) acc += __shfl_xor_sync(0xffffffffu, acc, o);
        if (lane == 0) w1v[j] = acc;
    }
}

// ---------------------------------------------------------------------------
// mma.sync fp16 dot-attention scores — R6 best-measured variant (unchanged).
// ---------------------------------------------------------------------------
#define MOFF_Y  0
#define MOFF_V  4096
#define MOFF_S  5120
#define MOFF_A  8192
#define MOFF_B  40960
#define MSMEM   106496

__global__ __launch_bounds__(512, 1) void dot_scores_mma(
    const float* __restrict__ x0, const float* __restrict__ x1,
    const __half* __restrict__ w1t, const __half* __restrict__ w2t,
    const float* __restrict__ vd1, const float* __restrict__ vd2,
    float* __restrict__ sp1, float* __restrict__ sp2)
{
    extern __shared__ char smc[];
    const uint32_t sb = smem_u32(smc);

    const int hc  = blockIdx.x;
    const int m   = blockIdx.y;
    const int att = blockIdx.z & 1;
    const int b   = blockIdx.z >> 1;

    const float* x = att ? x1 : x0;
    const float* y = att ? x0 : x1;
    const __half* wt = att ? w2t : w1t;
    const float* v = att ? vd2 : vd1;
    float* spart = att ? sp2 : sp1;

    const int t = threadIdx.x;
    const int lane = t & 31, wid = t >> 5;
    const int wn = wid & 3, whi = wid >> 2;
    const int lane15 = lane & 15, lhalf = lane >> 4;

    float* ysm = (float*)(smc + MOFF_Y);
    float* vsm = (float*)(smc + MOFF_V);
    float* ssm = (float*)(smc + MOFF_S);

    ((float2*)ysm)[t] = ((const float2*)(y + ((size_t)b * NN + m) * DD))[t];
    if (t < 64) ((float4*)vsm)[t] = ((const float4*)(v + hc * 256))[t];
    if (t < 128) ssm[t] = 0.0f;

    const float* xg = x + (size_t)b * NN * DD;
    const __half* wg = wt + (size_t)(hc * 256) * DD;

    const int an = t >> 2, ac = t & 3;
    const uint32_t a_st0 = sw128(an, ac);
    const uint32_t a_st1 = sw128(an, ac + 4);
    const int br = t >> 1, bc4 = (t & 1) * 4;
    uint32_t b_st[4];
#pragma unroll
    for (int j = 0; j < 4; j++) b_st[j] = sw128(br, bc4 + j);

    float xs[16];

#define ISSUE_B(kt, buf) do { \
        const __half* bp_ = wg + (size_t)br * DD + (kt) * 64 + bc4 * 8; \
        uint32_t Bb_ = sb + MOFF_B + (buf) * 32768u; \
        CP_ASYNC16(Bb_ + b_st[0], bp_); \
        CP_ASYNC16(Bb_ + b_st[1], bp_ + 8); \
        CP_ASYNC16(Bb_ + b_st[2], bp_ + 16); \
        CP_ASYNC16(Bb_ + b_st[3], bp_ + 24); \
        CP_COMMIT(); \
    } while (0)

#define LOAD_X(kt) do { \
        const float* xp_ = xg + (size_t)an * DD + (kt) * 64 + ac * 8; \
        *(float4*)&xs[0]  = *(const float4*)xp_; \
        *(float4*)&xs[4]  = *(const float4*)(xp_ + 4); \
        *(float4*)&xs[8]  = *(const float4*)(xp_ + 32); \
        *(float4*)&xs[12] = *(const float4*)(xp_ + 36); \
    } while (0)

#define STORE_A(kt, buf) do { \
        int kb_ = (kt) * 64 + ac * 8; \
        union { __half h[8]; uint4 q; } u0_, u1_; \
        _Pragma("unroll") \
        for (int j_ = 0; j_ < 8; j_++) { \
            u0_.h[j_] = __float2half_rn(xs[j_]     * ysm[kb_ + j_]); \
            u1_.h[j_] = __float2half_rn(xs[j_ + 8] * ysm[kb_ + 32 + j_]); \
        } \
        char* Ab_ = smc + MOFF_A + (buf) * 16384; \
        *(uint4*)(Ab_ + a_st0) = u0_.q; \
        *(uint4*)(Ab_ + a_st1) = u1_.q; \
    } while (0)

    float acc[2][8][4];
#pragma unroll
    for (int i = 0; i < 2; i++)
#pragma unroll
        for (int j = 0; j < 8; j++)
#pragma unroll
            for (int k = 0; k < 4; k++) acc[i][j][k] = 0.0f;

    ISSUE_B(0, 0);
    LOAD_X(0);
    __syncthreads();
    STORE_A(0, 0);
    CP_WAIT0();
    __syncthreads();

    uint32_t a_row[2], b_row[4];
#pragma unroll
    for (int mi = 0; mi < 2; mi++) a_row[mi] = wn * 32 + mi * 16 + lane15;
#pragma unroll
    for (int nj = 0; nj < 4; nj++) b_row[nj] = whi * 64 + nj * 16 + lane15;

    for (int kt = 0; kt < 16; kt++) {
        const int buf = kt & 1;
        if (kt < 15) { ISSUE_B(kt + 1, buf ^ 1); LOAD_X(kt + 1); }

        const uint32_t Ah = sb + MOFF_A + buf * 16384u;
        const uint32_t Bh = sb + MOFF_B + buf * 32768u;

#pragma unroll
        for (int ks = 0; ks < 4; ks++) {
            const uint32_t cidx = ks * 2 + lhalf;
            uint32_t a[2][4], bb[4][4];
#pragma unroll
            for (int mi = 0; mi < 2; mi++)
                LDSM4(a[mi][0], a[mi][1], a[mi][2], a[mi][3], Ah + sw128(a_row[mi], cidx));
#pragma unroll
            for (int nj = 0; nj < 4; nj++)
                LDSM4(bb[nj][0], bb[nj][1], bb[nj][2], bb[nj][3], Bh + sw128(b_row[nj], cidx));
#pragma unroll
            for (int mi = 0; mi < 2; mi++)
#pragma unroll
                for (int nj = 0; nj < 4; nj++) {
                    MMA16816(acc[mi][nj*2+0], a[mi][0], a[mi][1], a[mi][2], a[mi][3], bb[nj][0], bb[nj][2]);
                    MMA16816(acc[mi][nj*2+1], a[mi][0], a[mi][1], a[mi][2], a[mi][3], bb[nj][1], bb[nj][3]);
                }
        }

        if (kt < 15) { STORE_A(kt + 1, buf ^ 1); CP_WAIT0(); }
        __syncthreads();
    }

    float rs[2][2] = {{0.0f, 0.0f}, {0.0f, 0.0f}};
#pragma unroll
    for (int mi = 0; mi < 2; mi++)
#pragma unroll
        for (int hj = 0; hj < 8; hj++) {
            int hcol = whi * 64 + hj * 8 + (lane & 3) * 2;
            float v0 = vsm[hcol], v1 = vsm[hcol + 1];
            rs[mi][0] += ftanh(acc[mi][hj][0]) * v0 + ftanh(acc[mi][hj][1]) * v1;
            rs[mi][1] += ftanh(acc[mi][hj][2]) * v0 + ftanh(acc[mi][hj][3]) * v1;
        }
#pragma unroll
    for (int o = 1; o <= 2; o <<= 1) {
        rs[0][0] += __shfl_xor_sync(0xffffffffu, rs[0][0], o);
        rs[0][1] += __shfl_xor_sync(0xffffffffu, rs[0][1], o);
        rs[1][0] += __shfl_xor_sync(0xffffffffu, rs[1][0], o);
        rs[1][1] += __shfl_xor_sync(0xffffffffu, rs[1][1], o);
    }
    if ((lane & 3) == 0) {
        int r = wn * 32 + (lane >> 2);
        atomicAdd(&ssm[r],      rs[0][0]);
        atomicAdd(&ssm[r + 8],  rs[0][1]);
        atomicAdd(&ssm[r + 16], rs[1][0]);
        atomicAdd(&ssm[r + 24], rs[1][1]);
    }
    __syncthreads();
    if (t < 128)
        spart[(((size_t)b * NN + m) * 2 + hc) * NN + t] = ssm[t];
#undef ISSUE_B
#undef LOAD_X
#undef STORE_A
}

// ---------------------------------------------------------------------------
// fp16 mma projections: z<4 write fp16 outputs (pair is the only consumer);
// z==4 writes only fp16 xb (bilin is the only consumer).
// ---------------------------------------------------------------------------
#define POFF_A 0
#define POFF_B 32768
#define PSMEM  65536

__global__ __launch_bounds__(256, 1) void proj_mma(
    const __half* __restrict__ xh0, const __half* __restrict__ xh1,
    __half* __restrict__ HP)
{
    const __half* A; const __half* W; __half* Ch; int N;
    switch (blockIdx.z) {
        case 0: A = xh0; W = HP + HC1; Ch = HP + HXC; N = HH; break;
        case 1: A = xh1; W = HP + HC2; Ch = HP + HYC; N = HH; break;
        case 2: A = xh0; W = HP + HM;  Ch = HP + HXM; N = HH; break;
        case 3: A = xh1; W = HP + HM;  Ch = HP + HYM; N = HH; break;
        default: A = xh0; W = HP + HB; Ch = HP + HXB; N = DD; break;
    }
    const int bn = blockIdx.x * 128;
    if (bn >= N) return;
    const int bm = blockIdx.y * 128;

    extern __shared__ char smc[];
    const uint32_t sb = smem_u32(smc);
    const int t = threadIdx.x, lane = t & 31, wid = t >> 5;
    const int wm = wid & 3, whn = wid >> 2;
    const int lane15 = lane & 15, lhalf = lane >> 4;

    const int r = t >> 1, cc4 = (t & 1) * 4;
    uint32_t st_off[4];
#pragma unroll
    for (int j = 0; j < 4; j++) st_off[j] = sw128(r, cc4 + j);
    const __half* ag = A + (size_t)(bm + r) * DD + cc4 * 8;
    const __half* wgp = W + (size_t)(bn + r) * DD + cc4 * 8;

#define P_ISSUE(kt, buf) do { \
        uint32_t Ab_ = sb + POFF_A + (buf) * 16384u; \
        uint32_t Bb_ = sb + POFF_B + (buf) * 16384u; \
        const __half* ap_ = ag + (kt) * 64; \
        const __half* bp_ = wgp + (kt) * 64; \
        _Pragma("unroll") \
        for (int j_ = 0; j_ < 4; j_++) { \
            CP_ASYNC16(Ab_ + st_off[j_], ap_ + j_ * 8); \
            CP_ASYNC16(Bb_ + st_off[j_], bp_ + j_ * 8); \
        } \
        CP_COMMIT(); \
    } while (0)

    float acc[2][8][4];
#pragma unroll
    for (int i = 0; i < 2; i++)
#pragma unroll
        for (int j = 0; j < 8; j++)
#pragma unroll
            for (int k = 0; k < 4; k++) acc[i][j][k] = 0.0f;

    P_ISSUE(0, 0);
    CP_WAIT0();
    __syncthreads();

    uint32_t a_row[2], b_row[4];
#pragma unroll
    for (int mi = 0; mi < 2; mi++) a_row[mi] = wm * 32 + mi * 16 + lane15;
#pragma unroll
    for (int nj = 0; nj < 4; nj++) b_row[nj] = whn * 64 + nj * 16 + lane15;

    for (int kt = 0; kt < 16; kt++) {
        const int buf = kt & 1;
        if (kt < 15) P_ISSUE(kt + 1, buf ^ 1);

        const uint32_t Ah = sb + POFF_A + buf * 16384u;
        const uint32_t Bh = sb + POFF_B + buf * 16384u;

#pragma unroll
        for (int ks = 0; ks < 4; ks++) {
            const uint32_t cidx = ks * 2 + lhalf;
            uint32_t a[2][4], bb[4][4];
#pragma unroll
            for (int mi = 0; mi < 2; mi++)
                LDSM4(a[mi][0], a[mi][1], a[mi][2], a[mi][3], Ah + sw128(a_row[mi], cidx));
#pragma unroll
            for (int nj = 0; nj < 4; nj++)
                LDSM4(bb[nj][0], bb[nj][1], bb[nj][2], bb[nj][3], Bh + sw128(b_row[nj], cidx));
#pragma unroll
            for (int mi = 0; mi < 2; mi++)
#pragma unroll
                for (int nj = 0; nj < 4; nj++) {
                    MMA16816(acc[mi][nj*2+0], a[mi][0], a[mi][1], a[mi][2], a[mi][3], bb[nj][0], bb[nj][2]);
                    MMA16816(acc[mi][nj*2+1], a[mi][0], a[mi][1], a[mi][2], a[mi][3], bb[nj][1], bb[nj][3]);
                }
        }

        CP_WAIT0();
        __syncthreads();
    }

#pragma unroll
    for (int mi = 0; mi < 2; mi++) {
        int row = bm + wm * 32 + mi * 16 + (lane >> 2);
#pragma unroll
        for (int nj8 = 0; nj8 < 8; nj8++) {
            int col = bn + whn * 64 + nj8 * 8 + (lane & 3) * 2;
            *(__half2*)&Ch[(size_t)row * N + col] =
                __floats2half2_rn(acc[mi][nj8][0], acc[mi][nj8][1]);
            *(__half2*)&Ch[(size_t)(row + 8) * N + col] =
                __floats2half2_rn(acc[mi][nj8][2], acc[mi][nj8][3]);
        }
    }
#undef P_ISSUE
}

// ---------------------------------------------------------------------------
// Bilinear scores on tensor cores (unchanged): grid (2, BB), tile 128m x 64n.
// ---------------------------------------------------------------------------
#define BOFF_A 0
#define BOFF_B 32768
#define BSMEM  49152

__global__ __launch_bounds__(256, 1) void bilin_tc(
    const __half* __restrict__ xh1, const __half* __restrict__ xbh,
    float* __restrict__ sbuf)
{
    const int half_n = blockIdx.x;
    const int b = blockIdx.y;
    const __half* A = xh1 + (size_t)b * NN * DD;
    const __half* Bq = xbh + (size_t)b * NN * DD + (size_t)half_n * 64 * DD;

    extern __shared__ char smc[];
    const uint32_t sb = smem_u32(smc);
    const int t = threadIdx.x, lane = t & 31, wid = t >> 5;
    const int wm = wid & 3, whn = wid >> 2;
    const int lane15 = lane & 15, lhalf = lane >> 4;

    const int ra = t >> 1, ca4 = (t & 1) * 4;
    uint32_t a_off[4];
#pragma unroll
    for (int j = 0; j < 4; j++) a_off[j] = sw128(ra, ca4 + j);
    const __half* ag = A + (size_t)ra * DD + ca4 * 8;
    const int rb = t >> 2, cb2 = (t & 3) * 2;
    const uint32_t b_off0 = sw128(rb, cb2), b_off1 = sw128(rb, cb2 + 1);
    const __half* bg = Bq + (size_t)rb * DD + cb2 * 8;

#define BL_ISSUE(kt, buf) do { \
        uint32_t Ab_ = sb + BOFF_A + (buf) * 16384u; \
        uint32_t Bb_ = sb + BOFF_B + (buf) * 8192u; \
        const __half* ap_ = ag + (kt) * 64; \
        const __half* bp_ = bg + (kt) * 64; \
        _Pragma("unroll") \
        for (int j_ = 0; j_ < 4; j_++) CP_ASYNC16(Ab_ + a_off[j_], ap_ + j_ * 8); \
        CP_ASYNC16(Bb_ + b_off0, bp_); \
        CP_ASYNC16(Bb_ + b_off1, bp_ + 8); \
        CP_COMMIT(); \
    } while (0)

    float acc[2][4][4];
#pragma unroll
    for (int i = 0; i < 2; i++)
#pragma unroll
        for (int j = 0; j < 4; j++)
#pragma unroll
            for (int k = 0; k < 4; k++) acc[i][j][k] = 0.0f;

    BL_ISSUE(0, 0);
    CP_WAIT0();
    __syncthreads();

    uint32_t a_row[2], b_row[2];
#pragma unroll
    for (int mi = 0; mi < 2; mi++) a_row[mi] = wm * 32 + mi * 16 + lane15;
#pragma unroll
    for (int nj = 0; nj < 2; nj++) b_row[nj] = whn * 32 + nj * 16 + lane15;

    for (int kt = 0; kt < 16; kt++) {
        const int buf = kt & 1;
        if (kt < 15) BL_ISSUE(kt + 1, buf ^ 1);

        const uint32_t Ah = sb + BOFF_A + buf * 16384u;
        const uint32_t Bh = sb + BOFF_B + buf * 8192u;

#pragma unroll
        for (int ks = 0; ks < 4; ks++) {
            const uint32_t cidx = ks * 2 + lhalf;
            uint32_t a[2][4], bb[2][4];
#pragma unroll
            for (int mi = 0; mi < 2; mi++)
                LDSM4(a[mi][0], a[mi][1], a[mi][2], a[mi][3], Ah + sw128(a_row[mi], cidx));
#pragma unroll
            for (int nj = 0; nj < 2; nj++)
                LDSM4(bb[nj][0], bb[nj][1], bb[nj][2], bb[nj][3], Bh + sw128(b_row[nj], cidx));
#pragma unroll
            for (int mi = 0; mi < 2; mi++)
#pragma unroll
                for (int nj = 0; nj < 2; nj++) {
                    MMA16816(acc[mi][nj*2+0], a[mi][0], a[mi][1], a[mi][2], a[mi][3], bb[nj][0], bb[nj][2]);
                    MMA16816(acc[mi][nj*2+1], a[mi][0], a[mi][1], a[mi][2], a[mi][3], bb[nj][1], bb[nj][3]);
                }
        }

        CP_WAIT0();
        __syncthreads();
    }

#pragma unroll
    for (int mi = 0; mi < 2; mi++) {
        int row = wm * 32 + mi * 16 + (lane >> 2);
#pragma unroll
        for (int nj8 = 0; nj8 < 4; nj8++) {
            int col = half_n * 64 + whn * 32 + nj8 * 8 + (lane & 3) * 2;
            sbuf[((size_t)b * NN + row) * NN + col]         = acc[mi][nj8][0];
            sbuf[((size_t)b * NN + row) * NN + col + 1]     = acc[mi][nj8][1];
            sbuf[((size_t)b * NN + row + 8) * NN + col]     = acc[mi][nj8][2];
            sbuf[((size_t)b * NN + row + 8) * NN + col + 1] = acc[mi][nj8][3];
        }
    }
#undef BL_ISSUE
}

// ---------------------------------------------------------------------------
// Concat + minus scores, 4-m blocked, fp16 inputs. grid (32, 8, 2).
// ---------------------------------------------------------------------------
__global__ __launch_bounds__(256) void pair_scores4(
    const __half* __restrict__ HP,
    const float* __restrict__ vcv, const float* __restrict__ vmv,
    float* __restrict__ sc, float* __restrict__ smn)
{
    const int m0 = blockIdx.x * 4, b = blockIdx.y, z = blockIdx.z;
    const __half* p = HP + (z ? HXM : HXC);
    const __half* q = HP + (z ? HYM : HYC);
    const float* v = z ? vmv : vcv;
    float* s = z ? smn : sc;
    const float sign = z ? -1.0f : 1.0f;

    const int t = threadIdx.x, lane = t & 31, w = t >> 5;
    __shared__ float qs[4][HH], vs[HH];
    {   // 4 q rows = 2048 halves = 256 uint4; convert to fp32 in smem
        uint4 qv = ((const uint4*)(q + ((size_t)b * NN + m0) * HH))[t];
        const __half2* h2 = (const __half2*)&qv;
        float* dst = &qs[0][0] + t * 8;
        float2 f0 = __half22float2(h2[0]), f1 = __half22float2(h2[1]);
        float2 f2 = __half22float2(h2[2]), f3 = __half22float2(h2[3]);
        dst[0] = f0.x; dst[1] = f0.y; dst[2] = f1.x; dst[3] = f1.y;
        dst[4] = f2.x; dst[5] = f2.y; dst[6] = f3.x; dst[7] = f3.y;
        if (t < 128) ((float4*)vs)[t] = ((const float4*)v)[t];
    }
    __syncthreads();

    const __half* pb = p + (size_t)b * NN * HH;
    for (int n = w; n < NN; n += 8) {
        const __half* pr = pb + (size_t)n * HH;
        float a0 = 0.0f, a1 = 0.0f, a2 = 0.0f, a3 = 0.0f;
#pragma unroll
        for (int h = 0; h < HH; h += 32) {
            int hh = h + lane;
            float pv = __half2float(pr[hh]), vv = vs[hh];
            a0 += vv * ftanh(fmaf(sign, qs[0][hh], pv));
            a1 += vv * ftanh(fmaf(sign, qs[1][hh], pv));
            a2 += vv * ftanh(fmaf(sign, qs[2][hh], pv));
            a3 += vv * ftanh(fmaf(sign, qs[3][hh], pv));
        }
#pragma unroll
        for (int o = 16; o; o >>= 1) {
            a0 += __shfl_xor_sync(0xffffffffu, a0, o);
            a1 += __shfl_xor_sync(0xffffffffu, a1, o);
            a2 += __shfl_xor_sync(0xffffffffu, a2, o);
            a3 += __shfl_xor_sync(0xffffffffu, a3, o);
        }
        if (lane == 0) {
            s[((size_t)b * NN + m0 + 0) * NN + n] = a0;
            s[((size_t)b * NN + m0 + 1) * NN + n] = a1;
            s[((size_t)b * NN + m0 + 2) * NN + n] = a2;
            s[((size_t)b * NN + m0 + 3) * NN + n] = a3;
        }
    }
}

// ---------------------------------------------------------------------------
// Fused: 20 softmaxes + weighted sums + max + agg_rep, 4 m's per CTA.
// ---------------------------------------------------------------------------
__global__ __launch_bounds__(256) void fuse_att4(
    const float* __restrict__ sc,  const float* __restrict__ sb,
    const float* __restrict__ smn, const float* __restrict__ sd1,
    const float* __restrict__ sd2,
    const float* __restrict__ x0,  const float* __restrict__ x1,
    float* __restrict__ aggrep)
{
    const int m0 = blockIdx.x * 4, b = blockIdx.y;
    const int t = threadIdx.x, lane = t & 31, w = t >> 5;
    __shared__ float aw[20][NN];

    if (t < 128) {
        const int n = t;
#pragma unroll
        for (int mi = 0; mi < 4; mi++) {
            const size_t bm = (size_t)b * NN + m0 + mi;
            aw[0 * 4 + mi][n] = sc [bm * NN + n];
            aw[1 * 4 + mi][n] = sb [bm * NN + n];
            aw[2 * 4 + mi][n] = smn[bm * NN + n];
            aw[3 * 4 + mi][n] = sd1[(bm * 2 + 0) * NN + n] + sd1[(bm * 2 + 1) * NN + n];
            aw[4 * 4 + mi][n] = sd2[(bm * 2 + 0) * NN + n] + sd2[(bm * 2 + 1) * NN + n];
        }
    }
    __syncthreads();

    for (int row = w; row < 20; row += 8) {
        float v0 = aw[row][lane], v1 = aw[row][lane + 32];
        float v2 = aw[row][lane + 64], v3 = aw[row][lane + 96];
        float mx = fmaxf(fmaxf(v0, v1), fmaxf(v2, v3));
#pragma unroll
        for (int o = 16; o; o >>= 1) mx = fmaxf(mx, __shfl_xor_sync(0xffffffffu, mx, o));
        float e0 = __expf(v0 - mx), e1 = __expf(v1 - mx);
        float e2 = __expf(v2 - mx), e3 = __expf(v3 - mx);
        float sm = e0 + e1 + e2 + e3;
#pragma unroll
        for (int o = 16; o; o >>= 1) sm += __shfl_xor_sync(0xffffffffu, sm, o);
        float inv = 1.0f / sm;
        aw[row][lane]      = e0 * inv; aw[row][lane + 32] = e1 * inv;
        aw[row][lane + 64] = e2 * inv; aw[row][lane + 96] = e3 * inv;
    }
    __syncthreads();

    const int d = t * 4;
    float4 acc[5][4];
#pragma unroll
    for (int a = 0; a < 5; a++)
#pragma unroll
        for (int mi = 0; mi < 4; mi++) acc[a][mi] = make_float4(0.f, 0.f, 0.f, 0.f);

    const float* x0b = x0 + (size_t)b * NN * DD;
    const float* x1b = x1 + (size_t)b * NN * DD;
    for (int n = 0; n < NN; n++) {
        float4 xv = *(const float4*)(x0b + (size_t)n * DD + d);
        float4 yv = *(const float4*)(x1b + (size_t)n * DD + d);
#pragma unroll
        for (int mi = 0; mi < 4; mi++) {
            float w0 = aw[0 * 4 + mi][n], w1 = aw[1 * 4 + mi][n];
            float w2 = aw[2 * 4 + mi][n], w3 = aw[3 * 4 + mi][n];
            float w4 = aw[4 * 4 + mi][n];
            acc[0][mi].x = fmaf(w0, xv.x, acc[0][mi].x); acc[0][mi].y = fmaf(w0, xv.y, acc[0][mi].y);
            acc[0][mi].z = fmaf(w0, xv.z, acc[0][mi].z); acc[0][mi].w = fmaf(w0, xv.w, acc[0][mi].w);
            acc[1][mi].x = fmaf(w1, xv.x, acc[1][mi].x); acc[1][mi].y = fmaf(w1, xv.y, acc[1][mi].y);
            acc[1][mi].z = fmaf(w1, xv.z, acc[1][mi].z); acc[1][mi].w = fmaf(w1, xv.w, acc[1][mi].w);
            acc[2][mi].x = fmaf(w2, xv.x, acc[2][mi].x); acc[2][mi].y = fmaf(w2, xv.y, acc[2][mi].y);
            acc[2][mi].z = fmaf(w2, xv.z, acc[2][mi].z); acc[2][mi].w = fmaf(w2, xv.w, acc[2][mi].w);
            acc[3][mi].x = fmaf(w3, xv.x, acc[3][mi].x); acc[3][mi].y = fmaf(w3, xv.y, acc[3][mi].y);
            acc[3][mi].z = fmaf(w3, xv.z, acc[3][mi].z); acc[3][mi].w = fmaf(w3, xv.w, acc[3][mi].w);
            acc[4][mi].x = fmaf(w4, yv.x, acc[4][mi].x); acc[4][mi].y = fmaf(w4, yv.y, acc[4][mi].y);
            acc[4][mi].z = fmaf(w4, yv.z, acc[4][mi].z); acc[4][mi].w = fmaf(w4, yv.w, acc[4][mi].w);
        }
    }

#pragma unroll
    for (int mi = 0; mi < 4; mi++) {
        const size_t bm = (size_t)b * NN + m0 + mi;
        float4 xm1 = *(const float4*)(x1b + (size_t)(m0 + mi) * DD + d);
        float4 ag;
        ag.x = fmaxf(xm1.x, fmaxf(fmaxf(acc[3][mi].x, acc[0][mi].x),
                                  fmaxf(fmaxf(acc[4][mi].x, acc[1][mi].x), acc[2][mi].x)));
        ag.y = fmaxf(xm1.y, fmaxf(fmaxf(acc[3][mi].y, acc[0][mi].y),
                                  fmaxf(fmaxf(acc[4][mi].y, acc[1][mi].y), acc[2][mi].y)));
        ag.z = fmaxf(xm1.z, fmaxf(fmaxf(acc[3][mi].z, acc[0][mi].z),
                                  fmaxf(fmaxf(acc[4][mi].z, acc[1][mi].z), acc[2][mi].z)));
        ag.w = fmaxf(xm1.w, fmaxf(fmaxf(acc[3][mi].w, acc[0][mi].w),
                                  fmaxf(fmaxf(acc[4][mi].w, acc[1][mi].w), acc[2][mi].w)));
        float* arow = aggrep + bm * (2 * DD);
        *(float4*)(arow + d)      = xm1;
        *(float4*)(arow + DD + d) = ag;
    }
}

// ---------------------------------------------------------------------------
// Final head
// ---------------------------------------------------------------------------
__global__ __launch_bounds__(256) void final_kernel(
    const float* __restrict__ aggrep, const float* __restrict__ w1v,
    const float* __restrict__ Wpred,  const float* __restrict__ bpred,
    float* __restrict__ out)
{
    const int b = blockIdx.x;
    const int t = threadIdx.x, lane = t & 31, w = t >> 5;
    __shared__ float sp[NN];
    __shared__ float r0[8], r1[8];
    const float* ab = aggrep + (size_t)b * NN * (2 * DD);

    for (int mm = w; mm < NN; mm += 8) {
        const float* ar = ab + (size_t)mm * (2 * DD);
        float acc = 0.0f;
#pragma unroll
        for (int j = lane; j < 2 * DD; j += 32) acc += ar[j] * w1v[j];
#pragma unroll
        for (int o = 16; o; o >>= 1) acc += __shfl_xor_sync(0xffffffffu, acc, o);
        if (lane == 0) sp[mm] = acc;
    }
    __syncthreads();
    if (w == 0) {
        float v0 = sp[lane], v1 = sp[lane + 32], v2 = sp[lane + 64], v3 = sp[lane + 96];
        float mx = fmaxf(fmaxf(v0, v1), fmaxf(v2, v3));
#pragma unroll
        for (int o = 16; o; o >>= 1) mx = fmaxf(mx, __shfl_xor_sync(0xffffffffu, mx, o));
        float e0 = __expf(v0 - mx), e1 = __expf(v1 - mx);
        float e2 = __expf(v2 - mx), e3 = __expf(v3 - mx);
        float sm = e0 + e1 + e2 + e3;
#pragma unroll
        for (int o = 16; o; o >>= 1) sm += __shfl_xor_sync(0xffffffffu, sm, o);
        float inv = 1.0f / sm;
        sp[lane] = e0 * inv; sp[lane + 32] = e1 * inv;
        sp[lane + 64] = e2 * inv; sp[lane + 96] = e3 * inv;
    }
    __syncthreads();

    float rp[8];
#pragma unroll
    for (int k = 0; k < 8; k++) rp[k] = 0.0f;
    for (int mm = 0; mm < NN; mm++) {
        float wgt = sp[mm];
        const float* ar = ab + (size_t)mm * (2 * DD);
#pragma unroll
        for (int k = 0; k < 8; k++) rp[k] = fmaf(wgt, ar[t + k * 256], rp[k]);
    }
    float p0 = 0.0f, p1 = 0.0f;
#pragma unroll
    for (int k = 0; k < 8; k++) {
        int j = t + k * 256;
        p0 = fmaf(rp[k], Wpred[(size_t)j * 2 + 0], p0);
        p1 = fmaf(rp[k], Wpred[(size_t)j * 2 + 1], p1);
    }
#pragma unroll
    for (int o = 16; o; o >>= 1) {
        p0 += __shfl_xor_sync(0xffffffffu, p0, o);
        p1 += __shfl_xor_sync(0xffffffffu, p1, o);
    }
    if (lane == 0) { r0[w] = p0; r1[w] = p1; }
    __syncthreads();
    if (t == 0) {
        float s0 = 0.0f, s1 = 0.0f;
#pragma unroll
        for (int i = 0; i < 8; i++) { s0 += r0[i]; s1 += r1[i]; }
        out[b * 2 + 0] = fmaxf(s0 + bpred[0], 0.0f);
        out[b * 2 + 1] = fmaxf(s1 + bpred[1], 0.0f);
    }
}

// ---------------------------------------------------------------------------
extern "C" void kernel_launch(void* const* d_in, const int* in_sizes, int n_in,
                              void* d_out, int out_size)
{
    (void)in_sizes; (void)n_in; (void)out_size;
    float* S = nullptr;
    cudaGetSymbolAddress((void**)&S, g_scratch);
    __half* HP = nullptr;
    cudaGetSymbolAddress((void**)&HP, g_half);

    const float* x0    = (const float*)d_in[0];
    const float* x1    = (const float*)d_in[1];
    const float* Wc1   = (const float*)d_in[2];
    const float* Wc2   = (const float*)d_in[3];
    const float* vc    = (const float*)d_in[4];
    const float* Wb    = (const float*)d_in[5];
    const float* Wd1   = (const float*)d_in[6];
    const float* vd1   = (const float*)d_in[7];
    const float* Wd2   = (const float*)d_in[8];
    const float* vd2   = (const float*)d_in[9];
    const float* Wm    = (const float*)d_in[10];
    const float* vm    = (const float*)d_in[11];
    const float* Wp1   = (const float*)d_in[14];
    const float* vp    = (const float*)d_in[16];
    const float* Wpred = (const float*)d_in[17];
    const float* bpred = (const float*)d_in[18];
    float* out = (float*)d_out;

    static cudaStream_t s_dot = nullptr;
    static cudaEvent_t ev_prep = nullptr, ev_dot = nullptr;
    static bool attrs_set = false;
    if (!attrs_set) {
        cudaFuncSetAttribute(dot_scores_mma,
                             cudaFuncAttributeMaxDynamicSharedMemorySize, MSMEM);
        cudaFuncSetAttribute(proj_mma,
                             cudaFuncAttributeMaxDynamicSharedMemorySize, PSMEM);
        cudaFuncSetAttribute(bilin_tc,
                             cudaFuncAttributeMaxDynamicSharedMemorySize, BSMEM);
        cudaStreamCreateWithFlags(&s_dot, cudaStreamNonBlocking);
        cudaEventCreateWithFlags(&ev_prep, cudaEventDisableTiming);
        cudaEventCreateWithFlags(&ev_dot, cudaEventDisableTiming);
        attrs_set = true;
    }

    __half* w1t = HP + HW1;
    __half* w2t = HP + HW2;
    __half* xh0 = HP + HX0;
    __half* xh1 = HP + HX1;
    __half* xbh = HP + HXB;

    // Prep (main stream): coalesced weight transposes + x converts + w1v
    wtrans<<<dim3(16, 16, 6), 256>>>(Wd1, Wd2, Wc1, Wc2, Wm, Wb, HP);
    prep_rest<<<dim3(1024, 3), 256>>>(x0, x1, Wp1, vp, HP, S + OFF_W1V);
    cudaEventRecord(ev_prep, 0);

    // Fork: dominant dot kernel
    cudaStreamWaitEvent(s_dot, ev_prep, 0);
    dot_scores_mma<<<dim3(2, NN, 2 * BB), 512, MSMEM, s_dot>>>(
        x0, x1, w1t, w2t, vd1, vd2, S + OFF_SD1, S + OFF_SD2);
    cudaEventRecord(ev_dot, s_dot);

    // Main: projections (fp16 outputs), bilin on TC, pair scores (fp16 in)
    proj_mma<<<dim3(8, 8, 5), 256, PSMEM>>>(xh0, xh1, HP);
    bilin_tc<<<dim3(2, BB), 256, BSMEM>>>(xh1, xbh, S + OFF_SB);
    pair_scores4<<<dim3(NN / 4, BB, 2), 256>>>(HP, vc, vm, S + OFF_SC, S + OFF_SMN);

    // Join + fused aggregation + final head
    cudaStreamWaitEvent(0, ev_dot, 0);
    fuse_att4<<<dim3(NN / 4, BB), 256>>>(S + OFF_SC, S + OFF_SB, S + OFF_SMN,
                                         S + OFF_SD1, S + OFF_SD2, x0, x1, S + OFF_AGG);
    final_kernel<<<BB, 256>>>(S + OFF_AGG, S + OFF_W1V, Wpred, bpred, out);
}